// round 3
// baseline (speedup 1.0000x reference)
#include <cuda_runtime.h>
#include <math.h>
#include <stdint.h>

#define TOK   4096
#define DIM   1024
#define MLPD  4096
#define NHEAD 16
#define HD    64
#define SEQ   2048

// ---------------- scratch ----------------
__device__ float g_xln [TOK * DIM];
__device__ float g_qkv [TOK * 3 * DIM];
__device__ float g_attn[TOK * DIM];
__device__ float g_x1  [TOK * DIM];
__device__ float g_xln2[TOK * DIM];
__device__ float g_h   [TOK * MLPD];

// ---------------- LayerNorm ----------------
__global__ __launch_bounds__(256) void ln_kernel(
    const float* __restrict__ x, const float* __restrict__ w,
    const float* __restrict__ b, float* __restrict__ out)
{
    int row = blockIdx.x;
    int tid = threadIdx.x;
    const float4* xr = (const float4*)(x + (size_t)row * DIM);
    float4 v = xr[tid];

    __shared__ float red[9];
    float s = v.x + v.y + v.z + v.w;
    #pragma unroll
    for (int o = 16; o > 0; o >>= 1) s += __shfl_xor_sync(0xffffffffu, s, o);
    if ((tid & 31) == 0) red[tid >> 5] = s;
    __syncthreads();
    if (tid == 0) {
        float t = 0.f;
        #pragma unroll
        for (int i = 0; i < 8; i++) t += red[i];
        red[8] = t * (1.0f / DIM);
    }
    __syncthreads();
    float mean = red[8];
    float dx = v.x - mean, dy = v.y - mean, dz = v.z - mean, dw = v.w - mean;
    float sq = dx*dx + dy*dy + dz*dz + dw*dw;
    #pragma unroll
    for (int o = 16; o > 0; o >>= 1) sq += __shfl_xor_sync(0xffffffffu, sq, o);
    if ((tid & 31) == 0) red[tid >> 5] = sq;
    __syncthreads();
    if (tid == 0) {
        float t = 0.f;
        #pragma unroll
        for (int i = 0; i < 8; i++) t += red[i];
        red[8] = rsqrtf(t * (1.0f / DIM) + 1e-5f);
    }
    __syncthreads();
    float rstd = red[8];

    float4 wv = ((const float4*)w)[tid];
    float4 bv = ((const float4*)b)[tid];
    float4 o;
    o.x = dx * rstd * wv.x + bv.x;
    o.y = dy * rstd * wv.y + bv.y;
    o.z = dz * rstd * wv.z + bv.z;
    o.w = dw * rstd * wv.w + bv.w;
    ((float4*)(out + (size_t)row * DIM))[tid] = o;
}

// ---------------- tf32 helpers ----------------
__device__ __forceinline__ float2 split2(float v) {
    uint32_t h;
    asm("cvt.rna.tf32.f32 %0, %1;" : "=r"(h) : "f"(v));
    float hf = __uint_as_float(h);
    float l = v - hf;
    uint32_t lw;
    asm("cvt.rna.tf32.f32 %0, %1;" : "=r"(lw) : "f"(l));
    return make_float2(hf, __uint_as_float(lw));
}

__device__ __forceinline__ void mma_t(float* d,
    uint32_t a0, uint32_t a1, uint32_t a2, uint32_t a3,
    uint32_t b0, uint32_t b1)
{
    asm volatile(
        "mma.sync.aligned.m16n8k8.row.col.f32.tf32.tf32.f32 "
        "{%0,%1,%2,%3}, {%4,%5,%6,%7}, {%8,%9}, {%0,%1,%2,%3};"
        : "+f"(d[0]), "+f"(d[1]), "+f"(d[2]), "+f"(d[3])
        : "r"(a0), "r"(a1), "r"(a2), "r"(a3), "r"(b0), "r"(b1));
}

#define FU(x) __float_as_uint(x)

// ---------------- NT GEMM (3xTF32, split-at-store) ----------------
// C[M,N] = A[M,K] @ B[N,K]^T + epilogue. 128x128 CTA, KT=16, double buffer.
// smem planes hold (hi,lo) float2 per element.
#define EPI_NONE      0
#define EPI_BIAS_RES  1
#define EPI_BIAS_SILU 2

#define KT    16
#define SSTR  18                                  // float2 stride per row
#define GEMM_SM_F2 (4 * 128 * SSTR)               // 2 stages x (A+B)
#define GEMM_SM_BYTES (GEMM_SM_F2 * 8)            // 73728

__device__ __forceinline__ void store_split8(
    float2* row, const float4& v0, const float4& v1)
{
    float2 s0 = split2(v0.x), s1 = split2(v0.y), s2 = split2(v0.z), s3 = split2(v0.w);
    *(float4*)(row + 0) = make_float4(s0.x, s0.y, s1.x, s1.y);
    *(float4*)(row + 2) = make_float4(s2.x, s2.y, s3.x, s3.y);
    float2 t0 = split2(v1.x), t1 = split2(v1.y), t2 = split2(v1.z), t3 = split2(v1.w);
    *(float4*)(row + 4) = make_float4(t0.x, t0.y, t1.x, t1.y);
    *(float4*)(row + 6) = make_float4(t2.x, t2.y, t3.x, t3.y);
}

template <int EPI>
__global__ __launch_bounds__(256) void gemm_tf32(
    const float* __restrict__ A, const float* __restrict__ Bm,
    const float* __restrict__ bias, const float* __restrict__ res,
    float* __restrict__ C, int M, int N, int K)
{
    extern __shared__ float2 sm2[];
    float2* Asm = sm2;                        // [2][128][SSTR]
    float2* Bsm = sm2 + 2 * 128 * SSTR;       // [2][128][SSTR]

    int tid  = threadIdx.x;
    int bm   = blockIdx.y * 128;
    int bn   = blockIdx.x * 128;
    int warp = tid >> 5, lane = tid & 31;
    int wm   = (warp & 1) * 64;
    int wn   = (warp >> 1) * 32;
    int gid  = lane >> 2, tig = lane & 3;

    int lr = tid & 127;
    int lk = (tid >> 7) * 8;                  // 0 or 8
    const float* ag = A  + (size_t)(bm + lr) * K + lk;
    const float* bg = Bm + (size_t)(bn + lr) * K + lk;

    float acc[4][4][4];
    #pragma unroll
    for (int i = 0; i < 4; i++)
        #pragma unroll
        for (int j = 0; j < 4; j++)
            #pragma unroll
            for (int r = 0; r < 4; r++) acc[i][j][r] = 0.f;

    int ntiles = K / KT;

    // prologue: tile 0 -> stage 0
    float4 ra0 = *(const float4*)ag;
    float4 ra1 = *(const float4*)(ag + 4);
    float4 rb0 = *(const float4*)bg;
    float4 rb1 = *(const float4*)(bg + 4);
    store_split8(Asm + lr * SSTR + lk, ra0, ra1);
    store_split8(Bsm + lr * SSTR + lk, rb0, rb1);
    __syncthreads();

    for (int t = 0; t < ntiles; ++t) {
        if (t + 1 < ntiles) {
            const float* an = ag + (size_t)(t + 1) * KT;
            const float* bn2 = bg + (size_t)(t + 1) * KT;
            ra0 = *(const float4*)an;  ra1 = *(const float4*)(an + 4);
            rb0 = *(const float4*)bn2; rb1 = *(const float4*)(bn2 + 4);
        }
        const float2* as = Asm + (t & 1) * 128 * SSTR;
        const float2* bs = Bsm + (t & 1) * 128 * SSTR;

        #pragma unroll
        for (int ks = 0; ks < 2; ++ks) {
            int kk = ks * 8;
            float2 B0[4], B1[4];
            #pragma unroll
            for (int nt = 0; nt < 4; ++nt) {
                const float2* br = bs + (wn + nt * 8 + gid) * SSTR;
                B0[nt] = br[kk + tig];
                B1[nt] = br[kk + 4 + tig];
            }
            #pragma unroll
            for (int mt = 0; mt < 4; ++mt) {
                const float2* ar0 = as + (wm + mt * 16 + gid) * SSTR;
                const float2* ar1 = ar0 + 8 * SSTR;
                float2 A0 = ar0[kk + tig];
                float2 A1 = ar1[kk + tig];
                float2 A2 = ar0[kk + 4 + tig];
                float2 A3 = ar1[kk + 4 + tig];
                #pragma unroll
                for (int nt = 0; nt < 4; ++nt) {
                    mma_t(acc[mt][nt], FU(A0.x), FU(A1.x), FU(A2.x), FU(A3.x),
                          FU(B0[nt].x), FU(B1[nt].x));                      // hi*hi
                    mma_t(acc[mt][nt], FU(A0.x), FU(A1.x), FU(A2.x), FU(A3.x),
                          FU(B0[nt].y), FU(B1[nt].y));                      // hi*lo
                    mma_t(acc[mt][nt], FU(A0.y), FU(A1.y), FU(A2.y), FU(A3.y),
                          FU(B0[nt].x), FU(B1[nt].x));                      // lo*hi
                }
            }
        }

        if (t + 1 < ntiles) {
            float2* aw = Asm + ((t + 1) & 1) * 128 * SSTR + lr * SSTR + lk;
            float2* bw = Bsm + ((t + 1) & 1) * 128 * SSTR + lr * SSTR + lk;
            store_split8(aw, ra0, ra1);
            store_split8(bw, rb0, rb1);
        }
        __syncthreads();
    }

    // epilogue
    #pragma unroll
    for (int mt = 0; mt < 4; ++mt) {
        #pragma unroll
        for (int nt = 0; nt < 4; ++nt) {
            int row = bm + wm + mt * 16 + gid;
            int col = bn + wn + nt * 8 + tig * 2;
            float2 v0 = make_float2(acc[mt][nt][0], acc[mt][nt][1]);
            float2 v1 = make_float2(acc[mt][nt][2], acc[mt][nt][3]);
            if (EPI != EPI_NONE) {
                float bx = bias[col], by = bias[col + 1];
                v0.x += bx; v0.y += by; v1.x += bx; v1.y += by;
            }
            if (EPI == EPI_BIAS_RES) {
                float2 r0 = *(const float2*)(res + (size_t)row * N + col);
                float2 r1 = *(const float2*)(res + (size_t)(row + 8) * N + col);
                v0.x += r0.x; v0.y += r0.y; v1.x += r1.x; v1.y += r1.y;
            } else if (EPI == EPI_BIAS_SILU) {
                v0.x *= 1.f / (1.f + __expf(-v0.x));
                v0.y *= 1.f / (1.f + __expf(-v0.y));
                v1.x *= 1.f / (1.f + __expf(-v1.x));
                v1.y *= 1.f / (1.f + __expf(-v1.y));
            }
            *(float2*)(C + (size_t)row * N + col)       = v0;
            *(float2*)(C + (size_t)(row + 8) * N + col) = v1;
        }
    }
}

// ---------------- Flash attention, 3xTF32 HMMA ----------------
// CTA: 256 threads (8 warps), Q tile 128 rows, K/V tiles 64.
// Warp w owns Q rows 16w..16w+15 end-to-end (S, softmax, P, O).
#define ASTR 66                                   // float2 stride
#define SM_K_OFF (128 * ASTR)
#define SM_V_OFF (SM_K_OFF + 64 * ASTR)
#define SM_P_OFF (SM_V_OFF + 64 * ASTR)
#define ATTN_SM_F2 (SM_P_OFF + 128 * ASTR)
#define ATTN_SM_BYTES (ATTN_SM_F2 * 8)            // 202752

__global__ __launch_bounds__(256) void attn_tf32(
    const float* __restrict__ qkv, float* __restrict__ out)
{
    extern __shared__ float2 sm2[];
    float2* Qs = sm2;                 // [128][ASTR]  A-frag source (i rows, k=d)
    float2* Ks = sm2 + SM_K_OFF;      // [64][ASTR]   B-frag source (n=j rows, k=d)
    float2* Vt = sm2 + SM_V_OFF;      // [64][ASTR]   B-frag source (n=d rows, k=j)
    float2* Ps = sm2 + SM_P_OFF;      // [128][ASTR]  A-frag source (i rows, k=j)

    int tid  = threadIdx.x;
    int warp = tid >> 5, lane = tid & 31;
    int gid  = lane >> 2, tig = lane & 3;
    int qrow0 = warp * 16;

    int qb = blockIdx.x;              // 0..15 (128-row Q tiles)
    int b  = blockIdx.y >> 4;
    int h  = blockIdx.y & 15;

    // fill Q (pre-scaled by 1/sqrt(hd)=0.125)
    const float* qbase = qkv + (size_t)(b * SEQ + qb * 128) * (3 * DIM) + h * HD;
    for (int e = tid; e < 128 * 16; e += 256) {
        int r = e >> 4, c4 = (e & 15) * 4;
        float4 v = *(const float4*)(qbase + (size_t)r * (3 * DIM) + c4);
        float2* qr = Qs + r * ASTR + c4;
        float2 s0 = split2(v.x * 0.125f), s1 = split2(v.y * 0.125f);
        float2 s2 = split2(v.z * 0.125f), s3 = split2(v.w * 0.125f);
        *(float4*)(qr)     = make_float4(s0.x, s0.y, s1.x, s1.y);
        *(float4*)(qr + 2) = make_float4(s2.x, s2.y, s3.x, s3.y);
    }

    float m0 = -1e30f, m1 = -1e30f, l0 = 0.f, l1 = 0.f;
    float oacc[8][4];
    #pragma unroll
    for (int nt = 0; nt < 8; nt++)
        #pragma unroll
        for (int r = 0; r < 4; r++) oacc[nt][r] = 0.f;

    for (int jb = 0; jb < SEQ / 64; ++jb) {
        __syncthreads();   // prev tile fully consumed; Q fill visible (first iter)
        const float* kb = qkv + (size_t)(b * SEQ + jb * 64) * (3 * DIM) + h * HD + DIM;
        const float* vb = kb + DIM;
        for (int e = tid; e < 64 * 16; e += 256) {
            int r = e >> 4, c4 = (e & 15) * 4;
            float4 kv = *(const float4*)(kb + (size_t)r * (3 * DIM) + c4);
            float2* kr = Ks + r * ASTR + c4;
            float2 s0 = split2(kv.x), s1 = split2(kv.y);
            float2 s2 = split2(kv.z), s3 = split2(kv.w);
            *(float4*)(kr)     = make_float4(s0.x, s0.y, s1.x, s1.y);
            *(float4*)(kr + 2) = make_float4(s2.x, s2.y, s3.x, s3.y);
            float4 vv = *(const float4*)(vb + (size_t)r * (3 * DIM) + c4);
            Vt[(c4 + 0) * ASTR + r] = split2(vv.x);
            Vt[(c4 + 1) * ASTR + r] = split2(vv.y);
            Vt[(c4 + 2) * ASTR + r] = split2(vv.z);
            Vt[(c4 + 3) * ASTR + r] = split2(vv.w);
        }
        __syncthreads();

        // ---- S = Q K^T (warp rows qrow0..+15, cols 0..63) ----
        float s[8][4];
        #pragma unroll
        for (int nt = 0; nt < 8; nt++)
            #pragma unroll
            for (int r = 0; r < 4; r++) s[nt][r] = 0.f;

        #pragma unroll
        for (int ks = 0; ks < 8; ++ks) {
            int kk = ks * 8;
            const float2* ar0 = Qs + (qrow0 + gid) * ASTR;
            const float2* ar1 = ar0 + 8 * ASTR;
            float2 A0 = ar0[kk + tig];
            float2 A1 = ar1[kk + tig];
            float2 A2 = ar0[kk + 4 + tig];
            float2 A3 = ar1[kk + 4 + tig];
            #pragma unroll
            for (int nt = 0; nt < 8; ++nt) {
                const float2* br = Ks + (nt * 8 + gid) * ASTR;
                float2 B0 = br[kk + tig];
                float2 B1 = br[kk + 4 + tig];
                mma_t(s[nt], FU(A0.x), FU(A1.x), FU(A2.x), FU(A3.x), FU(B0.x), FU(B1.x));
                mma_t(s[nt], FU(A0.x), FU(A1.x), FU(A2.x), FU(A3.x), FU(B0.y), FU(B1.y));
                mma_t(s[nt], FU(A0.y), FU(A1.y), FU(A2.y), FU(A3.y), FU(B0.x), FU(B1.x));
            }
        }

        // ---- online softmax (rows qrow0+gid, qrow0+8+gid) ----
        float mc0 = s[0][0], mc1 = s[0][2];
        #pragma unroll
        for (int nt = 0; nt < 8; ++nt) {
            mc0 = fmaxf(mc0, fmaxf(s[nt][0], s[nt][1]));
            mc1 = fmaxf(mc1, fmaxf(s[nt][2], s[nt][3]));
        }
        mc0 = fmaxf(mc0, __shfl_xor_sync(0xffffffffu, mc0, 1));
        mc0 = fmaxf(mc0, __shfl_xor_sync(0xffffffffu, mc0, 2));
        mc1 = fmaxf(mc1, __shfl_xor_sync(0xffffffffu, mc1, 1));
        mc1 = fmaxf(mc1, __shfl_xor_sync(0xffffffffu, mc1, 2));
        float mn0 = fmaxf(m0, mc0), mn1 = fmaxf(m1, mc1);
        float f0 = __expf(m0 - mn0), f1 = __expf(m1 - mn1);
        m0 = mn0; m1 = mn1;

        float ps0 = 0.f, ps1 = 0.f;
        #pragma unroll
        for (int nt = 0; nt < 8; ++nt) {
            float p0 = __expf(s[nt][0] - m0);
            float p1 = __expf(s[nt][1] - m0);
            float p2 = __expf(s[nt][2] - m1);
            float p3 = __expf(s[nt][3] - m1);
            ps0 += p0 + p1; ps1 += p2 + p3;
            float2 q0 = split2(p0), q1 = split2(p1);
            float2 q2 = split2(p2), q3 = split2(p3);
            float2* pr0 = Ps + (qrow0 + gid) * ASTR + nt * 8 + tig * 2;
            float2* pr1 = Ps + (qrow0 + 8 + gid) * ASTR + nt * 8 + tig * 2;
            *(float4*)pr0 = make_float4(q0.x, q0.y, q1.x, q1.y);
            *(float4*)pr1 = make_float4(q2.x, q2.y, q3.x, q3.y);
        }
        ps0 += __shfl_xor_sync(0xffffffffu, ps0, 1);
        ps0 += __shfl_xor_sync(0xffffffffu, ps0, 2);
        ps1 += __shfl_xor_sync(0xffffffffu, ps1, 1);
        ps1 += __shfl_xor_sync(0xffffffffu, ps1, 2);
        l0 = l0 * f0 + ps0;
        l1 = l1 * f1 + ps1;
        #pragma unroll
        for (int nt = 0; nt < 8; ++nt) {
            oacc[nt][0] *= f0; oacc[nt][1] *= f0;
            oacc[nt][2] *= f1; oacc[nt][3] *= f1;
        }
        __syncwarp();     // Ps rows are warp-private: warp sync suffices

        // ---- O += P V ----
        #pragma unroll
        for (int ks = 0; ks < 8; ++ks) {
            int kk = ks * 8;
            const float2* pr0 = Ps + (qrow0 + gid) * ASTR;
            const float2* pr1 = pr0 + 8 * ASTR;
            float2 A0 = pr0[kk + tig];
            float2 A1 = pr1[kk + tig];
            float2 A2 = pr0[kk + 4 + tig];
            float2 A3 = pr1[kk + 4 + tig];
            #pragma unroll
            for (int nt = 0; nt < 8; ++nt) {
                const float2* br = Vt + (nt * 8 + gid) * ASTR;
                float2 B0 = br[kk + tig];
                float2 B1 = br[kk + 4 + tig];
                mma_t(oacc[nt], FU(A0.x), FU(A1.x), FU(A2.x), FU(A3.x), FU(B0.x), FU(B1.x));
                mma_t(oacc[nt], FU(A0.x), FU(A1.x), FU(A2.x), FU(A3.x), FU(B0.y), FU(B1.y));
                mma_t(oacc[nt], FU(A0.y), FU(A1.y), FU(A2.y), FU(A3.y), FU(B0.x), FU(B1.x));
            }
        }
    }

    // ---- write O / l ----
    float inv0 = 1.0f / l0, inv1 = 1.0f / l1;
    int grow0 = b * SEQ + qb * 128 + qrow0 + gid;
    #pragma unroll
    for (int nt = 0; nt < 8; ++nt) {
        int col = h * HD + nt * 8 + tig * 2;
        float2 v0 = make_float2(oacc[nt][0] * inv0, oacc[nt][1] * inv0);
        float2 v1 = make_float2(oacc[nt][2] * inv1, oacc[nt][3] * inv1);
        *(float2*)(out + (size_t)grow0 * DIM + col)       = v0;
        *(float2*)(out + (size_t)(grow0 + 8) * DIM + col) = v1;
    }
}

// ---------------- launch ----------------
extern "C" void kernel_launch(void* const* d_in, const int* in_sizes, int n_in,
                              void* d_out, int out_size)
{
    const float* x     = (const float*)d_in[0];
    const float* qkv_w = (const float*)d_in[1];
    const float* out_w = (const float*)d_in[2];
    const float* out_b = (const float*)d_in[3];
    const float* ff_w1 = (const float*)d_in[4];
    const float* ff_b1 = (const float*)d_in[5];
    const float* ff_w2 = (const float*)d_in[6];
    const float* ff_b2 = (const float*)d_in[7];
    const float* ln1_w = (const float*)d_in[8];
    const float* ln1_b = (const float*)d_in[9];
    const float* ln2_w = (const float*)d_in[10];
    const float* ln2_b = (const float*)d_in[11];
    float* out = (float*)d_out;

    float *xln, *qkv, *attn, *x1, *xln2, *hbuf;
    cudaGetSymbolAddress((void**)&xln,  g_xln);
    cudaGetSymbolAddress((void**)&qkv,  g_qkv);
    cudaGetSymbolAddress((void**)&attn, g_attn);
    cudaGetSymbolAddress((void**)&x1,   g_x1);
    cudaGetSymbolAddress((void**)&xln2, g_xln2);
    cudaGetSymbolAddress((void**)&hbuf, g_h);

    cudaFuncSetAttribute(gemm_tf32<EPI_NONE>,
        cudaFuncAttributeMaxDynamicSharedMemorySize, GEMM_SM_BYTES);
    cudaFuncSetAttribute(gemm_tf32<EPI_BIAS_RES>,
        cudaFuncAttributeMaxDynamicSharedMemorySize, GEMM_SM_BYTES);
    cudaFuncSetAttribute(gemm_tf32<EPI_BIAS_SILU>,
        cudaFuncAttributeMaxDynamicSharedMemorySize, GEMM_SM_BYTES);
    cudaFuncSetAttribute(attn_tf32,
        cudaFuncAttributeMaxDynamicSharedMemorySize, ATTN_SM_BYTES);

    // 1. LN1
    ln_kernel<<<TOK, 256>>>(x, ln1_w, ln1_b, xln);
    // 2. QKV = xln @ qkv_w^T
    gemm_tf32<EPI_NONE><<<dim3(3 * DIM / 128, TOK / 128), 256, GEMM_SM_BYTES>>>(
        xln, qkv_w, nullptr, nullptr, qkv, TOK, 3 * DIM, DIM);
    // 3. attention
    attn_tf32<<<dim3(SEQ / 128, 2 * NHEAD), 256, ATTN_SM_BYTES>>>(qkv, attn);
    // 4. x1 = x + attn @ out_w^T + out_b
    gemm_tf32<EPI_BIAS_RES><<<dim3(DIM / 128, TOK / 128), 256, GEMM_SM_BYTES>>>(
        attn, out_w, out_b, x, x1, TOK, DIM, DIM);
    // 5. LN2
    ln_kernel<<<TOK, 256>>>(x1, ln2_w, ln2_b, xln2);
    // 6. h = silu(xln2 @ ff_w1^T + ff_b1)
    gemm_tf32<EPI_BIAS_SILU><<<dim3(MLPD / 128, TOK / 128), 256, GEMM_SM_BYTES>>>(
        xln2, ff_w1, ff_b1, nullptr, hbuf, TOK, MLPD, DIM);
    // 7. out = x1 + h @ ff_w2^T + ff_b2
    gemm_tf32<EPI_BIAS_RES><<<dim3(DIM / 128, TOK / 128), 256, GEMM_SM_BYTES>>>(
        hbuf, ff_w2, ff_b2, x1, out, TOK, MLPD >= DIM ? DIM : DIM, MLPD);
}

// round 4
// speedup vs baseline: 2.1301x; 2.1301x over previous
#include <cuda_runtime.h>
#include <cuda_bf16.h>
#include <math.h>
#include <stdint.h>

#define TOK   4096
#define DIM   1024
#define MLPD  4096
#define NHEAD 16
#define HD    64
#define SEQ   2048

// ---------------- scratch ----------------
__device__ float g_xln [TOK * DIM];
__device__ float g_qkv [TOK * 3 * DIM];
__device__ float g_attn[TOK * DIM];
__device__ float g_x1  [TOK * DIM];
__device__ float g_xln2[TOK * DIM];
__device__ float g_h   [TOK * MLPD];

// ---------------- LayerNorm ----------------
__global__ __launch_bounds__(256) void ln_kernel(
    const float* __restrict__ x, const float* __restrict__ w,
    const float* __restrict__ b, float* __restrict__ out)
{
    int row = blockIdx.x;
    int tid = threadIdx.x;
    const float4* xr = (const float4*)(x + (size_t)row * DIM);
    float4 v = xr[tid];

    __shared__ float red[9];
    float s = v.x + v.y + v.z + v.w;
    #pragma unroll
    for (int o = 16; o > 0; o >>= 1) s += __shfl_xor_sync(0xffffffffu, s, o);
    if ((tid & 31) == 0) red[tid >> 5] = s;
    __syncthreads();
    if (tid == 0) {
        float t = 0.f;
        #pragma unroll
        for (int i = 0; i < 8; i++) t += red[i];
        red[8] = t * (1.0f / DIM);
    }
    __syncthreads();
    float mean = red[8];
    float dx = v.x - mean, dy = v.y - mean, dz = v.z - mean, dw = v.w - mean;
    float sq = dx*dx + dy*dy + dz*dz + dw*dw;
    #pragma unroll
    for (int o = 16; o > 0; o >>= 1) sq += __shfl_xor_sync(0xffffffffu, sq, o);
    if ((tid & 31) == 0) red[tid >> 5] = sq;
    __syncthreads();
    if (tid == 0) {
        float t = 0.f;
        #pragma unroll
        for (int i = 0; i < 8; i++) t += red[i];
        red[8] = rsqrtf(t * (1.0f / DIM) + 1e-5f);
    }
    __syncthreads();
    float rstd = red[8];

    float4 wv = ((const float4*)w)[tid];
    float4 bv = ((const float4*)b)[tid];
    float4 o;
    o.x = dx * rstd * wv.x + bv.x;
    o.y = dy * rstd * wv.y + bv.y;
    o.z = dz * rstd * wv.z + bv.z;
    o.w = dw * rstd * wv.w + bv.w;
    ((float4*)(out + (size_t)row * DIM))[tid] = o;
}

// ---------------- bf16 split helpers ----------------
__device__ __forceinline__ void split_pair(float x, float y, uint32_t& hi, uint32_t& lo) {
    __nv_bfloat162 h = __floats2bfloat162_rn(x, y);     // .x = x (low half)
    float rx = x - __bfloat162float(h.x);
    float ry = y - __bfloat162float(h.y);
    __nv_bfloat162 l = __floats2bfloat162_rn(rx, ry);
    hi = *(uint32_t*)&h;
    lo = *(uint32_t*)&l;
}

__device__ __forceinline__ void mma_bf16(float* d,
    uint32_t a0, uint32_t a1, uint32_t a2, uint32_t a3,
    uint32_t b0, uint32_t b1)
{
    asm volatile(
        "mma.sync.aligned.m16n8k16.row.col.f32.bf16.bf16.f32 "
        "{%0,%1,%2,%3}, {%4,%5,%6,%7}, {%8,%9}, {%0,%1,%2,%3};"
        : "+f"(d[0]), "+f"(d[1]), "+f"(d[2]), "+f"(d[3])
        : "r"(a0), "r"(a1), "r"(a2), "r"(a3), "r"(b0), "r"(b1));
}

// ---------------- NT GEMM (3xBF16 split): C = A[M,K] @ B[N,K]^T + epi -------
// 128x128 CTA tile, KT=16, double-buffered packed-bf16x2 hi/lo planes.
#define EPI_NONE      0
#define EPI_BIAS_RES  1
#define EPI_BIAS_SILU 2

#define WST 12                        // words per smem row (8 data + 4 pad)
#define PLANE (128 * WST)             // 1536 words per plane

template <int EPI>
__global__ __launch_bounds__(256, 2) void gemm_bf16(
    const float* __restrict__ A, const float* __restrict__ Bm,
    const float* __restrict__ bias, const float* __restrict__ res,
    float* __restrict__ C, int M, int N, int K)
{
    // [2 stages][2 planes hi/lo][128 rows][WST]; A then B. 12288 words = 48KB.
    __shared__ uint32_t smw[8 * PLANE];

    int tid  = threadIdx.x;
    int bm   = blockIdx.y * 128;
    int bn   = blockIdx.x * 128;
    int warp = tid >> 5, lane = tid & 31;
    int wm   = (warp & 1) * 64;
    int wn   = (warp >> 1) * 32;
    int gid  = lane >> 2, tig = lane & 3;

    int lr = tid & 127;
    int lk = (tid >> 7) * 8;          // 0 or 8
    const float* ag = A  + (size_t)(bm + lr) * K + lk;
    const float* bg = Bm + (size_t)(bn + lr) * K + lk;
    int wbase = lr * WST + (lk >> 1); // word offset within a plane

    float acc[4][4][4];
    #pragma unroll
    for (int i = 0; i < 4; i++)
        #pragma unroll
        for (int j = 0; j < 4; j++)
            #pragma unroll
            for (int r = 0; r < 4; r++) acc[i][j][r] = 0.f;

    int ntiles = K >> 4;

    // split 8 floats -> 4 hi words + 4 lo words, store as uint4
    auto store8 = [&](uint32_t* hp, uint32_t* lp, float4 v0, float4 v1) {
        uint4 hw, lw;
        split_pair(v0.x, v0.y, hw.x, lw.x);
        split_pair(v0.z, v0.w, hw.y, lw.y);
        split_pair(v1.x, v1.y, hw.z, lw.z);
        split_pair(v1.z, v1.w, hw.w, lw.w);
        *(uint4*)hp = hw;
        *(uint4*)lp = lw;
    };

    // prologue: tile 0 -> stage 0
    float4 ra0 = *(const float4*)ag;
    float4 ra1 = *(const float4*)(ag + 4);
    float4 rb0 = *(const float4*)bg;
    float4 rb1 = *(const float4*)(bg + 4);
    store8(smw + 0 * PLANE + wbase, smw + 1 * PLANE + wbase, ra0, ra1);
    store8(smw + 4 * PLANE + wbase, smw + 5 * PLANE + wbase, rb0, rb1);
    __syncthreads();

    for (int t = 0; t < ntiles; ++t) {
        if (t + 1 < ntiles) {
            const float* an = ag + (size_t)(t + 1) * 16;
            const float* bn2 = bg + (size_t)(t + 1) * 16;
            ra0 = *(const float4*)an;  ra1 = *(const float4*)(an + 4);
            rb0 = *(const float4*)bn2; rb1 = *(const float4*)(bn2 + 4);
        }
        int s2 = (t & 1) * 2;
        const uint32_t* Ah = smw + s2 * PLANE;
        const uint32_t* Al = Ah + PLANE;
        const uint32_t* Bh = smw + (4 + s2) * PLANE;
        const uint32_t* Bl = Bh + PLANE;

        uint32_t bh[4][2], bl[4][2];
        #pragma unroll
        for (int nt = 0; nt < 4; ++nt) {
            int n = (wn + nt * 8 + gid) * WST;
            bh[nt][0] = Bh[n + tig];     bh[nt][1] = Bh[n + 4 + tig];
            bl[nt][0] = Bl[n + tig];     bl[nt][1] = Bl[n + 4 + tig];
        }
        #pragma unroll
        for (int mt = 0; mt < 4; ++mt) {
            int r0 = (wm + mt * 16 + gid) * WST;
            int r1 = r0 + 8 * WST;
            uint32_t ah0 = Ah[r0 + tig],     ah1 = Ah[r1 + tig];
            uint32_t ah2 = Ah[r0 + 4 + tig], ah3 = Ah[r1 + 4 + tig];
            uint32_t al0 = Al[r0 + tig],     al1 = Al[r1 + tig];
            uint32_t al2 = Al[r0 + 4 + tig], al3 = Al[r1 + 4 + tig];
            #pragma unroll
            for (int nt = 0; nt < 4; ++nt) {
                mma_bf16(acc[mt][nt], ah0, ah1, ah2, ah3, bh[nt][0], bh[nt][1]); // hi*hi
                mma_bf16(acc[mt][nt], ah0, ah1, ah2, ah3, bl[nt][0], bl[nt][1]); // hi*lo
                mma_bf16(acc[mt][nt], al0, al1, al2, al3, bh[nt][0], bh[nt][1]); // lo*hi
            }
        }

        if (t + 1 < ntiles) {
            int n2 = ((t + 1) & 1) * 2;
            store8(smw + n2 * PLANE + wbase, smw + (n2 + 1) * PLANE + wbase, ra0, ra1);
            store8(smw + (4 + n2) * PLANE + wbase, smw + (5 + n2) * PLANE + wbase, rb0, rb1);
        }
        __syncthreads();
    }

    // epilogue
    #pragma unroll
    for (int mt = 0; mt < 4; ++mt) {
        #pragma unroll
        for (int nt = 0; nt < 4; ++nt) {
            int row = bm + wm + mt * 16 + gid;
            int col = bn + wn + nt * 8 + tig * 2;
            float2 v0 = make_float2(acc[mt][nt][0], acc[mt][nt][1]);
            float2 v1 = make_float2(acc[mt][nt][2], acc[mt][nt][3]);
            if (EPI != EPI_NONE) {
                float bx = bias[col], by = bias[col + 1];
                v0.x += bx; v0.y += by; v1.x += bx; v1.y += by;
            }
            if (EPI == EPI_BIAS_RES) {
                float2 r0 = *(const float2*)(res + (size_t)row * N + col);
                float2 r1 = *(const float2*)(res + (size_t)(row + 8) * N + col);
                v0.x += r0.x; v0.y += r0.y; v1.x += r1.x; v1.y += r1.y;
            } else if (EPI == EPI_BIAS_SILU) {
                v0.x *= 1.f / (1.f + __expf(-v0.x));
                v0.y *= 1.f / (1.f + __expf(-v0.y));
                v1.x *= 1.f / (1.f + __expf(-v1.x));
                v1.y *= 1.f / (1.f + __expf(-v1.y));
            }
            *(float2*)(C + (size_t)row * N + col)       = v0;
            *(float2*)(C + (size_t)(row + 8) * N + col) = v1;
        }
    }
}

// ---------------- Flash attention, 3xBF16 split HMMA ----------------
// 256 threads; Q tile 128 rows; K/V tiles 64. Warp w owns Q rows 16w..16w+15.
// smem word layout (stride AST=36 words/row = 32 data + 4 pad):
#define AST 36
#define W_QH 0
#define W_QL (W_QH + 128 * AST)
#define W_KH (W_QL + 128 * AST)
#define W_KL (W_KH + 64 * AST)
#define W_VH (W_KL + 64 * AST)
#define W_VL (W_VH + 64 * AST)
#define W_PH (W_VL + 64 * AST)
#define W_PL (W_PH + 128 * AST)
#define ATTN_WORDS (W_PL + 128 * AST)
#define ATTN_SM_BYTES (ATTN_WORDS * 4)   // 110592

__global__ __launch_bounds__(256, 2) void attn_bf16(
    const float* __restrict__ qkv, float* __restrict__ out)
{
    extern __shared__ uint32_t smw[];
    uint32_t* Qh = smw + W_QH;  uint32_t* Ql = smw + W_QL;
    uint32_t* Kh = smw + W_KH;  uint32_t* Kl = smw + W_KL;
    uint32_t* Vh = smw + W_VH;  uint32_t* Vl = smw + W_VL;
    uint32_t* Ph = smw + W_PH;  uint32_t* Pl = smw + W_PL;

    int tid  = threadIdx.x;
    int warp = tid >> 5, lane = tid & 31;
    int gid  = lane >> 2, tig = lane & 3;
    int qrow0 = warp * 16;

    int qb = blockIdx.x;
    int b  = blockIdx.y >> 4;
    int h  = blockIdx.y & 15;

    // ---- fill Q (pre-scaled by 1/8) ----
    const float* qbase = qkv + (size_t)(b * SEQ + qb * 128) * (3 * DIM) + h * HD;
    for (int e = tid; e < 128 * 16; e += 256) {
        int r = e >> 4, c4 = (e & 15) * 4;
        float4 v = *(const float4*)(qbase + (size_t)r * (3 * DIM) + c4);
        uint32_t h0, l0, h1, l1;
        split_pair(v.x * 0.125f, v.y * 0.125f, h0, l0);
        split_pair(v.z * 0.125f, v.w * 0.125f, h1, l1);
        int w = r * AST + (c4 >> 1);
        *(uint2*)(Qh + w) = make_uint2(h0, h1);
        *(uint2*)(Ql + w) = make_uint2(l0, l1);
    }

    float m0 = -1e30f, m1 = -1e30f, l0r = 0.f, l1r = 0.f;
    float oacc[8][4];
    #pragma unroll
    for (int nt = 0; nt < 8; nt++)
        #pragma unroll
        for (int r = 0; r < 4; r++) oacc[nt][r] = 0.f;

    for (int jb = 0; jb < SEQ / 64; ++jb) {
        __syncthreads();     // prev tile consumed; Q visible on first iter
        const float* kb = qkv + (size_t)(b * SEQ + jb * 64) * (3 * DIM) + h * HD + DIM;
        const float* vb = kb + DIM;
        // K: rows j, packed d-pairs
        for (int e = tid; e < 64 * 16; e += 256) {
            int r = e >> 4, c4 = (e & 15) * 4;
            float4 kv = *(const float4*)(kb + (size_t)r * (3 * DIM) + c4);
            uint32_t h0, lo0, h1, lo1;
            split_pair(kv.x, kv.y, h0, lo0);
            split_pair(kv.z, kv.w, h1, lo1);
            int w = r * AST + (c4 >> 1);
            *(uint2*)(Kh + w) = make_uint2(h0, h1);
            *(uint2*)(Kl + w) = make_uint2(lo0, lo1);
        }
        // V transposed: rows d, packed j-pairs
        for (int e = tid; e < 32 * 16; e += 256) {
            int r2 = e >> 4, c4 = (e & 15) * 4;
            float4 va = *(const float4*)(vb + (size_t)(2 * r2)     * (3 * DIM) + c4);
            float4 vc = *(const float4*)(vb + (size_t)(2 * r2 + 1) * (3 * DIM) + c4);
            uint32_t hw, lw;
            split_pair(va.x, vc.x, hw, lw); Vh[(c4+0)*AST + r2] = hw; Vl[(c4+0)*AST + r2] = lw;
            split_pair(va.y, vc.y, hw, lw); Vh[(c4+1)*AST + r2] = hw; Vl[(c4+1)*AST + r2] = lw;
            split_pair(va.z, vc.z, hw, lw); Vh[(c4+2)*AST + r2] = hw; Vl[(c4+2)*AST + r2] = lw;
            split_pair(va.w, vc.w, hw, lw); Vh[(c4+3)*AST + r2] = hw; Vl[(c4+3)*AST + r2] = lw;
        }
        __syncthreads();

        // ---- S = Q K^T ----
        float s[8][4];
        #pragma unroll
        for (int nt = 0; nt < 8; nt++)
            #pragma unroll
            for (int r = 0; r < 4; r++) s[nt][r] = 0.f;

        #pragma unroll
        for (int kc = 0; kc < 4; ++kc) {
            int wb = kc * 8;
            int r0 = (qrow0 + gid) * AST + wb;
            int r1 = r0 + 8 * AST;
            uint32_t ah0 = Qh[r0 + tig],     ah1 = Qh[r1 + tig];
            uint32_t ah2 = Qh[r0 + 4 + tig], ah3 = Qh[r1 + 4 + tig];
            uint32_t al0 = Ql[r0 + tig],     al1 = Ql[r1 + tig];
            uint32_t al2 = Ql[r0 + 4 + tig], al3 = Ql[r1 + 4 + tig];
            #pragma unroll
            for (int nt = 0; nt < 8; ++nt) {
                int n = (nt * 8 + gid) * AST + wb;
                uint32_t bh0 = Kh[n + tig], bh1 = Kh[n + 4 + tig];
                uint32_t bl0 = Kl[n + tig], bl1 = Kl[n + 4 + tig];
                mma_bf16(s[nt], ah0, ah1, ah2, ah3, bh0, bh1);
                mma_bf16(s[nt], ah0, ah1, ah2, ah3, bl0, bl1);
                mma_bf16(s[nt], al0, al1, al2, al3, bh0, bh1);
            }
        }

        // ---- online softmax ----
        float mc0 = s[0][0], mc1 = s[0][2];
        #pragma unroll
        for (int nt = 0; nt < 8; ++nt) {
            mc0 = fmaxf(mc0, fmaxf(s[nt][0], s[nt][1]));
            mc1 = fmaxf(mc1, fmaxf(s[nt][2], s[nt][3]));
        }
        mc0 = fmaxf(mc0, __shfl_xor_sync(0xffffffffu, mc0, 1));
        mc0 = fmaxf(mc0, __shfl_xor_sync(0xffffffffu, mc0, 2));
        mc1 = fmaxf(mc1, __shfl_xor_sync(0xffffffffu, mc1, 1));
        mc1 = fmaxf(mc1, __shfl_xor_sync(0xffffffffu, mc1, 2));
        float mn0 = fmaxf(m0, mc0), mn1 = fmaxf(m1, mc1);
        float f0 = __expf(m0 - mn0), f1 = __expf(m1 - mn1);
        m0 = mn0; m1 = mn1;

        float ps0 = 0.f, ps1 = 0.f;
        #pragma unroll
        for (int nt = 0; nt < 8; ++nt) {
            float p0 = __expf(s[nt][0] - m0);
            float p1 = __expf(s[nt][1] - m0);
            float p2 = __expf(s[nt][2] - m1);
            float p3 = __expf(s[nt][3] - m1);
            ps0 += p0 + p1; ps1 += p2 + p3;
            uint32_t hw, lw;
            int w0 = (qrow0 + gid) * AST + nt * 4 + tig;
            split_pair(p0, p1, hw, lw); Ph[w0] = hw; Pl[w0] = lw;
            int w1 = (qrow0 + 8 + gid) * AST + nt * 4 + tig;
            split_pair(p2, p3, hw, lw); Ph[w1] = hw; Pl[w1] = lw;
        }
        ps0 += __shfl_xor_sync(0xffffffffu, ps0, 1);
        ps0 += __shfl_xor_sync(0xffffffffu, ps0, 2);
        ps1 += __shfl_xor_sync(0xffffffffu, ps1, 1);
        ps1 += __shfl_xor_sync(0xffffffffu, ps1, 2);
        l0r = l0r * f0 + ps0;
        l1r = l1r * f1 + ps1;
        #pragma unroll
        for (int nt = 0; nt < 8; ++nt) {
            oacc[nt][0] *= f0; oacc[nt][1] *= f0;
            oacc[nt][2] *= f1; oacc[nt][3] *= f1;
        }
        __syncwarp();        // P rows are warp-private

        // ---- O += P V ----
        #pragma unroll
        for (int kc = 0; kc < 4; ++kc) {
            int wb = kc * 8;
            int r0 = (qrow0 + gid) * AST + wb;
            int r1 = r0 + 8 * AST;
            uint32_t ah0 = Ph[r0 + tig],     ah1 = Ph[r1 + tig];
            uint32_t ah2 = Ph[r0 + 4 + tig], ah3 = Ph[r1 + 4 + tig];
            uint32_t al0 = Pl[r0 + tig],     al1 = Pl[r1 + tig];
            uint32_t al2 = Pl[r0 + 4 + tig], al3 = Pl[r1 + 4 + tig];
            #pragma unroll
            for (int nt = 0; nt < 8; ++nt) {
                int n = (nt * 8 + gid) * AST + wb;
                uint32_t bh0 = Vh[n + tig], bh1 = Vh[n + 4 + tig];
                uint32_t bl0 = Vl[n + tig], bl1 = Vl[n + 4 + tig];
                mma_bf16(oacc[nt], ah0, ah1, ah2, ah3, bh0, bh1);
                mma_bf16(oacc[nt], ah0, ah1, ah2, ah3, bl0, bl1);
                mma_bf16(oacc[nt], al0, al1, al2, al3, bh0, bh1);
            }
        }
    }

    // ---- write O ----
    float inv0 = 1.0f / l0r, inv1 = 1.0f / l1r;
    int grow0 = b * SEQ + qb * 128 + qrow0 + gid;
    #pragma unroll
    for (int nt = 0; nt < 8; ++nt) {
        int col = h * HD + nt * 8 + tig * 2;
        float2 v0 = make_float2(oacc[nt][0] * inv0, oacc[nt][1] * inv0);
        float2 v1 = make_float2(oacc[nt][2] * inv1, oacc[nt][3] * inv1);
        *(float2*)(out + (size_t)grow0 * DIM + col)       = v0;
        *(float2*)(out + (size_t)(grow0 + 8) * DIM + col) = v1;
    }
}

// ---------------- launch ----------------
extern "C" void kernel_launch(void* const* d_in, const int* in_sizes, int n_in,
                              void* d_out, int out_size)
{
    const float* x     = (const float*)d_in[0];
    const float* qkv_w = (const float*)d_in[1];
    const float* out_w = (const float*)d_in[2];
    const float* out_b = (const float*)d_in[3];
    const float* ff_w1 = (const float*)d_in[4];
    const float* ff_b1 = (const float*)d_in[5];
    const float* ff_w2 = (const float*)d_in[6];
    const float* ff_b2 = (const float*)d_in[7];
    const float* ln1_w = (const float*)d_in[8];
    const float* ln1_b = (const float*)d_in[9];
    const float* ln2_w = (const float*)d_in[10];
    const float* ln2_b = (const float*)d_in[11];
    float* out = (float*)d_out;

    float *xln, *qkv, *attn, *x1, *xln2, *hbuf;
    cudaGetSymbolAddress((void**)&xln,  g_xln);
    cudaGetSymbolAddress((void**)&qkv,  g_qkv);
    cudaGetSymbolAddress((void**)&attn, g_attn);
    cudaGetSymbolAddress((void**)&x1,   g_x1);
    cudaGetSymbolAddress((void**)&xln2, g_xln2);
    cudaGetSymbolAddress((void**)&hbuf, g_h);

    cudaFuncSetAttribute(attn_bf16,
        cudaFuncAttributeMaxDynamicSharedMemorySize, ATTN_SM_BYTES);

    // 1. LN1
    ln_kernel<<<TOK, 256>>>(x, ln1_w, ln1_b, xln);
    // 2. QKV = xln @ qkv_w^T
    gemm_bf16<EPI_NONE><<<dim3(3 * DIM / 128, TOK / 128), 256>>>(
        xln, qkv_w, nullptr, nullptr, qkv, TOK, 3 * DIM, DIM);
    // 3. attention
    attn_bf16<<<dim3(SEQ / 128, 2 * NHEAD), 256, ATTN_SM_BYTES>>>(qkv, attn);
    // 4. x1 = x + attn @ out_w^T + out_b
    gemm_bf16<EPI_BIAS_RES><<<dim3(DIM / 128, TOK / 128), 256>>>(
        attn, out_w, out_b, x, x1, TOK, DIM, DIM);
    // 5. LN2
    ln_kernel<<<TOK, 256>>>(x1, ln2_w, ln2_b, xln2);
    // 6. h = silu(xln2 @ ff_w1^T + ff_b1)
    gemm_bf16<EPI_BIAS_SILU><<<dim3(MLPD / 128, TOK / 128), 256>>>(
        xln2, ff_w1, ff_b1, nullptr, hbuf, TOK, MLPD, DIM);
    // 7. out = x1 + h @ ff_w2^T + ff_b2
    gemm_bf16<EPI_BIAS_RES><<<dim3(DIM / 128, TOK / 128), 256>>>(
        hbuf, ff_w2, ff_b2, x1, out, TOK, DIM, MLPD);
}

// round 6
// speedup vs baseline: 2.5140x; 1.1802x over previous
#include <cuda_runtime.h>
#include <cuda_bf16.h>
#include <math.h>
#include <stdint.h>

#define TOK   4096
#define DIM   1024
#define MLPD  4096
#define NHEAD 16
#define HD    64
#define SEQ   2048

typedef __nv_bfloat16 bf16;

// ---------------- scratch ----------------
__device__ float g_qkv [TOK * 3 * DIM];
__device__ float g_x1  [TOK * DIM];
// split activation planes
__device__ bf16 g_xln_h [TOK * DIM];
__device__ bf16 g_xln_l [TOK * DIM];
__device__ bf16 g_attn_h[TOK * DIM];
__device__ bf16 g_attn_l[TOK * DIM];
__device__ bf16 g_xln2_h[TOK * DIM];
__device__ bf16 g_xln2_l[TOK * DIM];
__device__ bf16 g_hh    [TOK * MLPD];
__device__ bf16 g_hl    [TOK * MLPD];
// split weight planes
__device__ bf16 g_wqkv_h[3 * DIM * DIM];
__device__ bf16 g_wqkv_l[3 * DIM * DIM];
__device__ bf16 g_wout_h[DIM * DIM];
__device__ bf16 g_wout_l[DIM * DIM];
__device__ bf16 g_w1_h  [MLPD * DIM];
__device__ bf16 g_w1_l  [MLPD * DIM];
__device__ bf16 g_w2_h  [DIM * MLPD];
__device__ bf16 g_w2_l  [DIM * MLPD];

// ---------------- helpers ----------------
__device__ __forceinline__ void split_pair(float x, float y, uint32_t& hi, uint32_t& lo) {
    __nv_bfloat162 h = __floats2bfloat162_rn(x, y);
    float rx = x - __bfloat162float(h.x);
    float ry = y - __bfloat162float(h.y);
    __nv_bfloat162 l = __floats2bfloat162_rn(rx, ry);
    hi = *(uint32_t*)&h;
    lo = *(uint32_t*)&l;
}

__device__ __forceinline__ void mma_bf16(float* d,
    uint32_t a0, uint32_t a1, uint32_t a2, uint32_t a3,
    uint32_t b0, uint32_t b1)
{
    asm volatile(
        "mma.sync.aligned.m16n8k16.row.col.f32.bf16.bf16.f32 "
        "{%0,%1,%2,%3}, {%4,%5,%6,%7}, {%8,%9}, {%0,%1,%2,%3};"
        : "+f"(d[0]), "+f"(d[1]), "+f"(d[2]), "+f"(d[3])
        : "r"(a0), "r"(a1), "r"(a2), "r"(a3), "r"(b0), "r"(b1));
}

#define CP16(dst, src) \
    asm volatile("cp.async.ca.shared.global [%0], [%1], 16;" :: "r"(dst), "l"(src) : "memory")
#define CP_COMMIT() asm volatile("cp.async.commit_group;" ::: "memory")
#define CP_WAIT2()  asm volatile("cp.async.wait_group 2;" ::: "memory")

// ---------------- weight/operand split kernel (n % 4 == 0) ----------------
__global__ __launch_bounds__(256) void split_kernel(
    const float* __restrict__ src, bf16* __restrict__ hi, bf16* __restrict__ lo, int n4)
{
    int i = blockIdx.x * 256 + threadIdx.x;
    if (i >= n4) return;
    float4 v = ((const float4*)src)[i];
    uint32_t h0, l0, h1, l1;
    split_pair(v.x, v.y, h0, l0);
    split_pair(v.z, v.w, h1, l1);
    ((uint2*)hi)[i] = make_uint2(h0, h1);
    ((uint2*)lo)[i] = make_uint2(l0, l1);
}

// ---------------- LayerNorm -> split bf16 planes ----------------
__global__ __launch_bounds__(256) void ln_kernel(
    const float* __restrict__ x, const float* __restrict__ w,
    const float* __restrict__ b, bf16* __restrict__ oh, bf16* __restrict__ ol)
{
    int row = blockIdx.x;
    int tid = threadIdx.x;
    const float4* xr = (const float4*)(x + (size_t)row * DIM);
    float4 v = xr[tid];

    __shared__ float red[9];
    float s = v.x + v.y + v.z + v.w;
    #pragma unroll
    for (int o = 16; o > 0; o >>= 1) s += __shfl_xor_sync(0xffffffffu, s, o);
    if ((tid & 31) == 0) red[tid >> 5] = s;
    __syncthreads();
    if (tid == 0) {
        float t = 0.f;
        #pragma unroll
        for (int i = 0; i < 8; i++) t += red[i];
        red[8] = t * (1.0f / DIM);
    }
    __syncthreads();
    float mean = red[8];
    float dx = v.x - mean, dy = v.y - mean, dz = v.z - mean, dw = v.w - mean;
    float sq = dx*dx + dy*dy + dz*dz + dw*dw;
    #pragma unroll
    for (int o = 16; o > 0; o >>= 1) sq += __shfl_xor_sync(0xffffffffu, sq, o);
    if ((tid & 31) == 0) red[tid >> 5] = sq;
    __syncthreads();
    if (tid == 0) {
        float t = 0.f;
        #pragma unroll
        for (int i = 0; i < 8; i++) t += red[i];
        red[8] = rsqrtf(t * (1.0f / DIM) + 1e-5f);
    }
    __syncthreads();
    float rstd = red[8];

    float4 wv = ((const float4*)w)[tid];
    float4 bv = ((const float4*)b)[tid];
    float ox = dx * rstd * wv.x + bv.x;
    float oy = dy * rstd * wv.y + bv.y;
    float oz = dz * rstd * wv.z + bv.z;
    float ow = dw * rstd * wv.w + bv.w;
    uint32_t h0, l0, h1, l1;
    split_pair(ox, oy, h0, l0);
    split_pair(oz, ow, h1, l1);
    size_t idx4 = (size_t)row * (DIM / 4) + tid;
    ((uint2*)oh)[idx4] = make_uint2(h0, h1);
    ((uint2*)ol)[idx4] = make_uint2(l0, l1);
}

// ---------------- NT GEMM, pre-split bf16 inputs, cp.async 4-stage ----------
// C[M,N] = A[M,K] @ B[N,K]^T (3xBF16 split). 128x128 CTA tile.
#define EPI_NONE      0
#define EPI_BIAS_RES  1
#define EPI_SILU_SPL  2

#define WST  12                      // words per smem row (8 data + 4 pad)
#define PLW  (128 * WST)             // words per plane
#define STGW (4 * PLW)               // words per stage (AH AL BH BL)
#define NSTAGE 4
#define GEMM_SMEM (NSTAGE * STGW * 4)   // 98304

template <int EPI>
__global__ __launch_bounds__(256, 2) void gemm_sp(
    const bf16* __restrict__ Ah, const bf16* __restrict__ Al,
    const bf16* __restrict__ Bh, const bf16* __restrict__ Bl,
    const float* __restrict__ bias, const float* __restrict__ res,
    float* __restrict__ C, bf16* __restrict__ Oh, bf16* __restrict__ Ol,
    int M, int N, int K)
{
    extern __shared__ __align__(16) uint32_t smw[];
    uint32_t sbase = (uint32_t)__cvta_generic_to_shared(smw);

    int tid  = threadIdx.x;
    int warp = tid >> 5, lane = tid & 31;
    int bm   = blockIdx.y * 128;
    int bn   = blockIdx.x * 128;
    int wm   = (warp & 1) * 64;
    int wn   = (warp >> 1) * 32;
    int gid  = lane >> 2, tig = lane & 3;

    // cp.async mapping: thread t loads row t>>1, 8-elem half (t&1)
    int lrow  = tid >> 1;
    int lhalf = (tid & 1) * 8;
    const bf16* pAh = Ah + (size_t)(bm + lrow) * K + lhalf;
    const bf16* pAl = Al + (size_t)(bm + lrow) * K + lhalf;
    const bf16* pBh = Bh + (size_t)(bn + lrow) * K + lhalf;
    const bf16* pBl = Bl + (size_t)(bn + lrow) * K + lhalf;
    uint32_t dstw = (uint32_t)(lrow * WST + (tid & 1) * 4) * 4;  // byte offset in plane

    float acc[4][4][4];
    #pragma unroll
    for (int i = 0; i < 4; i++)
        #pragma unroll
        for (int j = 0; j < 4; j++)
            #pragma unroll
            for (int r = 0; r < 4; r++) acc[i][j][r] = 0.f;

    int ntiles = K >> 4;

    auto issue = [&](int t) {
        uint32_t base = sbase + ((t % NSTAGE) * STGW) * 4 + dstw;
        const bf16* off = (const bf16*)0 + (size_t)t * 16;
        CP16(base,               pAh + (size_t)t * 16);
        CP16(base + PLW * 4,     pAl + (size_t)t * 16);
        CP16(base + 2 * PLW * 4, pBh + (size_t)t * 16);
        CP16(base + 3 * PLW * 4, pBl + (size_t)t * 16);
        (void)off;
    };

    issue(0); CP_COMMIT();
    issue(1); CP_COMMIT();
    issue(2); CP_COMMIT();

    for (int t = 0; t < ntiles; ++t) {
        CP_WAIT2();
        __syncthreads();
        const uint32_t* st = smw + (t % NSTAGE) * STGW;
        const uint32_t* qAh = st;
        const uint32_t* qAl = st + PLW;
        const uint32_t* qBh = st + 2 * PLW;
        const uint32_t* qBl = st + 3 * PLW;

        uint32_t bhf[4][2], blf[4][2];
        #pragma unroll
        for (int nt = 0; nt < 4; ++nt) {
            int n = (wn + nt * 8 + gid) * WST;
            bhf[nt][0] = qBh[n + tig];     bhf[nt][1] = qBh[n + 4 + tig];
            blf[nt][0] = qBl[n + tig];     blf[nt][1] = qBl[n + 4 + tig];
        }
        #pragma unroll
        for (int mt = 0; mt < 4; ++mt) {
            int r0 = (wm + mt * 16 + gid) * WST;
            int r1 = r0 + 8 * WST;
            uint32_t ah0 = qAh[r0 + tig],     ah1 = qAh[r1 + tig];
            uint32_t ah2 = qAh[r0 + 4 + tig], ah3 = qAh[r1 + 4 + tig];
            uint32_t al0 = qAl[r0 + tig],     al1 = qAl[r1 + tig];
            uint32_t al2 = qAl[r0 + 4 + tig], al3 = qAl[r1 + 4 + tig];
            #pragma unroll
            for (int nt = 0; nt < 4; ++nt) {
                mma_bf16(acc[mt][nt], ah0, ah1, ah2, ah3, bhf[nt][0], bhf[nt][1]);
                mma_bf16(acc[mt][nt], ah0, ah1, ah2, ah3, blf[nt][0], blf[nt][1]);
                mma_bf16(acc[mt][nt], al0, al1, al2, al3, bhf[nt][0], bhf[nt][1]);
            }
        }
        if (t + 3 < ntiles) issue(t + 3);
        CP_COMMIT();
    }

    // ---- epilogue ----
    #pragma unroll
    for (int mt = 0; mt < 4; ++mt) {
        #pragma unroll
        for (int nt = 0; nt < 4; ++nt) {
            int row = bm + wm + mt * 16 + gid;
            int col = bn + wn + nt * 8 + tig * 2;
            float2 v0 = make_float2(acc[mt][nt][0], acc[mt][nt][1]);
            float2 v1 = make_float2(acc[mt][nt][2], acc[mt][nt][3]);
            if (EPI != EPI_NONE) {
                float bx = bias[col], by = bias[col + 1];
                v0.x += bx; v0.y += by; v1.x += bx; v1.y += by;
            }
            if (EPI == EPI_BIAS_RES) {
                float2 r0 = *(const float2*)(res + (size_t)row * N + col);
                float2 r1 = *(const float2*)(res + (size_t)(row + 8) * N + col);
                v0.x += r0.x; v0.y += r0.y; v1.x += r1.x; v1.y += r1.y;
                *(float2*)(C + (size_t)row * N + col)       = v0;
                *(float2*)(C + (size_t)(row + 8) * N + col) = v1;
            } else if (EPI == EPI_SILU_SPL) {
                v0.x *= 1.f / (1.f + __expf(-v0.x));
                v0.y *= 1.f / (1.f + __expf(-v0.y));
                v1.x *= 1.f / (1.f + __expf(-v1.x));
                v1.y *= 1.f / (1.f + __expf(-v1.y));
                uint32_t hw, lw;
                split_pair(v0.x, v0.y, hw, lw);
                *(uint32_t*)(Oh + (size_t)row * N + col) = hw;
                *(uint32_t*)(Ol + (size_t)row * N + col) = lw;
                split_pair(v1.x, v1.y, hw, lw);
                *(uint32_t*)(Oh + (size_t)(row + 8) * N + col) = hw;
                *(uint32_t*)(Ol + (size_t)(row + 8) * N + col) = lw;
            } else {
                *(float2*)(C + (size_t)row * N + col)       = v0;
                *(float2*)(C + (size_t)(row + 8) * N + col) = v1;
            }
        }
    }
}

// ---------------- Flash attention, 3xBF16 split HMMA (R4) + split output ----
#define AST 36
#define W_QH 0
#define W_QL (W_QH + 128 * AST)
#define W_KH (W_QL + 128 * AST)
#define W_KL (W_KH + 64 * AST)
#define W_VH (W_KL + 64 * AST)
#define W_VL (W_VH + 64 * AST)
#define W_PH (W_VL + 64 * AST)
#define W_PL (W_PH + 128 * AST)
#define ATTN_WORDS (W_PL + 128 * AST)
#define ATTN_SM_BYTES (ATTN_WORDS * 4)

__global__ __launch_bounds__(256, 2) void attn_bf16(
    const float* __restrict__ qkv, bf16* __restrict__ oh, bf16* __restrict__ ol)
{
    extern __shared__ uint32_t smw[];
    uint32_t* Qh = smw + W_QH;  uint32_t* Ql = smw + W_QL;
    uint32_t* Kh = smw + W_KH;  uint32_t* Kl = smw + W_KL;
    uint32_t* Vh = smw + W_VH;  uint32_t* Vl = smw + W_VL;
    uint32_t* Ph = smw + W_PH;  uint32_t* Pl = smw + W_PL;

    int tid  = threadIdx.x;
    int warp = tid >> 5, lane = tid & 31;
    int gid  = lane >> 2, tig = lane & 3;
    int qrow0 = warp * 16;

    int qb = blockIdx.x;
    int b  = blockIdx.y >> 4;
    int h  = blockIdx.y & 15;

    const float* qbase = qkv + (size_t)(b * SEQ + qb * 128) * (3 * DIM) + h * HD;
    for (int e = tid; e < 128 * 16; e += 256) {
        int r = e >> 4, c4 = (e & 15) * 4;
        float4 v = *(const float4*)(qbase + (size_t)r * (3 * DIM) + c4);
        uint32_t h0, l0, h1, l1;
        split_pair(v.x * 0.125f, v.y * 0.125f, h0, l0);
        split_pair(v.z * 0.125f, v.w * 0.125f, h1, l1);
        int w = r * AST + (c4 >> 1);
        *(uint2*)(Qh + w) = make_uint2(h0, h1);
        *(uint2*)(Ql + w) = make_uint2(l0, l1);
    }

    float m0 = -1e30f, m1 = -1e30f, l0r = 0.f, l1r = 0.f;
    float oacc[8][4];
    #pragma unroll
    for (int nt = 0; nt < 8; nt++)
        #pragma unroll
        for (int r = 0; r < 4; r++) oacc[nt][r] = 0.f;

    for (int jb = 0; jb < SEQ / 64; ++jb) {
        __syncthreads();
        const float* kb = qkv + (size_t)(b * SEQ + jb * 64) * (3 * DIM) + h * HD + DIM;
        const float* vb = kb + DIM;
        for (int e = tid; e < 64 * 16; e += 256) {
            int r = e >> 4, c4 = (e & 15) * 4;
            float4 kv = *(const float4*)(kb + (size_t)r * (3 * DIM) + c4);
            uint32_t h0, lo0, h1, lo1;
            split_pair(kv.x, kv.y, h0, lo0);
            split_pair(kv.z, kv.w, h1, lo1);
            int w = r * AST + (c4 >> 1);
            *(uint2*)(Kh + w) = make_uint2(h0, h1);
            *(uint2*)(Kl + w) = make_uint2(lo0, lo1);
        }
        for (int e = tid; e < 32 * 16; e += 256) {
            int r2 = e >> 4, c4 = (e & 15) * 4;
            float4 va = *(const float4*)(vb + (size_t)(2 * r2)     * (3 * DIM) + c4);
            float4 vc = *(const float4*)(vb + (size_t)(2 * r2 + 1) * (3 * DIM) + c4);
            uint32_t hw, lw;
            split_pair(va.x, vc.x, hw, lw); Vh[(c4+0)*AST + r2] = hw; Vl[(c4+0)*AST + r2] = lw;
            split_pair(va.y, vc.y, hw, lw); Vh[(c4+1)*AST + r2] = hw; Vl[(c4+1)*AST + r2] = lw;
            split_pair(va.z, vc.z, hw, lw); Vh[(c4+2)*AST + r2] = hw; Vl[(c4+2)*AST + r2] = lw;
            split_pair(va.w, vc.w, hw, lw); Vh[(c4+3)*AST + r2] = hw; Vl[(c4+3)*AST + r2] = lw;
        }
        __syncthreads();

        float s[8][4];
        #pragma unroll
        for (int nt = 0; nt < 8; nt++)
            #pragma unroll
            for (int r = 0; r < 4; r++) s[nt][r] = 0.f;

        #pragma unroll
        for (int kc = 0; kc < 4; ++kc) {
            int wb = kc * 8;
            int r0 = (qrow0 + gid) * AST + wb;
            int r1 = r0 + 8 * AST;
            uint32_t ah0 = Qh[r0 + tig],     ah1 = Qh[r1 + tig];
            uint32_t ah2 = Qh[r0 + 4 + tig], ah3 = Qh[r1 + 4 + tig];
            uint32_t al0 = Ql[r0 + tig],     al1 = Ql[r1 + tig];
            uint32_t al2 = Ql[r0 + 4 + tig], al3 = Ql[r1 + 4 + tig];
            #pragma unroll
            for (int nt = 0; nt < 8; ++nt) {
                int n = (nt * 8 + gid) * AST + wb;
                uint32_t bh0 = Kh[n + tig], bh1 = Kh[n + 4 + tig];
                uint32_t bl0 = Kl[n + tig], bl1 = Kl[n + 4 + tig];
                mma_bf16(s[nt], ah0, ah1, ah2, ah3, bh0, bh1);
                mma_bf16(s[nt], ah0, ah1, ah2, ah3, bl0, bl1);
                mma_bf16(s[nt], al0, al1, al2, al3, bh0, bh1);
            }
        }

        float mc0 = s[0][0], mc1 = s[0][2];
        #pragma unroll
        for (int nt = 0; nt < 8; ++nt) {
            mc0 = fmaxf(mc0, fmaxf(s[nt][0], s[nt][1]));
            mc1 = fmaxf(mc1, fmaxf(s[nt][2], s[nt][3]));
        }
        mc0 = fmaxf(mc0, __shfl_xor_sync(0xffffffffu, mc0, 1));
        mc0 = fmaxf(mc0, __shfl_xor_sync(0xffffffffu, mc0, 2));
        mc1 = fmaxf(mc1, __shfl_xor_sync(0xffffffffu, mc1, 1));
        mc1 = fmaxf(mc1, __shfl_xor_sync(0xffffffffu, mc1, 2));
        float mn0 = fmaxf(m0, mc0), mn1 = fmaxf(m1, mc1);
        float f0 = __expf(m0 - mn0), f1 = __expf(m1 - mn1);
        m0 = mn0; m1 = mn1;

        float ps0 = 0.f, ps1 = 0.f;
        #pragma unroll
        for (int nt = 0; nt < 8; ++nt) {
            float p0 = __expf(s[nt][0] - m0);
            float p1 = __expf(s[nt][1] - m0);
            float p2 = __expf(s[nt][2] - m1);
            float p3 = __expf(s[nt][3] - m1);
            ps0 += p0 + p1; ps1 += p2 + p3;
            uint32_t hw, lw;
            int w0 = (qrow0 + gid) * AST + nt * 4 + tig;
            split_pair(p0, p1, hw, lw); Ph[w0] = hw; Pl[w0] = lw;
            int w1 = (qrow0 + 8 + gid) * AST + nt * 4 + tig;
            split_pair(p2, p3, hw, lw); Ph[w1] = hw; Pl[w1] = lw;
        }
        ps0 += __shfl_xor_sync(0xffffffffu, ps0, 1);
        ps0 += __shfl_xor_sync(0xffffffffu, ps0, 2);
        ps1 += __shfl_xor_sync(0xffffffffu, ps1, 1);
        ps1 += __shfl_xor_sync(0xffffffffu, ps1, 2);
        l0r = l0r * f0 + ps0;
        l1r = l1r * f1 + ps1;
        #pragma unroll
        for (int nt = 0; nt < 8; ++nt) {
            oacc[nt][0] *= f0; oacc[nt][1] *= f0;
            oacc[nt][2] *= f1; oacc[nt][3] *= f1;
        }
        __syncwarp();

        #pragma unroll
        for (int kc = 0; kc < 4; ++kc) {
            int wb = kc * 8;
            int r0 = (qrow0 + gid) * AST + wb;
            int r1 = r0 + 8 * AST;
            uint32_t ah0 = Ph[r0 + tig],     ah1 = Ph[r1 + tig];
            uint32_t ah2 = Ph[r0 + 4 + tig], ah3 = Ph[r1 + 4 + tig];
            uint32_t al0 = Pl[r0 + tig],     al1 = Pl[r1 + tig];
            uint32_t al2 = Pl[r0 + 4 + tig], al3 = Pl[r1 + 4 + tig];
            #pragma unroll
            for (int nt = 0; nt < 8; ++nt) {
                int n = (nt * 8 + gid) * AST + wb;
                uint32_t bh0 = Vh[n + tig], bh1 = Vh[n + 4 + tig];
                uint32_t bl0 = Vl[n + tig], bl1 = Vl[n + 4 + tig];
                mma_bf16(oacc[nt], ah0, ah1, ah2, ah3, bh0, bh1);
                mma_bf16(oacc[nt], ah0, ah1, ah2, ah3, bl0, bl1);
                mma_bf16(oacc[nt], al0, al1, al2, al3, bh0, bh1);
            }
        }
    }

    float inv0 = 1.0f / l0r, inv1 = 1.0f / l1r;
    int grow0 = b * SEQ + qb * 128 + qrow0 + gid;
    #pragma unroll
    for (int nt = 0; nt < 8; ++nt) {
        int col = h * HD + nt * 8 + tig * 2;
        uint32_t hw, lw;
        split_pair(oacc[nt][0] * inv0, oacc[nt][1] * inv0, hw, lw);
        *(uint32_t*)(oh + (size_t)grow0 * DIM + col) = hw;
        *(uint32_t*)(ol + (size_t)grow0 * DIM + col) = lw;
        split_pair(oacc[nt][2] * inv1, oacc[nt][3] * inv1, hw, lw);
        *(uint32_t*)(oh + (size_t)(grow0 + 8) * DIM + col) = hw;
        *(uint32_t*)(ol + (size_t)(grow0 + 8) * DIM + col) = lw;
    }
}

// ---------------- launch ----------------
extern "C" void kernel_launch(void* const* d_in, const int* in_sizes, int n_in,
                              void* d_out, int out_size)
{
    const float* x     = (const float*)d_in[0];
    const float* qkv_w = (const float*)d_in[1];
    const float* out_w = (const float*)d_in[2];
    const float* out_b = (const float*)d_in[3];
    const float* ff_w1 = (const float*)d_in[4];
    const float* ff_b1 = (const float*)d_in[5];
    const float* ff_w2 = (const float*)d_in[6];
    const float* ff_b2 = (const float*)d_in[7];
    const float* ln1_w = (const float*)d_in[8];
    const float* ln1_b = (const float*)d_in[9];
    const float* ln2_w = (const float*)d_in[10];
    const float* ln2_b = (const float*)d_in[11];
    float* out = (float*)d_out;

    float *qkv, *x1;
    bf16 *xlnh, *xlnl, *attnh, *attnl, *xln2h, *xln2l, *hh, *hl;
    bf16 *wqh, *wql, *woh, *wol, *w1h, *w1l, *w2h, *w2l;
    cudaGetSymbolAddress((void**)&qkv,   g_qkv);
    cudaGetSymbolAddress((void**)&x1,    g_x1);
    cudaGetSymbolAddress((void**)&xlnh,  g_xln_h);
    cudaGetSymbolAddress((void**)&xlnl,  g_xln_l);
    cudaGetSymbolAddress((void**)&attnh, g_attn_h);
    cudaGetSymbolAddress((void**)&attnl, g_attn_l);
    cudaGetSymbolAddress((void**)&xln2h, g_xln2_h);
    cudaGetSymbolAddress((void**)&xln2l, g_xln2_l);
    cudaGetSymbolAddress((void**)&hh,    g_hh);
    cudaGetSymbolAddress((void**)&hl,    g_hl);
    cudaGetSymbolAddress((void**)&wqh,   g_wqkv_h);
    cudaGetSymbolAddress((void**)&wql,   g_wqkv_l);
    cudaGetSymbolAddress((void**)&woh,   g_wout_h);
    cudaGetSymbolAddress((void**)&wol,   g_wout_l);
    cudaGetSymbolAddress((void**)&w1h,   g_w1_h);
    cudaGetSymbolAddress((void**)&w1l,   g_w1_l);
    cudaGetSymbolAddress((void**)&w2h,   g_w2_h);
    cudaGetSymbolAddress((void**)&w2l,   g_w2_l);

    cudaFuncSetAttribute(gemm_sp<EPI_NONE>,
        cudaFuncAttributeMaxDynamicSharedMemorySize, GEMM_SMEM);
    cudaFuncSetAttribute(gemm_sp<EPI_BIAS_RES>,
        cudaFuncAttributeMaxDynamicSharedMemorySize, GEMM_SMEM);
    cudaFuncSetAttribute(gemm_sp<EPI_SILU_SPL>,
        cudaFuncAttributeMaxDynamicSharedMemorySize, GEMM_SMEM);
    cudaFuncSetAttribute(attn_bf16,
        cudaFuncAttributeMaxDynamicSharedMemorySize, ATTN_SM_BYTES);

    // 0. split weights (once per replay)
    split_kernel<<<(3 * DIM * DIM / 4 + 255) / 256, 256>>>(qkv_w, wqh, wql, 3 * DIM * DIM / 4);
    split_kernel<<<(DIM * DIM / 4 + 255) / 256, 256>>>(out_w, woh, wol, DIM * DIM / 4);
    split_kernel<<<(MLPD * DIM / 4 + 255) / 256, 256>>>(ff_w1, w1h, w1l, MLPD * DIM / 4);
    split_kernel<<<(DIM * MLPD / 4 + 255) / 256, 256>>>(ff_w2, w2h, w2l, DIM * MLPD / 4);

    // 1. LN1 -> split planes
    ln_kernel<<<TOK, 256>>>(x, ln1_w, ln1_b, xlnh, xlnl);
    // 2. QKV = xln @ qkv_w^T  -> fp32
    gemm_sp<EPI_NONE><<<dim3(3 * DIM / 128, TOK / 128), 256, GEMM_SMEM>>>(
        xlnh, xlnl, wqh, wql, nullptr, nullptr, qkv, nullptr, nullptr,
        TOK, 3 * DIM, DIM);
    // 3. attention -> split planes
    attn_bf16<<<dim3(SEQ / 128, 2 * NHEAD), 256, ATTN_SM_BYTES>>>(qkv, attnh, attnl);
    // 4. x1 = x + attn @ out_w^T + out_b  -> fp32
    gemm_sp<EPI_BIAS_RES><<<dim3(DIM / 128, TOK / 128), 256, GEMM_SMEM>>>(
        attnh, attnl, woh, wol, out_b, x, x1, nullptr, nullptr,
        TOK, DIM, DIM);
    // 5. LN2 -> split planes
    ln_kernel<<<TOK, 256>>>(x1, ln2_w, ln2_b, xln2h, xln2l);
    // 6. h = silu(xln2 @ ff_w1^T + ff_b1) -> split planes
    gemm_sp<EPI_SILU_SPL><<<dim3(MLPD / 128, TOK / 128), 256, GEMM_SMEM>>>(
        xln2h, xln2l, w1h, w1l, ff_b1, nullptr, nullptr, hh, hl,
        TOK, MLPD, DIM);
    // 7. out = x1 + h @ ff_w2^T + ff_b2  -> fp32
    gemm_sp<EPI_BIAS_RES><<<dim3(DIM / 128, TOK / 128), 256, GEMM_SMEM>>>(
        hh, hl, w2h, w2l, ff_b2, x1, out, nullptr, nullptr,
        TOK, DIM, MLPD);
}

// round 8
// speedup vs baseline: 4.3857x; 1.7445x over previous
#include <cuda_runtime.h>
#include <cuda_fp16.h>
#include <math.h>
#include <stdint.h>

#define TOK   4096
#define DIM   1024
#define MLPD  4096
#define NHEAD 16
#define HD    64
#define SEQ   2048

// ---------------- scratch ----------------
__device__ float g_qkv [TOK * 3 * DIM];
__device__ float g_x1  [TOK * DIM];
// single fp16 activation planes
__device__ __half g_xln [TOK * DIM];
__device__ __half g_attn[TOK * DIM];
__device__ __half g_xln2[TOK * DIM];
__device__ __half g_h   [TOK * MLPD];
// split fp16 weight planes
__device__ __half g_wqkv_h[3 * DIM * DIM];
__device__ __half g_wqkv_l[3 * DIM * DIM];
__device__ __half g_wout_h[DIM * DIM];
__device__ __half g_wout_l[DIM * DIM];
__device__ __half g_w1_h  [MLPD * DIM];
__device__ __half g_w1_l  [MLPD * DIM];
__device__ __half g_w2_h  [DIM * MLPD];
__device__ __half g_w2_l  [DIM * MLPD];

// ---------------- helpers ----------------
__device__ __forceinline__ uint32_t cvt2h(float x, float y) {
    __half2 h = __floats2half2_rn(x, y);
    return *(uint32_t*)&h;
}
__device__ __forceinline__ void split_h(float x, float y, uint32_t& hi, uint32_t& lo) {
    __half2 h = __floats2half2_rn(x, y);
    float rx = x - __half2float(__low2half(h));
    float ry = y - __half2float(__high2half(h));
    __half2 l = __floats2half2_rn(rx, ry);
    hi = *(uint32_t*)&h;
    lo = *(uint32_t*)&l;
}

__device__ __forceinline__ void mma_f16(float* d,
    uint32_t a0, uint32_t a1, uint32_t a2, uint32_t a3,
    uint32_t b0, uint32_t b1)
{
    asm volatile(
        "mma.sync.aligned.m16n8k16.row.col.f32.f16.f16.f32 "
        "{%0,%1,%2,%3}, {%4,%5,%6,%7}, {%8,%9}, {%0,%1,%2,%3};"
        : "+f"(d[0]), "+f"(d[1]), "+f"(d[2]), "+f"(d[3])
        : "r"(a0), "r"(a1), "r"(a2), "r"(a3), "r"(b0), "r"(b1));
}

#define LDSM4(R0,R1,R2,R3,ADDR) \
    asm volatile("ldmatrix.sync.aligned.m8n8.x4.shared.b16 {%0,%1,%2,%3}, [%4];" \
        : "=r"(R0), "=r"(R1), "=r"(R2), "=r"(R3) : "r"(ADDR))

#define CP16(dst, src) \
    asm volatile("cp.async.ca.shared.global [%0], [%1], 16;" :: "r"(dst), "l"(src) : "memory")
#define CP_COMMIT() asm volatile("cp.async.commit_group;" ::: "memory")
#define CP_WAIT2()  asm volatile("cp.async.wait_group 2;" ::: "memory")

// ---------------- weight split kernel (fp16 hi/lo) ----------------
__global__ __launch_bounds__(256) void split_w(
    const float* __restrict__ src, __half* __restrict__ hi, __half* __restrict__ lo, int n4)
{
    int i = blockIdx.x * 256 + threadIdx.x;
    if (i >= n4) return;
    float4 v = ((const float4*)src)[i];
    uint32_t h0, l0, h1, l1;
    split_h(v.x, v.y, h0, l0);
    split_h(v.z, v.w, h1, l1);
    ((uint2*)hi)[i] = make_uint2(h0, h1);
    ((uint2*)lo)[i] = make_uint2(l0, l1);
}

// ---------------- LayerNorm -> single fp16 plane ----------------
__global__ __launch_bounds__(256) void ln_kernel(
    const float* __restrict__ x, const float* __restrict__ w,
    const float* __restrict__ b, __half* __restrict__ o)
{
    int row = blockIdx.x;
    int tid = threadIdx.x;
    const float4* xr = (const float4*)(x + (size_t)row * DIM);
    float4 v = xr[tid];

    __shared__ float red[9];
    float s = v.x + v.y + v.z + v.w;
    #pragma unroll
    for (int of = 16; of > 0; of >>= 1) s += __shfl_xor_sync(0xffffffffu, s, of);
    if ((tid & 31) == 0) red[tid >> 5] = s;
    __syncthreads();
    if (tid == 0) {
        float t = 0.f;
        #pragma unroll
        for (int i = 0; i < 8; i++) t += red[i];
        red[8] = t * (1.0f / DIM);
    }
    __syncthreads();
    float mean = red[8];
    float dx = v.x - mean, dy = v.y - mean, dz = v.z - mean, dw = v.w - mean;
    float sq = dx*dx + dy*dy + dz*dz + dw*dw;
    #pragma unroll
    for (int of = 16; of > 0; of >>= 1) sq += __shfl_xor_sync(0xffffffffu, sq, of);
    if ((tid & 31) == 0) red[tid >> 5] = sq;
    __syncthreads();
    if (tid == 0) {
        float t = 0.f;
        #pragma unroll
        for (int i = 0; i < 8; i++) t += red[i];
        red[8] = rsqrtf(t * (1.0f / DIM) + 1e-5f);
    }
    __syncthreads();
    float rstd = red[8];

    float4 wv = ((const float4*)w)[tid];
    float4 bv = ((const float4*)b)[tid];
    float ox = dx * rstd * wv.x + bv.x;
    float oy = dy * rstd * wv.y + bv.y;
    float oz = dz * rstd * wv.z + bv.z;
    float ow = dw * rstd * wv.w + bv.w;
    ((uint2*)o)[(size_t)row * (DIM / 4) + tid] =
        make_uint2(cvt2h(ox, oy), cvt2h(oz, ow));
}

// ---------------- NT GEMM fp16: C = A[M,K] @ (Wh+Wl)[N,K]^T + epi ----------
// 128x128 CTA, KT=16, cp.async 4-stage, ldmatrix frags, 2 MMAs per n8 per k16.
#define EPI_NONE      0
#define EPI_BIAS_RES  1
#define EPI_SILU_H    2

#define WST  12                      // words per smem row (8 data + 4 pad) = 48B
#define PLW  (128 * WST)             // 1536 words per plane
#define STGW (3 * PLW)               // A, Wh, Wl
#define NSTAGE 4
#define GEMM_SMEM (NSTAGE * STGW * 4)   // 73728

template <int EPI>
__global__ __launch_bounds__(256, 2) void gemm_f16(
    const __half* __restrict__ A,
    const __half* __restrict__ Wh, const __half* __restrict__ Wl,
    const float* __restrict__ bias, const float* __restrict__ res,
    float* __restrict__ C, __half* __restrict__ Oh,
    int M, int N, int K)
{
    extern __shared__ __align__(16) uint32_t smw[];
    uint32_t sbase = (uint32_t)__cvta_generic_to_shared(smw);

    int tid  = threadIdx.x;
    int warp = tid >> 5, lane = tid & 31;
    int bm   = blockIdx.y * 128;
    int bn   = blockIdx.x * 128;
    int wm   = (warp & 1) * 64;
    int wn   = (warp >> 1) * 32;
    int gid  = lane >> 2, tig = lane & 3;

    // cp.async: thread t -> row t>>1, 16B half (t&1)
    int lrow  = tid >> 1;
    int lhalf = tid & 1;
    const __half* pA  = A  + (size_t)(bm + lrow) * K + lhalf * 8;
    const __half* pWh = Wh + (size_t)(bn + lrow) * K + lhalf * 8;
    const __half* pWl = Wl + (size_t)(bn + lrow) * K + lhalf * 8;
    uint32_t dstb = (uint32_t)(lrow * WST + lhalf * 4) * 4;

    // ldmatrix offsets (bytes within plane)
    uint32_t a_off = (uint32_t)(((wm + (lane & 15)) * WST + (lane >> 4) * 4) * 4);
    uint32_t b_off = (uint32_t)(((wn + ((lane >> 4) & 1) * 8 + (lane & 7)) * WST
                                 + ((lane >> 3) & 1) * 4) * 4);

    float acc[4][4][4];
    #pragma unroll
    for (int i = 0; i < 4; i++)
        #pragma unroll
        for (int j = 0; j < 4; j++)
            #pragma unroll
            for (int r = 0; r < 4; r++) acc[i][j][r] = 0.f;

    int ntiles = K >> 4;

    auto issue = [&](int t) {
        uint32_t base = sbase + ((t % NSTAGE) * STGW) * 4 + dstb;
        CP16(base,               pA  + (size_t)t * 16);
        CP16(base + PLW * 4,     pWh + (size_t)t * 16);
        CP16(base + 2 * PLW * 4, pWl + (size_t)t * 16);
    };

    issue(0); CP_COMMIT();
    issue(1); CP_COMMIT();
    issue(2); CP_COMMIT();

    for (int t = 0; t < ntiles; ++t) {
        CP_WAIT2();
        __syncthreads();
        uint32_t stb = sbase + ((t % NSTAGE) * STGW) * 4;

        // load W frags (both planes, 4 n-tiles)
        uint32_t bh[4][2], bl[4][2];
        #pragma unroll
        for (int p = 0; p < 2; ++p) {
            uint32_t r0, r1, r2, r3;
            LDSM4(r0, r1, r2, r3, stb + PLW * 4 + b_off + p * 16 * WST * 4);
            bh[2*p][0] = r0; bh[2*p][1] = r1; bh[2*p+1][0] = r2; bh[2*p+1][1] = r3;
            LDSM4(r0, r1, r2, r3, stb + 2 * PLW * 4 + b_off + p * 16 * WST * 4);
            bl[2*p][0] = r0; bl[2*p][1] = r1; bl[2*p+1][0] = r2; bl[2*p+1][1] = r3;
        }
        #pragma unroll
        for (int mt = 0; mt < 4; ++mt) {
            uint32_t a0, a1, a2, a3;
            LDSM4(a0, a1, a2, a3, stb + a_off + mt * 16 * WST * 4);
            #pragma unroll
            for (int nt = 0; nt < 4; ++nt) {
                mma_f16(acc[mt][nt], a0, a1, a2, a3, bh[nt][0], bh[nt][1]);
                mma_f16(acc[mt][nt], a0, a1, a2, a3, bl[nt][0], bl[nt][1]);
            }
        }
        if (t + 3 < ntiles) issue(t + 3);
        CP_COMMIT();
    }

    // ---- epilogue ----
    #pragma unroll
    for (int mt = 0; mt < 4; ++mt) {
        #pragma unroll
        for (int nt = 0; nt < 4; ++nt) {
            int row = bm + wm + mt * 16 + gid;
            int col = bn + wn + nt * 8 + tig * 2;
            float2 v0 = make_float2(acc[mt][nt][0], acc[mt][nt][1]);
            float2 v1 = make_float2(acc[mt][nt][2], acc[mt][nt][3]);
            if (EPI != EPI_NONE) {
                float bx = bias[col], by = bias[col + 1];
                v0.x += bx; v0.y += by; v1.x += bx; v1.y += by;
            }
            if (EPI == EPI_BIAS_RES) {
                float2 r0 = *(const float2*)(res + (size_t)row * N + col);
                float2 r1 = *(const float2*)(res + (size_t)(row + 8) * N + col);
                v0.x += r0.x; v0.y += r0.y; v1.x += r1.x; v1.y += r1.y;
                *(float2*)(C + (size_t)row * N + col)       = v0;
                *(float2*)(C + (size_t)(row + 8) * N + col) = v1;
            } else if (EPI == EPI_SILU_H) {
                v0.x *= 1.f / (1.f + __expf(-v0.x));
                v0.y *= 1.f / (1.f + __expf(-v0.y));
                v1.x *= 1.f / (1.f + __expf(-v1.x));
                v1.y *= 1.f / (1.f + __expf(-v1.y));
                *(uint32_t*)(Oh + (size_t)row * N + col)       = cvt2h(v0.x, v0.y);
                *(uint32_t*)(Oh + (size_t)(row + 8) * N + col) = cvt2h(v1.x, v1.y);
            } else {
                *(float2*)(C + (size_t)row * N + col)       = v0;
                *(float2*)(C + (size_t)(row + 8) * N + col) = v1;
            }
        }
    }
}

// ---------------- Flash attention fp16 + ldmatrix -------------------------
// Q split (2 planes), K/V/P single. 256 thr, Q tile 128, K/V tile 64.
#define AST 36     // words per row (32 data + 4 pad) = 144B
#define W_QH 0
#define W_QL (W_QH + 128 * AST)
#define W_K  (W_QL + 128 * AST)
#define W_V  (W_K  + 64 * AST)
#define W_P  (W_V  + 64 * AST)
#define ATTN_WORDS (W_P + 128 * AST)
#define ATTN_SM_BYTES (ATTN_WORDS * 4)   // 73728

__global__ __launch_bounds__(256, 2) void attn_f16(
    const float* __restrict__ qkv, __half* __restrict__ o)
{
    extern __shared__ uint32_t smw[];
    uint32_t sbase = (uint32_t)__cvta_generic_to_shared(smw);
    uint32_t* Qh = smw + W_QH;
    uint32_t* Ql = smw + W_QL;
    uint32_t* Ks = smw + W_K;
    uint32_t* Vt = smw + W_V;
    uint32_t* Ps = smw + W_P;

    int tid  = threadIdx.x;
    int warp = tid >> 5, lane = tid & 31;
    int gid  = lane >> 2, tig = lane & 3;
    int qrow0 = warp * 16;

    int qb = blockIdx.x;
    int b  = blockIdx.y >> 4;
    int h  = blockIdx.y & 15;

    // ldmatrix byte offsets (A-style for Q/P, B-style for K/V)
    uint32_t aoff = (uint32_t)((((lane & 15)) * AST + (lane >> 4) * 4) * 4);
    uint32_t boff = (uint32_t)(((((lane >> 4) & 1) * 8 + (lane & 7)) * AST
                                + ((lane >> 3) & 1) * 4) * 4);

    // ---- fill Q (scaled 1/8, split) ----
    const float* qbase = qkv + (size_t)(b * SEQ + qb * 128) * (3 * DIM) + h * HD;
    for (int e = tid; e < 128 * 16; e += 256) {
        int r = e >> 4, c4 = (e & 15) * 4;
        float4 v = *(const float4*)(qbase + (size_t)r * (3 * DIM) + c4);
        uint32_t h0, l0, h1, l1;
        split_h(v.x * 0.125f, v.y * 0.125f, h0, l0);
        split_h(v.z * 0.125f, v.w * 0.125f, h1, l1);
        int w = r * AST + (c4 >> 1);
        *(uint2*)(Qh + w) = make_uint2(h0, h1);
        *(uint2*)(Ql + w) = make_uint2(l0, l1);
    }

    float m0 = -1e30f, m1 = -1e30f, l0r = 0.f, l1r = 0.f;
    float oacc[8][4];
    #pragma unroll
    for (int nt = 0; nt < 8; nt++)
        #pragma unroll
        for (int r = 0; r < 4; r++) oacc[nt][r] = 0.f;

    for (int jb = 0; jb < SEQ / 64; ++jb) {
        __syncthreads();
        const float* kb = qkv + (size_t)(b * SEQ + jb * 64) * (3 * DIM) + h * HD + DIM;
        const float* vb = kb + DIM;
        for (int e = tid; e < 64 * 16; e += 256) {
            int r = e >> 4, c4 = (e & 15) * 4;
            float4 kv = *(const float4*)(kb + (size_t)r * (3 * DIM) + c4);
            int w = r * AST + (c4 >> 1);
            *(uint2*)(Ks + w) = make_uint2(cvt2h(kv.x, kv.y), cvt2h(kv.z, kv.w));
        }
        for (int e = tid; e < 32 * 16; e += 256) {
            int r2 = e >> 4, c4 = (e & 15) * 4;
            float4 va = *(const float4*)(vb + (size_t)(2 * r2)     * (3 * DIM) + c4);
            float4 vc = *(const float4*)(vb + (size_t)(2 * r2 + 1) * (3 * DIM) + c4);
            Vt[(c4 + 0) * AST + r2] = cvt2h(va.x, vc.x);
            Vt[(c4 + 1) * AST + r2] = cvt2h(va.y, vc.y);
            Vt[(c4 + 2) * AST + r2] = cvt2h(va.z, vc.z);
            Vt[(c4 + 3) * AST + r2] = cvt2h(va.w, vc.w);
        }
        __syncthreads();

        // ---- S = Q K^T ----
        float s[8][4];
        #pragma unroll
        for (int nt = 0; nt < 8; nt++)
            #pragma unroll
            for (int r = 0; r < 4; r++) s[nt][r] = 0.f;

        #pragma unroll
        for (int kc = 0; kc < 4; ++kc) {
            uint32_t kcb = kc * 32;   // kc*8 words * 4B
            uint32_t qa0, qa1, qa2, qa3, ql0, ql1, ql2, ql3;
            LDSM4(qa0, qa1, qa2, qa3,
                  sbase + (W_QH + qrow0 * AST) * 4 + aoff + kcb);
            LDSM4(ql0, ql1, ql2, ql3,
                  sbase + (W_QL + qrow0 * AST) * 4 + aoff + kcb);
            #pragma unroll
            for (int p = 0; p < 4; ++p) {
                uint32_t r0, r1, r2, r3;
                LDSM4(r0, r1, r2, r3,
                      sbase + (W_K + p * 16 * AST) * 4 + boff + kcb);
                mma_f16(s[2*p],   qa0, qa1, qa2, qa3, r0, r1);
                mma_f16(s[2*p],   ql0, ql1, ql2, ql3, r0, r1);
                mma_f16(s[2*p+1], qa0, qa1, qa2, qa3, r2, r3);
                mma_f16(s[2*p+1], ql0, ql1, ql2, ql3, r2, r3);
            }
        }

        // ---- online softmax ----
        float mc0 = s[0][0], mc1 = s[0][2];
        #pragma unroll
        for (int nt = 0; nt < 8; ++nt) {
            mc0 = fmaxf(mc0, fmaxf(s[nt][0], s[nt][1]));
            mc1 = fmaxf(mc1, fmaxf(s[nt][2], s[nt][3]));
        }
        mc0 = fmaxf(mc0, __shfl_xor_sync(0xffffffffu, mc0, 1));
        mc0 = fmaxf(mc0, __shfl_xor_sync(0xffffffffu, mc0, 2));
        mc1 = fmaxf(mc1, __shfl_xor_sync(0xffffffffu, mc1, 1));
        mc1 = fmaxf(mc1, __shfl_xor_sync(0xffffffffu, mc1, 2));
        float mn0 = fmaxf(m0, mc0), mn1 = fmaxf(m1, mc1);
        float f0 = __expf(m0 - mn0), f1 = __expf(m1 - mn1);
        m0 = mn0; m1 = mn1;

        float ps0 = 0.f, ps1 = 0.f;
        #pragma unroll
        for (int nt = 0; nt < 8; ++nt) {
            float p0 = __expf(s[nt][0] - m0);
            float p1 = __expf(s[nt][1] - m0);
            float p2 = __expf(s[nt][2] - m1);
            float p3 = __expf(s[nt][3] - m1);
            ps0 += p0 + p1; ps1 += p2 + p3;
            Ps[(qrow0 + gid) * AST + nt * 4 + tig]     = cvt2h(p0, p1);
            Ps[(qrow0 + 8 + gid) * AST + nt * 4 + tig] = cvt2h(p2, p3);
        }
        ps0 += __shfl_xor_sync(0xffffffffu, ps0, 1);
        ps0 += __shfl_xor_sync(0xffffffffu, ps0, 2);
        ps1 += __shfl_xor_sync(0xffffffffu, ps1, 1);
        ps1 += __shfl_xor_sync(0xffffffffu, ps1, 2);
        l0r = l0r * f0 + ps0;
        l1r = l1r * f1 + ps1;
        #pragma unroll
        for (int nt = 0; nt < 8; ++nt) {
            oacc[nt][0] *= f0; oacc[nt][1] *= f0;
            oacc[nt][2] *= f1; oacc[nt][3] *= f1;
        }
        __syncwarp();   // P rows are warp-private

        // ---- O += P V ----
        #pragma unroll
        for (int kc = 0; kc < 4; ++kc) {
            uint32_t kcb = kc * 32;
            uint32_t pa0, pa1, pa2, pa3;
            LDSM4(pa0, pa1, pa2, pa3,
                  sbase + (W_P + qrow0 * AST) * 4 + aoff + kcb);
            #pragma unroll
            for (int p = 0; p < 4; ++p) {
                uint32_t r0, r1, r2, r3;
                LDSM4(r0, r1, r2, r3,
                      sbase + (W_V + p * 16 * AST) * 4 + boff + kcb);
                mma_f16(oacc[2*p],   pa0, pa1, pa2, pa3, r0, r1);
                mma_f16(oacc[2*p+1], pa0, pa1, pa2, pa3, r2, r3);
            }
        }
    }

    float inv0 = 1.0f / l0r, inv1 = 1.0f / l1r;
    int grow0 = b * SEQ + qb * 128 + qrow0 + gid;
    #pragma unroll
    for (int nt = 0; nt < 8; ++nt) {
        int col = h * HD + nt * 8 + tig * 2;
        *(uint32_t*)(o + (size_t)grow0 * DIM + col) =
            cvt2h(oacc[nt][0] * inv0, oacc[nt][1] * inv0);
        *(uint32_t*)(o + (size_t)(grow0 + 8) * DIM + col) =
            cvt2h(oacc[nt][2] * inv1, oacc[nt][3] * inv1);
    }
}

// ---------------- launch ----------------
extern "C" void kernel_launch(void* const* d_in, const int* in_sizes, int n_in,
                              void* d_out, int out_size)
{
    const float* x     = (const float*)d_in[0];
    const float* qkv_w = (const float*)d_in[1];
    const float* out_w = (const float*)d_in[2];
    const float* out_b = (const float*)d_in[3];
    const float* ff_w1 = (const float*)d_in[4];
    const float* ff_b1 = (const float*)d_in[5];
    const float* ff_w2 = (const float*)d_in[6];
    const float* ff_b2 = (const float*)d_in[7];
    const float* ln1_w = (const float*)d_in[8];
    const float* ln1_b = (const float*)d_in[9];
    const float* ln2_w = (const float*)d_in[10];
    const float* ln2_b = (const float*)d_in[11];
    float* out = (float*)d_out;

    float *qkv, *x1;
    __half *xln, *attn, *xln2, *hbuf;
    __half *wqh, *wql, *woh, *wol, *w1h, *w1l, *w2h, *w2l;
    cudaGetSymbolAddress((void**)&qkv,  g_qkv);
    cudaGetSymbolAddress((void**)&x1,   g_x1);
    cudaGetSymbolAddress((void**)&xln,  g_xln);
    cudaGetSymbolAddress((void**)&attn, g_attn);
    cudaGetSymbolAddress((void**)&xln2, g_xln2);
    cudaGetSymbolAddress((void**)&hbuf, g_h);
    cudaGetSymbolAddress((void**)&wqh,  g_wqkv_h);
    cudaGetSymbolAddress((void**)&wql,  g_wqkv_l);
    cudaGetSymbolAddress((void**)&woh,  g_wout_h);
    cudaGetSymbolAddress((void**)&wol,  g_wout_l);
    cudaGetSymbolAddress((void**)&w1h,  g_w1_h);
    cudaGetSymbolAddress((void**)&w1l,  g_w1_l);
    cudaGetSymbolAddress((void**)&w2h,  g_w2_h);
    cudaGetSymbolAddress((void**)&w2l,  g_w2_l);

    cudaFuncSetAttribute(gemm_f16<EPI_NONE>,
        cudaFuncAttributeMaxDynamicSharedMemorySize, GEMM_SMEM);
    cudaFuncSetAttribute(gemm_f16<EPI_BIAS_RES>,
        cudaFuncAttributeMaxDynamicSharedMemorySize, GEMM_SMEM);
    cudaFuncSetAttribute(gemm_f16<EPI_SILU_H>,
        cudaFuncAttributeMaxDynamicSharedMemorySize, GEMM_SMEM);
    cudaFuncSetAttribute(attn_f16,
        cudaFuncAttributeMaxDynamicSharedMemorySize, ATTN_SM_BYTES);

    // 0. split weights
    split_w<<<(3 * DIM * DIM / 4 + 255) / 256, 256>>>(qkv_w, wqh, wql, 3 * DIM * DIM / 4);
    split_w<<<(DIM * DIM / 4 + 255) / 256, 256>>>(out_w, woh, wol, DIM * DIM / 4);
    split_w<<<(MLPD * DIM / 4 + 255) / 256, 256>>>(ff_w1, w1h, w1l, MLPD * DIM / 4);
    split_w<<<(DIM * MLPD / 4 + 255) / 256, 256>>>(ff_w2, w2h, w2l, DIM * MLPD / 4);

    // 1. LN1 -> fp16
    ln_kernel<<<TOK, 256>>>(x, ln1_w, ln1_b, xln);
    // 2. QKV -> fp32
    gemm_f16<EPI_NONE><<<dim3(3 * DIM / 128, TOK / 128), 256, GEMM_SMEM>>>(
        xln, wqh, wql, nullptr, nullptr, qkv, nullptr, TOK, 3 * DIM, DIM);
    // 3. attention -> fp16
    attn_f16<<<dim3(SEQ / 128, 2 * NHEAD), 256, ATTN_SM_BYTES>>>(qkv, attn);
    // 4. x1 = x + attn @ out_w^T + out_b -> fp32
    gemm_f16<EPI_BIAS_RES><<<dim3(DIM / 128, TOK / 128), 256, GEMM_SMEM>>>(
        attn, woh, wol, out_b, x, x1, nullptr, TOK, DIM, DIM);
    // 5. LN2 -> fp16
    ln_kernel<<<TOK, 256>>>(x1, ln2_w, ln2_b, xln2);
    // 6. h = silu(...) -> fp16
    gemm_f16<EPI_SILU_H><<<dim3(MLPD / 128, TOK / 128), 256, GEMM_SMEM>>>(
        xln2, w1h, w1l, ff_b1, nullptr, nullptr, hbuf, TOK, MLPD, DIM);
    // 7. out = x1 + h @ ff_w2^T + ff_b2 -> fp32
    gemm_f16<EPI_BIAS_RES><<<dim3(DIM / 128, TOK / 128), 256, GEMM_SMEM>>>(
        hbuf, w2h, w2l, ff_b2, x1, out, nullptr, TOK, DIM, MLPD);
}

// round 9
// speedup vs baseline: 4.6151x; 1.0523x over previous
#include <cuda_runtime.h>
#include <cuda_fp16.h>
#include <math.h>
#include <stdint.h>

#define TOK   4096
#define DIM   1024
#define MLPD  4096
#define NHEAD 16
#define HD    64
#define SEQ   2048

// ---------------- scratch ----------------
__device__ float g_x1  [TOK * DIM];
// fp16 activation planes
__device__ __half g_xln [TOK * DIM];
__device__ __half g_qh  [TOK * DIM];   // Q (scaled, hi)
__device__ __half g_ql  [TOK * DIM];   // Q (scaled, lo)
__device__ __half g_kh  [TOK * DIM];   // K
__device__ __half g_vh  [TOK * DIM];   // V
__device__ __half g_attn[TOK * DIM];
__device__ __half g_xln2[TOK * DIM];
__device__ __half g_h   [TOK * MLPD];
// split fp16 weight planes
__device__ __half g_wqkv_h[3 * DIM * DIM];
__device__ __half g_wqkv_l[3 * DIM * DIM];
__device__ __half g_wout_h[DIM * DIM];
__device__ __half g_wout_l[DIM * DIM];
__device__ __half g_w1_h  [MLPD * DIM];
__device__ __half g_w1_l  [MLPD * DIM];
__device__ __half g_w2_h  [DIM * MLPD];
__device__ __half g_w2_l  [DIM * MLPD];

// ---------------- helpers ----------------
__device__ __forceinline__ uint32_t cvt2h(float x, float y) {
    __half2 h = __floats2half2_rn(x, y);
    return *(uint32_t*)&h;
}
__device__ __forceinline__ void split_h(float x, float y, uint32_t& hi, uint32_t& lo) {
    __half2 h = __floats2half2_rn(x, y);
    float rx = x - __half2float(__low2half(h));
    float ry = y - __half2float(__high2half(h));
    __half2 l = __floats2half2_rn(rx, ry);
    hi = *(uint32_t*)&h;
    lo = *(uint32_t*)&l;
}

__device__ __forceinline__ void mma_f16(float* d,
    uint32_t a0, uint32_t a1, uint32_t a2, uint32_t a3,
    uint32_t b0, uint32_t b1)
{
    asm volatile(
        "mma.sync.aligned.m16n8k16.row.col.f32.f16.f16.f32 "
        "{%0,%1,%2,%3}, {%4,%5,%6,%7}, {%8,%9}, {%0,%1,%2,%3};"
        : "+f"(d[0]), "+f"(d[1]), "+f"(d[2]), "+f"(d[3])
        : "r"(a0), "r"(a1), "r"(a2), "r"(a3), "r"(b0), "r"(b1));
}

#define LDSM4(R0,R1,R2,R3,ADDR) \
    asm volatile("ldmatrix.sync.aligned.m8n8.x4.shared.b16 {%0,%1,%2,%3}, [%4];" \
        : "=r"(R0), "=r"(R1), "=r"(R2), "=r"(R3) : "r"(ADDR))

#define CP16(dst, src) \
    asm volatile("cp.async.ca.shared.global [%0], [%1], 16;" :: "r"(dst), "l"(src) : "memory")
#define CP_COMMIT() asm volatile("cp.async.commit_group;" ::: "memory")
#define CP_WAIT1()  asm volatile("cp.async.wait_group 1;" ::: "memory")

// ---------------- weight split kernel ----------------
__global__ __launch_bounds__(256) void split_w(
    const float* __restrict__ src, __half* __restrict__ hi, __half* __restrict__ lo, int n4)
{
    int i = blockIdx.x * 256 + threadIdx.x;
    if (i >= n4) return;
    float4 v = ((const float4*)src)[i];
    uint32_t h0, l0, h1, l1;
    split_h(v.x, v.y, h0, l0);
    split_h(v.z, v.w, h1, l1);
    ((uint2*)hi)[i] = make_uint2(h0, h1);
    ((uint2*)lo)[i] = make_uint2(l0, l1);
}

// ---------------- LayerNorm -> fp16 ----------------
__global__ __launch_bounds__(256) void ln_kernel(
    const float* __restrict__ x, const float* __restrict__ w,
    const float* __restrict__ b, __half* __restrict__ o)
{
    int row = blockIdx.x;
    int tid = threadIdx.x;
    const float4* xr = (const float4*)(x + (size_t)row * DIM);
    float4 v = xr[tid];

    __shared__ float red[9];
    float s = v.x + v.y + v.z + v.w;
    #pragma unroll
    for (int of = 16; of > 0; of >>= 1) s += __shfl_xor_sync(0xffffffffu, s, of);
    if ((tid & 31) == 0) red[tid >> 5] = s;
    __syncthreads();
    if (tid == 0) {
        float t = 0.f;
        #pragma unroll
        for (int i = 0; i < 8; i++) t += red[i];
        red[8] = t * (1.0f / DIM);
    }
    __syncthreads();
    float mean = red[8];
    float dx = v.x - mean, dy = v.y - mean, dz = v.z - mean, dw = v.w - mean;
    float sq = dx*dx + dy*dy + dz*dz + dw*dw;
    #pragma unroll
    for (int of = 16; of > 0; of >>= 1) sq += __shfl_xor_sync(0xffffffffu, sq, of);
    if ((tid & 31) == 0) red[tid >> 5] = sq;
    __syncthreads();
    if (tid == 0) {
        float t = 0.f;
        #pragma unroll
        for (int i = 0; i < 8; i++) t += red[i];
        red[8] = rsqrtf(t * (1.0f / DIM) + 1e-5f);
    }
    __syncthreads();
    float rstd = red[8];

    float4 wv = ((const float4*)w)[tid];
    float4 bv = ((const float4*)b)[tid];
    float ox = dx * rstd * wv.x + bv.x;
    float oy = dy * rstd * wv.y + bv.y;
    float oz = dz * rstd * wv.z + bv.z;
    float ow = dw * rstd * wv.w + bv.w;
    ((uint2*)o)[(size_t)row * (DIM / 4) + tid] =
        make_uint2(cvt2h(ox, oy), cvt2h(oz, ow));
}

// ---------------- NT GEMM fp16, KT=32, 3-stage cp.async, ldmatrix ----------
#define EPI_NONE      0
#define EPI_BIAS_RES  1
#define EPI_SILU_H    2
#define EPI_QKV       3

#define WST2 20                       // words per smem row (16 data + 4 pad) = 80B
#define PLW2 (128 * WST2)             // 2560 words per plane
#define STGW2 (3 * PLW2)              // A, Wh, Wl
#define NSTAGE 3
#define GEMM_SMEM (NSTAGE * STGW2 * 4)   // 92160

template <int EPI>
__global__ __launch_bounds__(256, 2) void gemm_f16(
    const __half* __restrict__ A,
    const __half* __restrict__ Wh, const __half* __restrict__ Wl,
    const float* __restrict__ bias, const float* __restrict__ res,
    float* __restrict__ C,
    __half* __restrict__ H0, __half* __restrict__ H1,
    __half* __restrict__ H2, __half* __restrict__ H3,
    int M, int N, int K)
{
    extern __shared__ __align__(16) uint32_t smw[];
    uint32_t sbase = (uint32_t)__cvta_generic_to_shared(smw);

    int tid  = threadIdx.x;
    int warp = tid >> 5, lane = tid & 31;
    int bm   = blockIdx.y * 128;
    int bn   = blockIdx.x * 128;
    int wm   = (warp & 1) * 64;
    int wn   = (warp >> 1) * 32;
    int gid  = lane >> 2, tig = lane & 3;

    // cp.async: thread t -> row t>>1, 32B half (t&1)
    int lrow  = tid >> 1;
    int lh    = tid & 1;
    const __half* pA  = A  + (size_t)(bm + lrow) * K + lh * 16;
    const __half* pWh = Wh + (size_t)(bn + lrow) * K + lh * 16;
    const __half* pWl = Wl + (size_t)(bn + lrow) * K + lh * 16;
    uint32_t dstb = (uint32_t)(lrow * WST2 + lh * 8) * 4;

    uint32_t a_off = (uint32_t)(((wm + (lane & 15)) * WST2 + (lane >> 4) * 4) * 4);
    uint32_t b_off = (uint32_t)(((wn + ((lane >> 4) & 1) * 8 + (lane & 7)) * WST2
                                 + ((lane >> 3) & 1) * 4) * 4);

    float acc[4][4][4];
    #pragma unroll
    for (int i = 0; i < 4; i++)
        #pragma unroll
        for (int j = 0; j < 4; j++)
            #pragma unroll
            for (int r = 0; r < 4; r++) acc[i][j][r] = 0.f;

    int ntiles = K >> 5;

    auto issue = [&](int t) {
        uint32_t base = sbase + ((t % NSTAGE) * STGW2) * 4 + dstb;
        const __half* a  = pA  + (size_t)t * 32;
        const __half* wh = pWh + (size_t)t * 32;
        const __half* wl = pWl + (size_t)t * 32;
        CP16(base,                a);
        CP16(base + 16,           a + 8);
        CP16(base + PLW2*4,       wh);
        CP16(base + PLW2*4 + 16,  wh + 8);
        CP16(base + 2*PLW2*4,     wl);
        CP16(base + 2*PLW2*4 + 16, wl + 8);
    };

    issue(0); CP_COMMIT();
    issue(1); CP_COMMIT();

    for (int t = 0; t < ntiles; ++t) {
        CP_WAIT1();
        __syncthreads();
        uint32_t stb = sbase + ((t % NSTAGE) * STGW2) * 4;

        #pragma unroll
        for (int kc = 0; kc < 2; ++kc) {
            uint32_t kcb = kc * 32;
            uint32_t bh[4][2], bl[4][2];
            #pragma unroll
            for (int p = 0; p < 2; ++p) {
                uint32_t r0, r1, r2, r3;
                LDSM4(r0, r1, r2, r3, stb + PLW2*4 + b_off + p * 16 * WST2 * 4 + kcb);
                bh[2*p][0] = r0; bh[2*p][1] = r1; bh[2*p+1][0] = r2; bh[2*p+1][1] = r3;
                LDSM4(r0, r1, r2, r3, stb + 2*PLW2*4 + b_off + p * 16 * WST2 * 4 + kcb);
                bl[2*p][0] = r0; bl[2*p][1] = r1; bl[2*p+1][0] = r2; bl[2*p+1][1] = r3;
            }
            #pragma unroll
            for (int mt = 0; mt < 4; ++mt) {
                uint32_t a0, a1, a2, a3;
                LDSM4(a0, a1, a2, a3, stb + a_off + mt * 16 * WST2 * 4 + kcb);
                #pragma unroll
                for (int nt = 0; nt < 4; ++nt) {
                    mma_f16(acc[mt][nt], a0, a1, a2, a3, bh[nt][0], bh[nt][1]);
                    mma_f16(acc[mt][nt], a0, a1, a2, a3, bl[nt][0], bl[nt][1]);
                }
            }
        }
        if (t + 2 < ntiles) issue(t + 2);
        CP_COMMIT();
    }

    // ---- epilogue ----
    #pragma unroll
    for (int mt = 0; mt < 4; ++mt) {
        #pragma unroll
        for (int nt = 0; nt < 4; ++nt) {
            int row = bm + wm + mt * 16 + gid;
            int col = bn + wn + nt * 8 + tig * 2;
            float2 v0 = make_float2(acc[mt][nt][0], acc[mt][nt][1]);
            float2 v1 = make_float2(acc[mt][nt][2], acc[mt][nt][3]);
            if (EPI == EPI_BIAS_RES || EPI == EPI_SILU_H) {
                float bx = bias[col], by = bias[col + 1];
                v0.x += bx; v0.y += by; v1.x += bx; v1.y += by;
            }
            if (EPI == EPI_BIAS_RES) {
                float2 r0 = *(const float2*)(res + (size_t)row * N + col);
                float2 r1 = *(const float2*)(res + (size_t)(row + 8) * N + col);
                v0.x += r0.x; v0.y += r0.y; v1.x += r1.x; v1.y += r1.y;
                *(float2*)(C + (size_t)row * N + col)       = v0;
                *(float2*)(C + (size_t)(row + 8) * N + col) = v1;
            } else if (EPI == EPI_SILU_H) {
                v0.x *= 1.f / (1.f + __expf(-v0.x));
                v0.y *= 1.f / (1.f + __expf(-v0.y));
                v1.x *= 1.f / (1.f + __expf(-v1.x));
                v1.y *= 1.f / (1.f + __expf(-v1.y));
                *(uint32_t*)(H0 + (size_t)row * N + col)       = cvt2h(v0.x, v0.y);
                *(uint32_t*)(H0 + (size_t)(row + 8) * N + col) = cvt2h(v1.x, v1.y);
            } else if (EPI == EPI_QKV) {
                int region = col >> 10;         // uniform per CTA
                int colr   = col & 1023;
                if (region == 0) {              // Q: scale + split
                    uint32_t hw, lw;
                    split_h(v0.x * 0.125f, v0.y * 0.125f, hw, lw);
                    *(uint32_t*)(H0 + (size_t)row * DIM + colr) = hw;
                    *(uint32_t*)(H1 + (size_t)row * DIM + colr) = lw;
                    split_h(v1.x * 0.125f, v1.y * 0.125f, hw, lw);
                    *(uint32_t*)(H0 + (size_t)(row + 8) * DIM + colr) = hw;
                    *(uint32_t*)(H1 + (size_t)(row + 8) * DIM + colr) = lw;
                } else if (region == 1) {       // K
                    *(uint32_t*)(H2 + (size_t)row * DIM + colr)       = cvt2h(v0.x, v0.y);
                    *(uint32_t*)(H2 + (size_t)(row + 8) * DIM + colr) = cvt2h(v1.x, v1.y);
                } else {                        // V
                    *(uint32_t*)(H3 + (size_t)row * DIM + colr)       = cvt2h(v0.x, v0.y);
                    *(uint32_t*)(H3 + (size_t)(row + 8) * DIM + colr) = cvt2h(v1.x, v1.y);
                }
            } else {
                *(float2*)(C + (size_t)row * N + col)       = v0;
                *(float2*)(C + (size_t)(row + 8) * N + col) = v1;
            }
        }
    }
}

// ---------------- Flash attention fp16, fp16 inputs -----------------------
#define AST 36     // words per row (32 data + 4 pad) = 144B
#define W_QH 0
#define W_QL (W_QH + 128 * AST)
#define W_K  (W_QL + 128 * AST)
#define W_V  (W_K  + 64 * AST)
#define W_P  (W_V  + 64 * AST)
#define ATTN_WORDS (W_P + 128 * AST)
#define ATTN_SM_BYTES (ATTN_WORDS * 4)   // 73728

__global__ __launch_bounds__(256, 2) void attn_f16(
    const __half* __restrict__ Qg, const __half* __restrict__ Qlg,
    const __half* __restrict__ Kg, const __half* __restrict__ Vg,
    __half* __restrict__ o)
{
    extern __shared__ uint32_t smw[];
    uint32_t sbase = (uint32_t)__cvta_generic_to_shared(smw);
    uint32_t* Qh = smw + W_QH;
    uint32_t* Ql = smw + W_QL;
    uint32_t* Ks = smw + W_K;
    uint32_t* Vt = smw + W_V;
    uint32_t* Ps = smw + W_P;

    int tid  = threadIdx.x;
    int warp = tid >> 5, lane = tid & 31;
    int gid  = lane >> 2, tig = lane & 3;
    int qrow0 = warp * 16;

    int qb = blockIdx.x;
    int b  = blockIdx.y >> 4;
    int h  = blockIdx.y & 15;

    uint32_t aoff = (uint32_t)((((lane & 15)) * AST + (lane >> 4) * 4) * 4);
    uint32_t boff = (uint32_t)(((((lane >> 4) & 1) * 8 + (lane & 7)) * AST
                                + ((lane >> 3) & 1) * 4) * 4);

    // ---- fill Q planes (raw uint4 copies) ----
    {
        const __half* qh_g = Qg  + (size_t)(b * SEQ + qb * 128) * DIM + h * HD;
        const __half* ql_g = Qlg + (size_t)(b * SEQ + qb * 128) * DIM + h * HD;
        for (int e = tid; e < 128 * 8; e += 256) {
            int r = e >> 3, c = (e & 7) * 8;
            uint4 v = *(const uint4*)(qh_g + (size_t)r * DIM + c);
            *(uint4*)(Qh + r * AST + (c >> 1)) = v;
            uint4 w = *(const uint4*)(ql_g + (size_t)r * DIM + c);
            *(uint4*)(Ql + r * AST + (c >> 1)) = w;
        }
    }

    float m0 = -1e30f, m1 = -1e30f, l0r = 0.f, l1r = 0.f;
    float oacc[8][4];
    #pragma unroll
    for (int nt = 0; nt < 8; nt++)
        #pragma unroll
        for (int r = 0; r < 4; r++) oacc[nt][r] = 0.f;

    for (int jb = 0; jb < SEQ / 64; ++jb) {
        __syncthreads();
        const __half* kg = Kg + (size_t)(b * SEQ + jb * 64) * DIM + h * HD;
        const __half* vg = Vg + (size_t)(b * SEQ + jb * 64) * DIM + h * HD;
        for (int e = tid; e < 64 * 8; e += 256) {
            int r = e >> 3, c = (e & 7) * 8;
            uint4 v = *(const uint4*)(kg + (size_t)r * DIM + c);
            *(uint4*)(Ks + r * AST + (c >> 1)) = v;
        }
        for (int e = tid; e < 32 * 16; e += 256) {
            int r2 = e >> 4, c4 = (e & 15) * 4;
            uint2 a = *(const uint2*)(vg + (size_t)(2 * r2)     * DIM + c4);
            uint2 c = *(const uint2*)(vg + (size_t)(2 * r2 + 1) * DIM + c4);
            Vt[(c4 + 0) * AST + r2] = __byte_perm(a.x, c.x, 0x5410);
            Vt[(c4 + 1) * AST + r2] = __byte_perm(a.x, c.x, 0x7632);
            Vt[(c4 + 2) * AST + r2] = __byte_perm(a.y, c.y, 0x5410);
            Vt[(c4 + 3) * AST + r2] = __byte_perm(a.y, c.y, 0x7632);
        }
        __syncthreads();

        // ---- S = Q K^T ----
        float s[8][4];
        #pragma unroll
        for (int nt = 0; nt < 8; nt++)
            #pragma unroll
            for (int r = 0; r < 4; r++) s[nt][r] = 0.f;

        #pragma unroll
        for (int kc = 0; kc < 4; ++kc) {
            uint32_t kcb = kc * 32;
            uint32_t qa0, qa1, qa2, qa3, ql0, ql1, ql2, ql3;
            LDSM4(qa0, qa1, qa2, qa3, sbase + (W_QH + qrow0 * AST) * 4 + aoff + kcb);
            LDSM4(ql0, ql1, ql2, ql3, sbase + (W_QL + qrow0 * AST) * 4 + aoff + kcb);
            #pragma unroll
            for (int p = 0; p < 4; ++p) {
                uint32_t r0, r1, r2, r3;
                LDSM4(r0, r1, r2, r3, sbase + (W_K + p * 16 * AST) * 4 + boff + kcb);
                mma_f16(s[2*p],   qa0, qa1, qa2, qa3, r0, r1);
                mma_f16(s[2*p],   ql0, ql1, ql2, ql3, r0, r1);
                mma_f16(s[2*p+1], qa0, qa1, qa2, qa3, r2, r3);
                mma_f16(s[2*p+1], ql0, ql1, ql2, ql3, r2, r3);
            }
        }

        // ---- online softmax ----
        float mc0 = s[0][0], mc1 = s[0][2];
        #pragma unroll
        for (int nt = 0; nt < 8; ++nt) {
            mc0 = fmaxf(mc0, fmaxf(s[nt][0], s[nt][1]));
            mc1 = fmaxf(mc1, fmaxf(s[nt][2], s[nt][3]));
        }
        mc0 = fmaxf(mc0, __shfl_xor_sync(0xffffffffu, mc0, 1));
        mc0 = fmaxf(mc0, __shfl_xor_sync(0xffffffffu, mc0, 2));
        mc1 = fmaxf(mc1, __shfl_xor_sync(0xffffffffu, mc1, 1));
        mc1 = fmaxf(mc1, __shfl_xor_sync(0xffffffffu, mc1, 2));
        float mn0 = fmaxf(m0, mc0), mn1 = fmaxf(m1, mc1);
        float f0 = __expf(m0 - mn0), f1 = __expf(m1 - mn1);
        m0 = mn0; m1 = mn1;

        float ps0 = 0.f, ps1 = 0.f;
        #pragma unroll
        for (int nt = 0; nt < 8; ++nt) {
            float p0 = __expf(s[nt][0] - m0);
            float p1 = __expf(s[nt][1] - m0);
            float p2 = __expf(s[nt][2] - m1);
            float p3 = __expf(s[nt][3] - m1);
            ps0 += p0 + p1; ps1 += p2 + p3;
            Ps[(qrow0 + gid) * AST + nt * 4 + tig]     = cvt2h(p0, p1);
            Ps[(qrow0 + 8 + gid) * AST + nt * 4 + tig] = cvt2h(p2, p3);
        }
        ps0 += __shfl_xor_sync(0xffffffffu, ps0, 1);
        ps0 += __shfl_xor_sync(0xffffffffu, ps0, 2);
        ps1 += __shfl_xor_sync(0xffffffffu, ps1, 1);
        ps1 += __shfl_xor_sync(0xffffffffu, ps1, 2);
        l0r = l0r * f0 + ps0;
        l1r = l1r * f1 + ps1;
        #pragma unroll
        for (int nt = 0; nt < 8; ++nt) {
            oacc[nt][0] *= f0; oacc[nt][1] *= f0;
            oacc[nt][2] *= f1; oacc[nt][3] *= f1;
        }
        __syncwarp();

        // ---- O += P V ----
        #pragma unroll
        for (int kc = 0; kc < 4; ++kc) {
            uint32_t kcb = kc * 32;
            uint32_t pa0, pa1, pa2, pa3;
            LDSM4(pa0, pa1, pa2, pa3, sbase + (W_P + qrow0 * AST) * 4 + aoff + kcb);
            #pragma unroll
            for (int p = 0; p < 4; ++p) {
                uint32_t r0, r1, r2, r3;
                LDSM4(r0, r1, r2, r3, sbase + (W_V + p * 16 * AST) * 4 + boff + kcb);
                mma_f16(oacc[2*p],   pa0, pa1, pa2, pa3, r0, r1);
                mma_f16(oacc[2*p+1], pa0, pa1, pa2, pa3, r2, r3);
            }
        }
    }

    float inv0 = 1.0f / l0r, inv1 = 1.0f / l1r;
    int grow0 = b * SEQ + qb * 128 + qrow0 + gid;
    #pragma unroll
    for (int nt = 0; nt < 8; ++nt) {
        int col = h * HD + nt * 8 + tig * 2;
        *(uint32_t*)(o + (size_t)grow0 * DIM + col) =
            cvt2h(oacc[nt][0] * inv0, oacc[nt][1] * inv0);
        *(uint32_t*)(o + (size_t)(grow0 + 8) * DIM + col) =
            cvt2h(oacc[nt][2] * inv1, oacc[nt][3] * inv1);
    }
}

// ---------------- launch ----------------
extern "C" void kernel_launch(void* const* d_in, const int* in_sizes, int n_in,
                              void* d_out, int out_size)
{
    const float* x     = (const float*)d_in[0];
    const float* qkv_w = (const float*)d_in[1];
    const float* out_w = (const float*)d_in[2];
    const float* out_b = (const float*)d_in[3];
    const float* ff_w1 = (const float*)d_in[4];
    const float* ff_b1 = (const float*)d_in[5];
    const float* ff_w2 = (const float*)d_in[6];
    const float* ff_b2 = (const float*)d_in[7];
    const float* ln1_w = (const float*)d_in[8];
    const float* ln1_b = (const float*)d_in[9];
    const float* ln2_w = (const float*)d_in[10];
    const float* ln2_b = (const float*)d_in[11];
    float* out = (float*)d_out;

    float *x1;
    __half *xln, *qh, *ql, *kh, *vh, *attn, *xln2, *hbuf;
    __half *wqh, *wql, *woh, *wol, *w1h, *w1l, *w2h, *w2l;
    cudaGetSymbolAddress((void**)&x1,   g_x1);
    cudaGetSymbolAddress((void**)&xln,  g_xln);
    cudaGetSymbolAddress((void**)&qh,   g_qh);
    cudaGetSymbolAddress((void**)&ql,   g_ql);
    cudaGetSymbolAddress((void**)&kh,   g_kh);
    cudaGetSymbolAddress((void**)&vh,   g_vh);
    cudaGetSymbolAddress((void**)&attn, g_attn);
    cudaGetSymbolAddress((void**)&xln2, g_xln2);
    cudaGetSymbolAddress((void**)&hbuf, g_h);
    cudaGetSymbolAddress((void**)&wqh,  g_wqkv_h);
    cudaGetSymbolAddress((void**)&wql,  g_wqkv_l);
    cudaGetSymbolAddress((void**)&woh,  g_wout_h);
    cudaGetSymbolAddress((void**)&wol,  g_wout_l);
    cudaGetSymbolAddress((void**)&w1h,  g_w1_h);
    cudaGetSymbolAddress((void**)&w1l,  g_w1_l);
    cudaGetSymbolAddress((void**)&w2h,  g_w2_h);
    cudaGetSymbolAddress((void**)&w2l,  g_w2_l);

    cudaFuncSetAttribute(gemm_f16<EPI_QKV>,
        cudaFuncAttributeMaxDynamicSharedMemorySize, GEMM_SMEM);
    cudaFuncSetAttribute(gemm_f16<EPI_BIAS_RES>,
        cudaFuncAttributeMaxDynamicSharedMemorySize, GEMM_SMEM);
    cudaFuncSetAttribute(gemm_f16<EPI_SILU_H>,
        cudaFuncAttributeMaxDynamicSharedMemorySize, GEMM_SMEM);
    cudaFuncSetAttribute(attn_f16,
        cudaFuncAttributeMaxDynamicSharedMemorySize, ATTN_SM_BYTES);

    // 0. split weights
    split_w<<<(3 * DIM * DIM / 4 + 255) / 256, 256>>>(qkv_w, wqh, wql, 3 * DIM * DIM / 4);
    split_w<<<(DIM * DIM / 4 + 255) / 256, 256>>>(out_w, woh, wol, DIM * DIM / 4);
    split_w<<<(MLPD * DIM / 4 + 255) / 256, 256>>>(ff_w1, w1h, w1l, MLPD * DIM / 4);
    split_w<<<(DIM * MLPD / 4 + 255) / 256, 256>>>(ff_w2, w2h, w2l, DIM * MLPD / 4);

    // 1. LN1 -> fp16
    ln_kernel<<<TOK, 256>>>(x, ln1_w, ln1_b, xln);
    // 2. QKV -> fp16 q(split)/k/v buffers
    gemm_f16<EPI_QKV><<<dim3(3 * DIM / 128, TOK / 128), 256, GEMM_SMEM>>>(
        xln, wqh, wql, nullptr, nullptr, nullptr, qh, ql, kh, vh, TOK, 3 * DIM, DIM);
    // 3. attention -> fp16
    attn_f16<<<dim3(SEQ / 128, 2 * NHEAD), 256, ATTN_SM_BYTES>>>(qh, ql, kh, vh, attn);
    // 4. x1 = x + attn @ out_w^T + out_b -> fp32
    gemm_f16<EPI_BIAS_RES><<<dim3(DIM / 128, TOK / 128), 256, GEMM_SMEM>>>(
        attn, woh, wol, out_b, x, x1, nullptr, nullptr, nullptr, nullptr, TOK, DIM, DIM);
    // 5. LN2 -> fp16
    ln_kernel<<<TOK, 256>>>(x1, ln2_w, ln2_b, xln2);
    // 6. h = silu(...) -> fp16
    gemm_f16<EPI_SILU_H><<<dim3(MLPD / 128, TOK / 128), 256, GEMM_SMEM>>>(
        xln2, w1h, w1l, ff_b1, nullptr, nullptr, hbuf, nullptr, nullptr, nullptr, TOK, MLPD, DIM);
    // 7. out = x1 + h @ ff_w2^T + ff_b2 -> fp32
    gemm_f16<EPI_BIAS_RES><<<dim3(DIM / 128, TOK / 128), 256, GEMM_SMEM>>>(
        hbuf, w2h, w2l, ff_b2, x1, out, nullptr, nullptr, nullptr, nullptr, TOK, DIM, MLPD);
}

// round 10
// speedup vs baseline: 5.9750x; 1.2947x over previous
#include <cuda_runtime.h>
#include <cuda_fp16.h>
#include <math.h>
#include <stdint.h>

#define TOK   4096
#define DIM   1024
#define MLPD  4096
#define NHEAD 16
#define HD    64
#define SEQ   2048

// ---------------- scratch ----------------
__device__ float g_x1  [TOK * DIM];
// fp16 activation planes
__device__ __half g_xln [TOK * DIM];
__device__ __half g_q   [TOK * DIM];   // Q (scaled)
__device__ __half g_k   [TOK * DIM];   // K
__device__ __half g_v   [TOK * DIM];   // V
__device__ __half g_attn[TOK * DIM];
__device__ __half g_xln2[TOK * DIM];
__device__ __half g_h   [TOK * MLPD];
// fp16 weights (single plane)
__device__ __half g_wqkv[3 * DIM * DIM];
__device__ __half g_wout[DIM * DIM];
__device__ __half g_w1  [MLPD * DIM];
__device__ __half g_w2  [DIM * MLPD];

// ---------------- helpers ----------------
__device__ __forceinline__ uint32_t cvt2h(float x, float y) {
    __half2 h = __floats2half2_rn(x, y);
    return *(uint32_t*)&h;
}

__device__ __forceinline__ void mma_f16(float* d,
    uint32_t a0, uint32_t a1, uint32_t a2, uint32_t a3,
    uint32_t b0, uint32_t b1)
{
    asm volatile(
        "mma.sync.aligned.m16n8k16.row.col.f32.f16.f16.f32 "
        "{%0,%1,%2,%3}, {%4,%5,%6,%7}, {%8,%9}, {%0,%1,%2,%3};"
        : "+f"(d[0]), "+f"(d[1]), "+f"(d[2]), "+f"(d[3])
        : "r"(a0), "r"(a1), "r"(a2), "r"(a3), "r"(b0), "r"(b1));
}

#define LDSM4(R0,R1,R2,R3,ADDR) \
    asm volatile("ldmatrix.sync.aligned.m8n8.x4.shared.b16 {%0,%1,%2,%3}, [%4];" \
        : "=r"(R0), "=r"(R1), "=r"(R2), "=r"(R3) : "r"(ADDR))

#define CP16(dst, src) \
    asm volatile("cp.async.ca.shared.global [%0], [%1], 16;" :: "r"(dst), "l"(src) : "memory")
#define CP_COMMIT() asm volatile("cp.async.commit_group;" ::: "memory")
#define CP_WAIT2()  asm volatile("cp.async.wait_group 2;" ::: "memory")

// ---------------- weight convert kernel (fp32 -> fp16) ----------------
__global__ __launch_bounds__(256) void conv_w(
    const float* __restrict__ src, __half* __restrict__ dst, int n4)
{
    int i = blockIdx.x * 256 + threadIdx.x;
    if (i >= n4) return;
    float4 v = ((const float4*)src)[i];
    ((uint2*)dst)[i] = make_uint2(cvt2h(v.x, v.y), cvt2h(v.z, v.w));
}

// ---------------- LayerNorm -> fp16 ----------------
__global__ __launch_bounds__(256) void ln_kernel(
    const float* __restrict__ x, const float* __restrict__ w,
    const float* __restrict__ b, __half* __restrict__ o)
{
    int row = blockIdx.x;
    int tid = threadIdx.x;
    const float4* xr = (const float4*)(x + (size_t)row * DIM);
    float4 v = xr[tid];

    __shared__ float red[9];
    float s = v.x + v.y + v.z + v.w;
    #pragma unroll
    for (int of = 16; of > 0; of >>= 1) s += __shfl_xor_sync(0xffffffffu, s, of);
    if ((tid & 31) == 0) red[tid >> 5] = s;
    __syncthreads();
    if (tid == 0) {
        float t = 0.f;
        #pragma unroll
        for (int i = 0; i < 8; i++) t += red[i];
        red[8] = t * (1.0f / DIM);
    }
    __syncthreads();
    float mean = red[8];
    float dx = v.x - mean, dy = v.y - mean, dz = v.z - mean, dw = v.w - mean;
    float sq = dx*dx + dy*dy + dz*dz + dw*dw;
    #pragma unroll
    for (int of = 16; of > 0; of >>= 1) sq += __shfl_xor_sync(0xffffffffu, sq, of);
    if ((tid & 31) == 0) red[tid >> 5] = sq;
    __syncthreads();
    if (tid == 0) {
        float t = 0.f;
        #pragma unroll
        for (int i = 0; i < 8; i++) t += red[i];
        red[8] = rsqrtf(t * (1.0f / DIM) + 1e-5f);
    }
    __syncthreads();
    float rstd = red[8];

    float4 wv = ((const float4*)w)[tid];
    float4 bv = ((const float4*)b)[tid];
    float ox = dx * rstd * wv.x + bv.x;
    float oy = dy * rstd * wv.y + bv.y;
    float oz = dz * rstd * wv.z + bv.z;
    float ow = dw * rstd * wv.w + bv.w;
    ((uint2*)o)[(size_t)row * (DIM / 4) + tid] =
        make_uint2(cvt2h(ox, oy), cvt2h(oz, ow));
}

// ---------------- NT GEMM fp16, KT=32, 4-stage cp.async, ldmatrix ----------
#define EPI_NONE      0
#define EPI_BIAS_RES  1
#define EPI_SILU_H    2
#define EPI_QKV       3

#define WST2 20                       // words per smem row (16 data + 4 pad) = 80B
#define PLW2 (128 * WST2)             // 2560 words per plane
#define STGW2 (2 * PLW2)              // A, W
#define NSTAGE 4
#define GEMM_SMEM (NSTAGE * STGW2 * 4)   // 81920

template <int EPI>
__global__ __launch_bounds__(256, 2) void gemm_f16(
    const __half* __restrict__ A, const __half* __restrict__ W,
    const float* __restrict__ bias, const float* __restrict__ res,
    float* __restrict__ C,
    __half* __restrict__ H0, __half* __restrict__ H1, __half* __restrict__ H2,
    int M, int N, int K)
{
    extern __shared__ __align__(16) uint32_t smw[];
    uint32_t sbase = (uint32_t)__cvta_generic_to_shared(smw);

    int tid  = threadIdx.x;
    int warp = tid >> 5, lane = tid & 31;
    int bm   = blockIdx.y * 128;
    int bn   = blockIdx.x * 128;
    int wm   = (warp & 1) * 64;
    int wn   = (warp >> 1) * 32;
    int gid  = lane >> 2, tig = lane & 3;

    int lrow  = tid >> 1;
    int lh    = tid & 1;
    const __half* pA = A + (size_t)(bm + lrow) * K + lh * 16;
    const __half* pW = W + (size_t)(bn + lrow) * K + lh * 16;
    uint32_t dstb = (uint32_t)(lrow * WST2 + lh * 8) * 4;

    uint32_t a_off = (uint32_t)(((wm + (lane & 15)) * WST2 + (lane >> 4) * 4) * 4);
    uint32_t b_off = (uint32_t)(((wn + ((lane >> 4) & 1) * 8 + (lane & 7)) * WST2
                                 + ((lane >> 3) & 1) * 4) * 4);

    float acc[4][4][4];
    #pragma unroll
    for (int i = 0; i < 4; i++)
        #pragma unroll
        for (int j = 0; j < 4; j++)
            #pragma unroll
            for (int r = 0; r < 4; r++) acc[i][j][r] = 0.f;

    int ntiles = K >> 5;

    auto issue = [&](int t) {
        uint32_t base = sbase + ((t % NSTAGE) * STGW2) * 4 + dstb;
        const __half* a = pA + (size_t)t * 32;
        const __half* w = pW + (size_t)t * 32;
        CP16(base,               a);
        CP16(base + 16,          a + 8);
        CP16(base + PLW2*4,      w);
        CP16(base + PLW2*4 + 16, w + 8);
    };

    issue(0); CP_COMMIT();
    issue(1); CP_COMMIT();
    issue(2); CP_COMMIT();

    for (int t = 0; t < ntiles; ++t) {
        CP_WAIT2();
        __syncthreads();
        uint32_t stb = sbase + ((t % NSTAGE) * STGW2) * 4;

        #pragma unroll
        for (int kc = 0; kc < 2; ++kc) {
            uint32_t kcb = kc * 32;
            uint32_t bw[4][2];
            #pragma unroll
            for (int p = 0; p < 2; ++p) {
                uint32_t r0, r1, r2, r3;
                LDSM4(r0, r1, r2, r3, stb + PLW2*4 + b_off + p * 16 * WST2 * 4 + kcb);
                bw[2*p][0] = r0; bw[2*p][1] = r1; bw[2*p+1][0] = r2; bw[2*p+1][1] = r3;
            }
            #pragma unroll
            for (int mt = 0; mt < 4; ++mt) {
                uint32_t a0, a1, a2, a3;
                LDSM4(a0, a1, a2, a3, stb + a_off + mt * 16 * WST2 * 4 + kcb);
                #pragma unroll
                for (int nt = 0; nt < 4; ++nt)
                    mma_f16(acc[mt][nt], a0, a1, a2, a3, bw[nt][0], bw[nt][1]);
            }
        }
        if (t + 3 < ntiles) issue(t + 3);
        CP_COMMIT();
    }

    // ---- epilogue ----
    #pragma unroll
    for (int mt = 0; mt < 4; ++mt) {
        #pragma unroll
        for (int nt = 0; nt < 4; ++nt) {
            int row = bm + wm + mt * 16 + gid;
            int col = bn + wn + nt * 8 + tig * 2;
            float2 v0 = make_float2(acc[mt][nt][0], acc[mt][nt][1]);
            float2 v1 = make_float2(acc[mt][nt][2], acc[mt][nt][3]);
            if (EPI == EPI_BIAS_RES || EPI == EPI_SILU_H) {
                float bx = bias[col], by = bias[col + 1];
                v0.x += bx; v0.y += by; v1.x += bx; v1.y += by;
            }
            if (EPI == EPI_BIAS_RES) {
                float2 r0 = *(const float2*)(res + (size_t)row * N + col);
                float2 r1 = *(const float2*)(res + (size_t)(row + 8) * N + col);
                v0.x += r0.x; v0.y += r0.y; v1.x += r1.x; v1.y += r1.y;
                *(float2*)(C + (size_t)row * N + col)       = v0;
                *(float2*)(C + (size_t)(row + 8) * N + col) = v1;
            } else if (EPI == EPI_SILU_H) {
                v0.x *= 1.f / (1.f + __expf(-v0.x));
                v0.y *= 1.f / (1.f + __expf(-v0.y));
                v1.x *= 1.f / (1.f + __expf(-v1.x));
                v1.y *= 1.f / (1.f + __expf(-v1.y));
                *(uint32_t*)(H0 + (size_t)row * N + col)       = cvt2h(v0.x, v0.y);
                *(uint32_t*)(H0 + (size_t)(row + 8) * N + col) = cvt2h(v1.x, v1.y);
            } else if (EPI == EPI_QKV) {
                int region = col >> 10;         // uniform per CTA
                int colr   = col & 1023;
                __half* dst = (region == 0) ? H0 : (region == 1) ? H1 : H2;
                float sc = (region == 0) ? 0.125f : 1.0f;
                *(uint32_t*)(dst + (size_t)row * DIM + colr) =
                    cvt2h(v0.x * sc, v0.y * sc);
                *(uint32_t*)(dst + (size_t)(row + 8) * DIM + colr) =
                    cvt2h(v1.x * sc, v1.y * sc);
            } else {
                *(float2*)(C + (size_t)row * N + col)       = v0;
                *(float2*)(C + (size_t)(row + 8) * N + col) = v1;
            }
        }
    }
}

// ---------------- Flash attention fp16 (single planes) --------------------
#define AST 36     // words per row (32 data + 4 pad) = 144B
#define W_Q 0
#define W_K (W_Q + 128 * AST)
#define W_V (W_K + 64 * AST)
#define W_P (W_V + 64 * AST)
#define ATTN_WORDS (W_P + 128 * AST)
#define ATTN_SM_BYTES (ATTN_WORDS * 4)   // 55296

__global__ __launch_bounds__(256, 2) void attn_f16(
    const __half* __restrict__ Qg, const __half* __restrict__ Kg,
    const __half* __restrict__ Vg, __half* __restrict__ o)
{
    extern __shared__ uint32_t smw[];
    uint32_t sbase = (uint32_t)__cvta_generic_to_shared(smw);
    uint32_t* Qs = smw + W_Q;
    uint32_t* Ks = smw + W_K;
    uint32_t* Vt = smw + W_V;
    uint32_t* Ps = smw + W_P;

    int tid  = threadIdx.x;
    int warp = tid >> 5, lane = tid & 31;
    int gid  = lane >> 2, tig = lane & 3;
    int qrow0 = warp * 16;

    int qb = blockIdx.x;
    int b  = blockIdx.y >> 4;
    int h  = blockIdx.y & 15;

    uint32_t aoff = (uint32_t)((((lane & 15)) * AST + (lane >> 4) * 4) * 4);
    uint32_t boff = (uint32_t)(((((lane >> 4) & 1) * 8 + (lane & 7)) * AST
                                + ((lane >> 3) & 1) * 4) * 4);

    // ---- fill Q ----
    {
        const __half* qg = Qg + (size_t)(b * SEQ + qb * 128) * DIM + h * HD;
        for (int e = tid; e < 128 * 8; e += 256) {
            int r = e >> 3, c = (e & 7) * 8;
            uint4 v = *(const uint4*)(qg + (size_t)r * DIM + c);
            *(uint4*)(Qs + r * AST + (c >> 1)) = v;
        }
    }

    float m0 = -1e30f, m1 = -1e30f, l0r = 0.f, l1r = 0.f;
    float oacc[8][4];
    #pragma unroll
    for (int nt = 0; nt < 8; nt++)
        #pragma unroll
        for (int r = 0; r < 4; r++) oacc[nt][r] = 0.f;

    for (int jb = 0; jb < SEQ / 64; ++jb) {
        __syncthreads();
        const __half* kg = Kg + (size_t)(b * SEQ + jb * 64) * DIM + h * HD;
        const __half* vg = Vg + (size_t)(b * SEQ + jb * 64) * DIM + h * HD;
        for (int e = tid; e < 64 * 8; e += 256) {
            int r = e >> 3, c = (e & 7) * 8;
            uint4 v = *(const uint4*)(kg + (size_t)r * DIM + c);
            *(uint4*)(Ks + r * AST + (c >> 1)) = v;
        }
        for (int e = tid; e < 32 * 16; e += 256) {
            int r2 = e >> 4, c4 = (e & 15) * 4;
            uint2 a = *(const uint2*)(vg + (size_t)(2 * r2)     * DIM + c4);
            uint2 c = *(const uint2*)(vg + (size_t)(2 * r2 + 1) * DIM + c4);
            Vt[(c4 + 0) * AST + r2] = __byte_perm(a.x, c.x, 0x5410);
            Vt[(c4 + 1) * AST + r2] = __byte_perm(a.x, c.x, 0x7632);
            Vt[(c4 + 2) * AST + r2] = __byte_perm(a.y, c.y, 0x5410);
            Vt[(c4 + 3) * AST + r2] = __byte_perm(a.y, c.y, 0x7632);
        }
        __syncthreads();

        // ---- S = Q K^T ----
        float s[8][4];
        #pragma unroll
        for (int nt = 0; nt < 8; nt++)
            #pragma unroll
            for (int r = 0; r < 4; r++) s[nt][r] = 0.f;

        #pragma unroll
        for (int kc = 0; kc < 4; ++kc) {
            uint32_t kcb = kc * 32;
            uint32_t qa0, qa1, qa2, qa3;
            LDSM4(qa0, qa1, qa2, qa3, sbase + (W_Q + qrow0 * AST) * 4 + aoff + kcb);
            #pragma unroll
            for (int p = 0; p < 4; ++p) {
                uint32_t r0, r1, r2, r3;
                LDSM4(r0, r1, r2, r3, sbase + (W_K + p * 16 * AST) * 4 + boff + kcb);
                mma_f16(s[2*p],   qa0, qa1, qa2, qa3, r0, r1);
                mma_f16(s[2*p+1], qa0, qa1, qa2, qa3, r2, r3);
            }
        }

        // ---- online softmax ----
        float mc0 = s[0][0], mc1 = s[0][2];
        #pragma unroll
        for (int nt = 0; nt < 8; ++nt) {
            mc0 = fmaxf(mc0, fmaxf(s[nt][0], s[nt][1]));
            mc1 = fmaxf(mc1, fmaxf(s[nt][2], s[nt][3]));
        }
        mc0 = fmaxf(mc0, __shfl_xor_sync(0xffffffffu, mc0, 1));
        mc0 = fmaxf(mc0, __shfl_xor_sync(0xffffffffu, mc0, 2));
        mc1 = fmaxf(mc1, __shfl_xor_sync(0xffffffffu, mc1, 1));
        mc1 = fmaxf(mc1, __shfl_xor_sync(0xffffffffu, mc1, 2));
        float mn0 = fmaxf(m0, mc0), mn1 = fmaxf(m1, mc1);
        float f0 = __expf(m0 - mn0), f1 = __expf(m1 - mn1);
        m0 = mn0; m1 = mn1;

        float ps0 = 0.f, ps1 = 0.f;
        #pragma unroll
        for (int nt = 0; nt < 8; ++nt) {
            float p0 = __expf(s[nt][0] - m0);
            float p1 = __expf(s[nt][1] - m0);
            float p2 = __expf(s[nt][2] - m1);
            float p3 = __expf(s[nt][3] - m1);
            ps0 += p0 + p1; ps1 += p2 + p3;
            Ps[(qrow0 + gid) * AST + nt * 4 + tig]     = cvt2h(p0, p1);
            Ps[(qrow0 + 8 + gid) * AST + nt * 4 + tig] = cvt2h(p2, p3);
        }
        ps0 += __shfl_xor_sync(0xffffffffu, ps0, 1);
        ps0 += __shfl_xor_sync(0xffffffffu, ps0, 2);
        ps1 += __shfl_xor_sync(0xffffffffu, ps1, 1);
        ps1 += __shfl_xor_sync(0xffffffffu, ps1, 2);
        l0r = l0r * f0 + ps0;
        l1r = l1r * f1 + ps1;
        #pragma unroll
        for (int nt = 0; nt < 8; ++nt) {
            oacc[nt][0] *= f0; oacc[nt][1] *= f0;
            oacc[nt][2] *= f1; oacc[nt][3] *= f1;
        }
        __syncwarp();

        // ---- O += P V ----
        #pragma unroll
        for (int kc = 0; kc < 4; ++kc) {
            uint32_t kcb = kc * 32;
            uint32_t pa0, pa1, pa2, pa3;
            LDSM4(pa0, pa1, pa2, pa3, sbase + (W_P + qrow0 * AST) * 4 + aoff + kcb);
            #pragma unroll
            for (int p = 0; p < 4; ++p) {
                uint32_t r0, r1, r2, r3;
                LDSM4(r0, r1, r2, r3, sbase + (W_V + p * 16 * AST) * 4 + boff + kcb);
                mma_f16(oacc[2*p],   pa0, pa1, pa2, pa3, r0, r1);
                mma_f16(oacc[2*p+1], pa0, pa1, pa2, pa3, r2, r3);
            }
        }
    }

    float inv0 = 1.0f / l0r, inv1 = 1.0f / l1r;
    int grow0 = b * SEQ + qb * 128 + qrow0 + gid;
    #pragma unroll
    for (int nt = 0; nt < 8; ++nt) {
        int col = h * HD + nt * 8 + tig * 2;
        *(uint32_t*)(o + (size_t)grow0 * DIM + col) =
            cvt2h(oacc[nt][0] * inv0, oacc[nt][1] * inv0);
        *(uint32_t*)(o + (size_t)(grow0 + 8) * DIM + col) =
            cvt2h(oacc[nt][2] * inv1, oacc[nt][3] * inv1);
    }
}

// ---------------- launch ----------------
extern "C" void kernel_launch(void* const* d_in, const int* in_sizes, int n_in,
                              void* d_out, int out_size)
{
    const float* x     = (const float*)d_in[0];
    const float* qkv_w = (const float*)d_in[1];
    const float* out_w = (const float*)d_in[2];
    const float* out_b = (const float*)d_in[3];
    const float* ff_w1 = (const float*)d_in[4];
    const float* ff_b1 = (const float*)d_in[5];
    const float* ff_w2 = (const float*)d_in[6];
    const float* ff_b2 = (const float*)d_in[7];
    const float* ln1_w = (const float*)d_in[8];
    const float* ln1_b = (const float*)d_in[9];
    const float* ln2_w = (const float*)d_in[10];
    const float* ln2_b = (const float*)d_in[11];
    float* out = (float*)d_out;

    float *x1;
    __half *xln, *q, *k, *v, *attn, *xln2, *hbuf;
    __half *wq, *wo, *w1, *w2;
    cudaGetSymbolAddress((void**)&x1,   g_x1);
    cudaGetSymbolAddress((void**)&xln,  g_xln);
    cudaGetSymbolAddress((void**)&q,    g_q);
    cudaGetSymbolAddress((void**)&k,    g_k);
    cudaGetSymbolAddress((void**)&v,    g_v);
    cudaGetSymbolAddress((void**)&attn, g_attn);
    cudaGetSymbolAddress((void**)&xln2, g_xln2);
    cudaGetSymbolAddress((void**)&hbuf, g_h);
    cudaGetSymbolAddress((void**)&wq,   g_wqkv);
    cudaGetSymbolAddress((void**)&wo,   g_wout);
    cudaGetSymbolAddress((void**)&w1,   g_w1);
    cudaGetSymbolAddress((void**)&w2,   g_w2);

    cudaFuncSetAttribute(gemm_f16<EPI_QKV>,
        cudaFuncAttributeMaxDynamicSharedMemorySize, GEMM_SMEM);
    cudaFuncSetAttribute(gemm_f16<EPI_BIAS_RES>,
        cudaFuncAttributeMaxDynamicSharedMemorySize, GEMM_SMEM);
    cudaFuncSetAttribute(gemm_f16<EPI_SILU_H>,
        cudaFuncAttributeMaxDynamicSharedMemorySize, GEMM_SMEM);
    cudaFuncSetAttribute(attn_f16,
        cudaFuncAttributeMaxDynamicSharedMemorySize, ATTN_SM_BYTES);

    // 0. convert weights to fp16
    conv_w<<<(3 * DIM * DIM / 4 + 255) / 256, 256>>>(qkv_w, wq, 3 * DIM * DIM / 4);
    conv_w<<<(DIM * DIM / 4 + 255) / 256, 256>>>(out_w, wo, DIM * DIM / 4);
    conv_w<<<(MLPD * DIM / 4 + 255) / 256, 256>>>(ff_w1, w1, MLPD * DIM / 4);
    conv_w<<<(DIM * MLPD / 4 + 255) / 256, 256>>>(ff_w2, w2, DIM * MLPD / 4);

    // 1. LN1 -> fp16
    ln_kernel<<<TOK, 256>>>(x, ln1_w, ln1_b, xln);
    // 2. QKV -> fp16 q(scaled)/k/v
    gemm_f16<EPI_QKV><<<dim3(3 * DIM / 128, TOK / 128), 256, GEMM_SMEM>>>(
        xln, wq, nullptr, nullptr, nullptr, q, k, v, TOK, 3 * DIM, DIM);
    // 3. attention -> fp16
    attn_f16<<<dim3(SEQ / 128, 2 * NHEAD), 256, ATTN_SM_BYTES>>>(q, k, v, attn);
    // 4. x1 = x + attn @ out_w^T + out_b -> fp32
    gemm_f16<EPI_BIAS_RES><<<dim3(DIM / 128, TOK / 128), 256, GEMM_SMEM>>>(
        attn, wo, out_b, x, x1, nullptr, nullptr, nullptr, TOK, DIM, DIM);
    // 5. LN2 -> fp16
    ln_kernel<<<TOK, 256>>>(x1, ln2_w, ln2_b, xln2);
    // 6. h = silu(...) -> fp16
    gemm_f16<EPI_SILU_H><<<dim3(MLPD / 128, TOK / 128), 256, GEMM_SMEM>>>(
        xln2, w1, ff_b1, nullptr, nullptr, hbuf, nullptr, nullptr, TOK, MLPD, DIM);
    // 7. out = x1 + h @ ff_w2^T + ff_b2 -> fp32
    gemm_f16<EPI_BIAS_RES><<<dim3(DIM / 128, TOK / 128), 256, GEMM_SMEM>>>(
        hbuf, w2, ff_b2, x1, out, nullptr, nullptr, nullptr, TOK, DIM, MLPD);
}

// round 11
// speedup vs baseline: 6.1423x; 1.0280x over previous
#include <cuda_runtime.h>
#include <cuda_fp16.h>
#include <math.h>
#include <stdint.h>

#define TOK   4096
#define DIM   1024
#define MLPD  4096
#define NHEAD 16
#define HD    64
#define SEQ   2048

// ---------------- scratch ----------------
__device__ float g_x1  [TOK * DIM];
// fp16 activation planes
__device__ __half g_xln [TOK * DIM];
__device__ __half g_q   [TOK * DIM];   // Q (scaled)
__device__ __half g_k   [TOK * DIM];   // K
__device__ __half g_v   [TOK * DIM];   // V
__device__ __half g_attn[TOK * DIM];
__device__ __half g_xln2[TOK * DIM];
__device__ __half g_h   [TOK * MLPD];
// fp16 weights (single plane)
__device__ __half g_wqkv[3 * DIM * DIM];
__device__ __half g_wout[DIM * DIM];
__device__ __half g_w1  [MLPD * DIM];
__device__ __half g_w2  [DIM * MLPD];

// ---------------- helpers ----------------
__device__ __forceinline__ uint32_t cvt2h(float x, float y) {
    __half2 h = __floats2half2_rn(x, y);
    return *(uint32_t*)&h;
}

__device__ __forceinline__ void mma_f16(float* d,
    uint32_t a0, uint32_t a1, uint32_t a2, uint32_t a3,
    uint32_t b0, uint32_t b1)
{
    asm volatile(
        "mma.sync.aligned.m16n8k16.row.col.f32.f16.f16.f32 "
        "{%0,%1,%2,%3}, {%4,%5,%6,%7}, {%8,%9}, {%0,%1,%2,%3};"
        : "+f"(d[0]), "+f"(d[1]), "+f"(d[2]), "+f"(d[3])
        : "r"(a0), "r"(a1), "r"(a2), "r"(a3), "r"(b0), "r"(b1));
}

#define LDSM4(R0,R1,R2,R3,ADDR) \
    asm volatile("ldmatrix.sync.aligned.m8n8.x4.shared.b16 {%0,%1,%2,%3}, [%4];" \
        : "=r"(R0), "=r"(R1), "=r"(R2), "=r"(R3) : "r"(ADDR))

#define CP16(dst, src) \
    asm volatile("cp.async.ca.shared.global [%0], [%1], 16;" :: "r"(dst), "l"(src) : "memory")
#define CP_COMMIT() asm volatile("cp.async.commit_group;" ::: "memory")
#define CP_WAIT2()  asm volatile("cp.async.wait_group 2;" ::: "memory")

// ---------------- weight convert kernel (fp32 -> fp16, 4x MLP) -------------
__global__ __launch_bounds__(256) void conv_w(
    const float* __restrict__ src, __half* __restrict__ dst, int n4)
{
    int i0 = blockIdx.x * 1024 + threadIdx.x;
    #pragma unroll
    for (int k = 0; k < 4; ++k) {
        int i = i0 + k * 256;
        if (i < n4) {
            float4 v = ((const float4*)src)[i];
            ((uint2*)dst)[i] = make_uint2(cvt2h(v.x, v.y), cvt2h(v.z, v.w));
        }
    }
}

// ---------------- LayerNorm -> fp16 ----------------
__global__ __launch_bounds__(256) void ln_kernel(
    const float* __restrict__ x, const float* __restrict__ w,
    const float* __restrict__ b, __half* __restrict__ o)
{
    int row = blockIdx.x;
    int tid = threadIdx.x;
    const float4* xr = (const float4*)(x + (size_t)row * DIM);
    float4 v = xr[tid];

    __shared__ float red[9];
    float s = v.x + v.y + v.z + v.w;
    #pragma unroll
    for (int of = 16; of > 0; of >>= 1) s += __shfl_xor_sync(0xffffffffu, s, of);
    if ((tid & 31) == 0) red[tid >> 5] = s;
    __syncthreads();
    if (tid == 0) {
        float t = 0.f;
        #pragma unroll
        for (int i = 0; i < 8; i++) t += red[i];
        red[8] = t * (1.0f / DIM);
    }
    __syncthreads();
    float mean = red[8];
    float dx = v.x - mean, dy = v.y - mean, dz = v.z - mean, dw = v.w - mean;
    float sq = dx*dx + dy*dy + dz*dz + dw*dw;
    #pragma unroll
    for (int of = 16; of > 0; of >>= 1) sq += __shfl_xor_sync(0xffffffffu, sq, of);
    if ((tid & 31) == 0) red[tid >> 5] = sq;
    __syncthreads();
    if (tid == 0) {
        float t = 0.f;
        #pragma unroll
        for (int i = 0; i < 8; i++) t += red[i];
        red[8] = rsqrtf(t * (1.0f / DIM) + 1e-5f);
    }
    __syncthreads();
    float rstd = red[8];

    float4 wv = ((const float4*)w)[tid];
    float4 bv = ((const float4*)b)[tid];
    float ox = dx * rstd * wv.x + bv.x;
    float oy = dy * rstd * wv.y + bv.y;
    float oz = dz * rstd * wv.z + bv.z;
    float ow = dw * rstd * wv.w + bv.w;
    ((uint2*)o)[(size_t)row * (DIM / 4) + tid] =
        make_uint2(cvt2h(ox, oy), cvt2h(oz, ow));
}

// ---------------- NT GEMM fp16, KT=32, 4-stage cp.async, ldmatrix ----------
#define EPI_NONE      0
#define EPI_BIAS_RES  1
#define EPI_SILU_H    2
#define EPI_QKV       3

#define WST2 20                       // words per smem row (16 data + 4 pad) = 80B
#define PLW2 (128 * WST2)             // 2560 words per plane
#define STGW2 (2 * PLW2)              // A, W
#define NSTAGE 4
#define GEMM_SMEM (NSTAGE * STGW2 * 4)   // 81920

template <int EPI>
__global__ __launch_bounds__(256, 2) void gemm_f16(
    const __half* __restrict__ A, const __half* __restrict__ W,
    const float* __restrict__ bias, const float* __restrict__ res,
    float* __restrict__ C,
    __half* __restrict__ H0, __half* __restrict__ H1, __half* __restrict__ H2,
    int M, int N, int K)
{
    extern __shared__ __align__(16) uint32_t smw[];
    uint32_t sbase = (uint32_t)__cvta_generic_to_shared(smw);

    int tid  = threadIdx.x;
    int warp = tid >> 5, lane = tid & 31;
    int bm   = blockIdx.y * 128;
    int bn   = blockIdx.x * 128;
    int wm   = (warp & 1) * 64;
    int wn   = (warp >> 1) * 32;
    int gid  = lane >> 2, tig = lane & 3;

    int lrow  = tid >> 1;
    int lh    = tid & 1;
    const __half* pA = A + (size_t)(bm + lrow) * K + lh * 16;
    const __half* pW = W + (size_t)(bn + lrow) * K + lh * 16;
    uint32_t dstb = (uint32_t)(lrow * WST2 + lh * 8) * 4;

    uint32_t a_off = (uint32_t)(((wm + (lane & 15)) * WST2 + (lane >> 4) * 4) * 4);
    uint32_t b_off = (uint32_t)(((wn + ((lane >> 4) & 1) * 8 + (lane & 7)) * WST2
                                 + ((lane >> 3) & 1) * 4) * 4);

    float acc[4][4][4];
    #pragma unroll
    for (int i = 0; i < 4; i++)
        #pragma unroll
        for (int j = 0; j < 4; j++)
            #pragma unroll
            for (int r = 0; r < 4; r++) acc[i][j][r] = 0.f;

    int ntiles = K >> 5;

    auto issue = [&](int t) {
        uint32_t base = sbase + ((t % NSTAGE) * STGW2) * 4 + dstb;
        const __half* a = pA + (size_t)t * 32;
        const __half* w = pW + (size_t)t * 32;
        CP16(base,               a);
        CP16(base + 16,          a + 8);
        CP16(base + PLW2*4,      w);
        CP16(base + PLW2*4 + 16, w + 8);
    };

    issue(0); CP_COMMIT();
    issue(1); CP_COMMIT();
    issue(2); CP_COMMIT();

    for (int t = 0; t < ntiles; ++t) {
        CP_WAIT2();
        __syncthreads();
        uint32_t stb = sbase + ((t % NSTAGE) * STGW2) * 4;

        #pragma unroll
        for (int kc = 0; kc < 2; ++kc) {
            uint32_t kcb = kc * 32;
            uint32_t bw[4][2];
            #pragma unroll
            for (int p = 0; p < 2; ++p) {
                uint32_t r0, r1, r2, r3;
                LDSM4(r0, r1, r2, r3, stb + PLW2*4 + b_off + p * 16 * WST2 * 4 + kcb);
                bw[2*p][0] = r0; bw[2*p][1] = r1; bw[2*p+1][0] = r2; bw[2*p+1][1] = r3;
            }
            #pragma unroll
            for (int mt = 0; mt < 4; ++mt) {
                uint32_t a0, a1, a2, a3;
                LDSM4(a0, a1, a2, a3, stb + a_off + mt * 16 * WST2 * 4 + kcb);
                #pragma unroll
                for (int nt = 0; nt < 4; ++nt)
                    mma_f16(acc[mt][nt], a0, a1, a2, a3, bw[nt][0], bw[nt][1]);
            }
        }
        if (t + 3 < ntiles) issue(t + 3);
        CP_COMMIT();
    }

    // ---- epilogue ----
    #pragma unroll
    for (int mt = 0; mt < 4; ++mt) {
        #pragma unroll
        for (int nt = 0; nt < 4; ++nt) {
            int row = bm + wm + mt * 16 + gid;
            int col = bn + wn + nt * 8 + tig * 2;
            float2 v0 = make_float2(acc[mt][nt][0], acc[mt][nt][1]);
            float2 v1 = make_float2(acc[mt][nt][2], acc[mt][nt][3]);
            if (EPI == EPI_BIAS_RES || EPI == EPI_SILU_H) {
                float bx = bias[col], by = bias[col + 1];
                v0.x += bx; v0.y += by; v1.x += bx; v1.y += by;
            }
            if (EPI == EPI_BIAS_RES) {
                float2 r0 = *(const float2*)(res + (size_t)row * N + col);
                float2 r1 = *(const float2*)(res + (size_t)(row + 8) * N + col);
                v0.x += r0.x; v0.y += r0.y; v1.x += r1.x; v1.y += r1.y;
                *(float2*)(C + (size_t)row * N + col)       = v0;
                *(float2*)(C + (size_t)(row + 8) * N + col) = v1;
            } else if (EPI == EPI_SILU_H) {
                v0.x *= 1.f / (1.f + __expf(-v0.x));
                v0.y *= 1.f / (1.f + __expf(-v0.y));
                v1.x *= 1.f / (1.f + __expf(-v1.x));
                v1.y *= 1.f / (1.f + __expf(-v1.y));
                *(uint32_t*)(H0 + (size_t)row * N + col)       = cvt2h(v0.x, v0.y);
                *(uint32_t*)(H0 + (size_t)(row + 8) * N + col) = cvt2h(v1.x, v1.y);
            } else if (EPI == EPI_QKV) {
                int region = col >> 10;         // uniform per CTA
                int colr   = col & 1023;
                __half* dst = (region == 0) ? H0 : (region == 1) ? H1 : H2;
                float sc = (region == 0) ? 0.125f : 1.0f;
                *(uint32_t*)(dst + (size_t)row * DIM + colr) =
                    cvt2h(v0.x * sc, v0.y * sc);
                *(uint32_t*)(dst + (size_t)(row + 8) * DIM + colr) =
                    cvt2h(v1.x * sc, v1.y * sc);
            } else {
                *(float2*)(C + (size_t)row * N + col)       = v0;
                *(float2*)(C + (size_t)(row + 8) * N + col) = v1;
            }
        }
    }
}

// ---------------- Flash attention fp16, register-repacked P ---------------
#define AST 36     // words per row (32 data + 4 pad) = 144B
#define W_Q 0
#define W_K (W_Q + 128 * AST)
#define W_V (W_K + 64 * AST)
#define ATTN_WORDS (W_V + 64 * AST)
#define ATTN_SM_BYTES (ATTN_WORDS * 4)   // 36864

__global__ __launch_bounds__(256, 2) void attn_f16(
    const __half* __restrict__ Qg, const __half* __restrict__ Kg,
    const __half* __restrict__ Vg, __half* __restrict__ o)
{
    extern __shared__ uint32_t smw[];
    uint32_t sbase = (uint32_t)__cvta_generic_to_shared(smw);
    uint32_t* Qs = smw + W_Q;
    uint32_t* Ks = smw + W_K;
    uint32_t* Vt = smw + W_V;

    int tid  = threadIdx.x;
    int warp = tid >> 5, lane = tid & 31;
    int gid  = lane >> 2, tig = lane & 3;
    int qrow0 = warp * 16;

    int qb = blockIdx.x;
    int b  = blockIdx.y >> 4;
    int h  = blockIdx.y & 15;

    uint32_t aoff = (uint32_t)((((lane & 15)) * AST + (lane >> 4) * 4) * 4);
    uint32_t boff = (uint32_t)(((((lane >> 4) & 1) * 8 + (lane & 7)) * AST
                                + ((lane >> 3) & 1) * 4) * 4);

    // ---- fill Q ----
    {
        const __half* qg = Qg + (size_t)(b * SEQ + qb * 128) * DIM + h * HD;
        for (int e = tid; e < 128 * 8; e += 256) {
            int r = e >> 3, c = (e & 7) * 8;
            uint4 v = *(const uint4*)(qg + (size_t)r * DIM + c);
            *(uint4*)(Qs + r * AST + (c >> 1)) = v;
        }
    }

    float m0 = -1e30f, m1 = -1e30f, l0r = 0.f, l1r = 0.f;
    float oacc[8][4];
    #pragma unroll
    for (int nt = 0; nt < 8; nt++)
        #pragma unroll
        for (int r = 0; r < 4; r++) oacc[nt][r] = 0.f;

    for (int jb = 0; jb < SEQ / 64; ++jb) {
        __syncthreads();
        const __half* kg = Kg + (size_t)(b * SEQ + jb * 64) * DIM + h * HD;
        const __half* vg = Vg + (size_t)(b * SEQ + jb * 64) * DIM + h * HD;
        for (int e = tid; e < 64 * 8; e += 256) {
            int r = e >> 3, c = (e & 7) * 8;
            uint4 v = *(const uint4*)(kg + (size_t)r * DIM + c);
            *(uint4*)(Ks + r * AST + (c >> 1)) = v;
        }
        for (int e = tid; e < 32 * 16; e += 256) {
            int r2 = e >> 4, c4 = (e & 15) * 4;
            uint2 a = *(const uint2*)(vg + (size_t)(2 * r2)     * DIM + c4);
            uint2 c = *(const uint2*)(vg + (size_t)(2 * r2 + 1) * DIM + c4);
            Vt[(c4 + 0) * AST + r2] = __byte_perm(a.x, c.x, 0x5410);
            Vt[(c4 + 1) * AST + r2] = __byte_perm(a.x, c.x, 0x7632);
            Vt[(c4 + 2) * AST + r2] = __byte_perm(a.y, c.y, 0x5410);
            Vt[(c4 + 3) * AST + r2] = __byte_perm(a.y, c.y, 0x7632);
        }
        __syncthreads();

        // ---- S = Q K^T ----
        float s[8][4];
        #pragma unroll
        for (int nt = 0; nt < 8; nt++)
            #pragma unroll
            for (int r = 0; r < 4; r++) s[nt][r] = 0.f;

        #pragma unroll
        for (int kc = 0; kc < 4; ++kc) {
            uint32_t kcb = kc * 32;
            uint32_t qa0, qa1, qa2, qa3;
            LDSM4(qa0, qa1, qa2, qa3, sbase + (W_Q + qrow0 * AST) * 4 + aoff + kcb);
            #pragma unroll
            for (int p = 0; p < 4; ++p) {
                uint32_t r0, r1, r2, r3;
                LDSM4(r0, r1, r2, r3, sbase + (W_K + p * 16 * AST) * 4 + boff + kcb);
                mma_f16(s[2*p],   qa0, qa1, qa2, qa3, r0, r1);
                mma_f16(s[2*p+1], qa0, qa1, qa2, qa3, r2, r3);
            }
        }

        // ---- online softmax (P stays in registers) ----
        float mc0 = s[0][0], mc1 = s[0][2];
        #pragma unroll
        for (int nt = 0; nt < 8; ++nt) {
            mc0 = fmaxf(mc0, fmaxf(s[nt][0], s[nt][1]));
            mc1 = fmaxf(mc1, fmaxf(s[nt][2], s[nt][3]));
        }
        mc0 = fmaxf(mc0, __shfl_xor_sync(0xffffffffu, mc0, 1));
        mc0 = fmaxf(mc0, __shfl_xor_sync(0xffffffffu, mc0, 2));
        mc1 = fmaxf(mc1, __shfl_xor_sync(0xffffffffu, mc1, 1));
        mc1 = fmaxf(mc1, __shfl_xor_sync(0xffffffffu, mc1, 2));
        float mn0 = fmaxf(m0, mc0), mn1 = fmaxf(m1, mc1);
        float f0 = __expf(m0 - mn0), f1 = __expf(m1 - mn1);
        m0 = mn0; m1 = mn1;

        float ps0 = 0.f, ps1 = 0.f;
        #pragma unroll
        for (int nt = 0; nt < 8; ++nt) {
            float p0 = __expf(s[nt][0] - m0);
            float p1 = __expf(s[nt][1] - m0);
            float p2 = __expf(s[nt][2] - m1);
            float p3 = __expf(s[nt][3] - m1);
            ps0 += p0 + p1; ps1 += p2 + p3;
            s[nt][0] = p0; s[nt][1] = p1; s[nt][2] = p2; s[nt][3] = p3;
        }
        ps0 += __shfl_xor_sync(0xffffffffu, ps0, 1);
        ps0 += __shfl_xor_sync(0xffffffffu, ps0, 2);
        ps1 += __shfl_xor_sync(0xffffffffu, ps1, 1);
        ps1 += __shfl_xor_sync(0xffffffffu, ps1, 2);
        l0r = l0r * f0 + ps0;
        l1r = l1r * f1 + ps1;
        #pragma unroll
        for (int nt = 0; nt < 8; ++nt) {
            oacc[nt][0] *= f0; oacc[nt][1] *= f0;
            oacc[nt][2] *= f1; oacc[nt][3] *= f1;
        }

        // ---- O += P V (P repacked from S accumulators: C-frag == A-frag) --
        #pragma unroll
        for (int kc = 0; kc < 4; ++kc) {
            uint32_t kcb = kc * 32;
            uint32_t pa0 = cvt2h(s[2*kc][0],   s[2*kc][1]);
            uint32_t pa1 = cvt2h(s[2*kc][2],   s[2*kc][3]);
            uint32_t pa2 = cvt2h(s[2*kc+1][0], s[2*kc+1][1]);
            uint32_t pa3 = cvt2h(s[2*kc+1][2], s[2*kc+1][3]);
            #pragma unroll
            for (int p = 0; p < 4; ++p) {
                uint32_t r0, r1, r2, r3;
                LDSM4(r0, r1, r2, r3, sbase + (W_V + p * 16 * AST) * 4 + boff + kcb);
                mma_f16(oacc[2*p],   pa0, pa1, pa2, pa3, r0, r1);
                mma_f16(oacc[2*p+1], pa0, pa1, pa2, pa3, r2, r3);
            }
        }
    }

    float inv0 = 1.0f / l0r, inv1 = 1.0f / l1r;
    int grow0 = b * SEQ + qb * 128 + qrow0 + gid;
    #pragma unroll
    for (int nt = 0; nt < 8; ++nt) {
        int col = h * HD + nt * 8 + tig * 2;
        *(uint32_t*)(o + (size_t)grow0 * DIM + col) =
            cvt2h(oacc[nt][0] * inv0, oacc[nt][1] * inv0);
        *(uint32_t*)(o + (size_t)(grow0 + 8) * DIM + col) =
            cvt2h(oacc[nt][2] * inv1, oacc[nt][3] * inv1);
    }
}

// ---------------- launch ----------------
extern "C" void kernel_launch(void* const* d_in, const int* in_sizes, int n_in,
                              void* d_out, int out_size)
{
    const float* x     = (const float*)d_in[0];
    const float* qkv_w = (const float*)d_in[1];
    const float* out_w = (const float*)d_in[2];
    const float* out_b = (const float*)d_in[3];
    const float* ff_w1 = (const float*)d_in[4];
    const float* ff_b1 = (const float*)d_in[5];
    const float* ff_w2 = (const float*)d_in[6];
    const float* ff_b2 = (const float*)d_in[7];
    const float* ln1_w = (const float*)d_in[8];
    const float* ln1_b = (const float*)d_in[9];
    const float* ln2_w = (const float*)d_in[10];
    const float* ln2_b = (const float*)d_in[11];
    float* out = (float*)d_out;

    float *x1;
    __half *xln, *q, *k, *v, *attn, *xln2, *hbuf;
    __half *wq, *wo, *w1, *w2;
    cudaGetSymbolAddress((void**)&x1,   g_x1);
    cudaGetSymbolAddress((void**)&xln,  g_xln);
    cudaGetSymbolAddress((void**)&q,    g_q);
    cudaGetSymbolAddress((void**)&k,    g_k);
    cudaGetSymbolAddress((void**)&v,    g_v);
    cudaGetSymbolAddress((void**)&attn, g_attn);
    cudaGetSymbolAddress((void**)&xln2, g_xln2);
    cudaGetSymbolAddress((void**)&hbuf, g_h);
    cudaGetSymbolAddress((void**)&wq,   g_wqkv);
    cudaGetSymbolAddress((void**)&wo,   g_wout);
    cudaGetSymbolAddress((void**)&w1,   g_w1);
    cudaGetSymbolAddress((void**)&w2,   g_w2);

    cudaFuncSetAttribute(gemm_f16<EPI_QKV>,
        cudaFuncAttributeMaxDynamicSharedMemorySize, GEMM_SMEM);
    cudaFuncSetAttribute(gemm_f16<EPI_BIAS_RES>,
        cudaFuncAttributeMaxDynamicSharedMemorySize, GEMM_SMEM);
    cudaFuncSetAttribute(gemm_f16<EPI_SILU_H>,
        cudaFuncAttributeMaxDynamicSharedMemorySize, GEMM_SMEM);
    cudaFuncSetAttribute(attn_f16,
        cudaFuncAttributeMaxDynamicSharedMemorySize, ATTN_SM_BYTES);

    // 0. convert weights to fp16
    conv_w<<<(3 * DIM * DIM / 4 + 1023) / 1024, 256>>>(qkv_w, wq, 3 * DIM * DIM / 4);
    conv_w<<<(DIM * DIM / 4 + 1023) / 1024, 256>>>(out_w, wo, DIM * DIM / 4);
    conv_w<<<(MLPD * DIM / 4 + 1023) / 1024, 256>>>(ff_w1, w1, MLPD * DIM / 4);
    conv_w<<<(DIM * MLPD / 4 + 1023) / 1024, 256>>>(ff_w2, w2, DIM * MLPD / 4);

    // 1. LN1 -> fp16
    ln_kernel<<<TOK, 256>>>(x, ln1_w, ln1_b, xln);
    // 2. QKV -> fp16 q(scaled)/k/v
    gemm_f16<EPI_QKV><<<dim3(3 * DIM / 128, TOK / 128), 256, GEMM_SMEM>>>(
        xln, wq, nullptr, nullptr, nullptr, q, k, v, TOK, 3 * DIM, DIM);
    // 3. attention -> fp16
    attn_f16<<<dim3(SEQ / 128, 2 * NHEAD), 256, ATTN_SM_BYTES>>>(q, k, v, attn);
    // 4. x1 = x + attn @ out_w^T + out_b -> fp32
    gemm_f16<EPI_BIAS_RES><<<dim3(DIM / 128, TOK / 128), 256, GEMM_SMEM>>>(
        attn, wo, out_b, x, x1, nullptr, nullptr, nullptr, TOK, DIM, DIM);
    // 5. LN2 -> fp16
    ln_kernel<<<TOK, 256>>>(x1, ln2_w, ln2_b, xln2);
    // 6. h = silu(...) -> fp16
    gemm_f16<EPI_SILU_H><<<dim3(MLPD / 128, TOK / 128), 256, GEMM_SMEM>>>(
        xln2, w1, ff_b1, nullptr, nullptr, hbuf, nullptr, nullptr, TOK, MLPD, DIM);
    // 7. out = x1 + h @ ff_w2^T + ff_b2 -> fp32
    gemm_f16<EPI_BIAS_RES><<<dim3(DIM / 128, TOK / 128), 256, GEMM_SMEM>>>(
        hbuf, w2, ff_b2, x1, out, nullptr, nullptr, nullptr, TOK, DIM, MLPD);
}

// round 12
// speedup vs baseline: 6.7613x; 1.1008x over previous
#include <cuda_runtime.h>
#include <cuda_fp16.h>
#include <math.h>
#include <stdint.h>

#define TOK   4096
#define DIM   1024
#define MLPD  4096
#define NHEAD 16
#define HD    64
#define SEQ   2048

// ---------------- scratch ----------------
__device__ float g_x1  [TOK * DIM];
__device__ __half g_xln [TOK * DIM];
__device__ __half g_q   [TOK * DIM];   // Q (scaled)
__device__ __half g_k   [TOK * DIM];   // K
__device__ __half g_v   [TOK * DIM];   // V
__device__ __half g_attn[TOK * DIM];
__device__ __half g_xln2[TOK * DIM];
__device__ __half g_h   [TOK * MLPD];
__device__ __half g_wqkv[3 * DIM * DIM];
__device__ __half g_wout[DIM * DIM];
__device__ __half g_w1  [MLPD * DIM];
__device__ __half g_w2  [DIM * MLPD];

// ---------------- helpers ----------------
__device__ __forceinline__ uint32_t cvt2h(float x, float y) {
    __half2 h = __floats2half2_rn(x, y);
    return *(uint32_t*)&h;
}

__device__ __forceinline__ void mma_f16(float* d,
    uint32_t a0, uint32_t a1, uint32_t a2, uint32_t a3,
    uint32_t b0, uint32_t b1)
{
    asm volatile(
        "mma.sync.aligned.m16n8k16.row.col.f32.f16.f16.f32 "
        "{%0,%1,%2,%3}, {%4,%5,%6,%7}, {%8,%9}, {%0,%1,%2,%3};"
        : "+f"(d[0]), "+f"(d[1]), "+f"(d[2]), "+f"(d[3])
        : "r"(a0), "r"(a1), "r"(a2), "r"(a3), "r"(b0), "r"(b1));
}

#define LDSM4(R0,R1,R2,R3,ADDR) \
    asm volatile("ldmatrix.sync.aligned.m8n8.x4.shared.b16 {%0,%1,%2,%3}, [%4];" \
        : "=r"(R0), "=r"(R1), "=r"(R2), "=r"(R3) : "r"(ADDR))

#define CP16(dst, src) \
    asm volatile("cp.async.ca.shared.global [%0], [%1], 16;" :: "r"(dst), "l"(src) : "memory")
#define CP_COMMIT() asm volatile("cp.async.commit_group;" ::: "memory")
#define CP_WAIT2()  asm volatile("cp.async.wait_group 2;" ::: "memory")

// ---------------- merged weight convert (fp32 -> fp16) ----------------
#define CB0 (3 * DIM * DIM / 4)
#define CB1 (CB0 + DIM * DIM / 4)
#define CB2 (CB1 + MLPD * DIM / 4)
#define CB3 (CB2 + DIM * MLPD / 4)

__global__ __launch_bounds__(256) void conv_all(
    const float* __restrict__ s0, const float* __restrict__ s1,
    const float* __restrict__ s2, const float* __restrict__ s3,
    __half* __restrict__ d0, __half* __restrict__ d1,
    __half* __restrict__ d2, __half* __restrict__ d3)
{
    int i0 = blockIdx.x * 1024 + threadIdx.x;
    #pragma unroll
    for (int k2 = 0; k2 < 4; ++k2) {
        int i = i0 + k2 * 256;
        if (i < CB3) {
            const float* sp; __half* dp; int off;
            if (i < CB0)      { sp = s0; dp = d0; off = i; }
            else if (i < CB1) { sp = s1; dp = d1; off = i - CB0; }
            else if (i < CB2) { sp = s2; dp = d2; off = i - CB1; }
            else              { sp = s3; dp = d3; off = i - CB2; }
            float4 v = ((const float4*)sp)[off];
            ((uint2*)dp)[off] = make_uint2(cvt2h(v.x, v.y), cvt2h(v.z, v.w));
        }
    }
}

// ---------------- LayerNorm, warp-per-row (8 rows/CTA, no barriers) --------
__global__ __launch_bounds__(256) void ln_kernel(
    const float* __restrict__ x, const float* __restrict__ w,
    const float* __restrict__ b, __half* __restrict__ o)
{
    int warp = threadIdx.x >> 5, lane = threadIdx.x & 31;
    int row = blockIdx.x * 8 + warp;
    const float4* xr = (const float4*)(x + (size_t)row * DIM);
    float4 v[8];
    float s = 0.f, sq = 0.f;
    #pragma unroll
    for (int i = 0; i < 8; i++) {
        v[i] = xr[lane + i * 32];
        s  += v[i].x + v[i].y + v[i].z + v[i].w;
        sq += v[i].x*v[i].x + v[i].y*v[i].y + v[i].z*v[i].z + v[i].w*v[i].w;
    }
    #pragma unroll
    for (int of = 16; of > 0; of >>= 1) {
        s  += __shfl_xor_sync(0xffffffffu, s,  of);
        sq += __shfl_xor_sync(0xffffffffu, sq, of);
    }
    float mean = s * (1.0f / DIM);
    float rstd = rsqrtf(sq * (1.0f / DIM) - mean * mean + 1e-5f);
    uint2* orow = (uint2*)o + (size_t)row * (DIM / 4);
    #pragma unroll
    for (int i = 0; i < 8; i++) {
        int idx = lane + i * 32;
        float4 wv = ((const float4*)w)[idx];
        float4 bv = ((const float4*)b)[idx];
        float ox = (v[i].x - mean) * rstd * wv.x + bv.x;
        float oy = (v[i].y - mean) * rstd * wv.y + bv.y;
        float oz = (v[i].z - mean) * rstd * wv.z + bv.z;
        float ow = (v[i].w - mean) * rstd * wv.w + bv.w;
        orow[idx] = make_uint2(cvt2h(ox, oy), cvt2h(oz, ow));
    }
}

// ---------------- NT GEMM fp16, KT=32, 4-stage cp.async, ldmatrix ----------
#define EPI_NONE      0
#define EPI_BIAS_RES  1
#define EPI_SILU_H    2
#define EPI_QKV       3

#define WST2 20
#define PLW2 (128 * WST2)
#define STGW2 (2 * PLW2)
#define NSTAGE 4
#define GEMM_SMEM (NSTAGE * STGW2 * 4)   // 81920

template <int EPI>
__global__ __launch_bounds__(256, 2) void gemm_f16(
    const __half* __restrict__ A, const __half* __restrict__ W,
    const float* __restrict__ bias, const float* __restrict__ res,
    float* __restrict__ C,
    __half* __restrict__ H0, __half* __restrict__ H1, __half* __restrict__ H2,
    int M, int N, int K)
{
    extern __shared__ __align__(16) uint32_t smw[];
    uint32_t sbase = (uint32_t)__cvta_generic_to_shared(smw);

    int tid  = threadIdx.x;
    int warp = tid >> 5, lane = tid & 31;
    int bm   = blockIdx.y * 128;
    int bn   = blockIdx.x * 128;
    int wm   = (warp & 1) * 64;
    int wn   = (warp >> 1) * 32;
    int gid  = lane >> 2, tig = lane & 3;

    int lrow  = tid >> 1;
    int lh    = tid & 1;
    const __half* pA = A + (size_t)(bm + lrow) * K + lh * 16;
    const __half* pW = W + (size_t)(bn + lrow) * K + lh * 16;
    uint32_t dstb = (uint32_t)(lrow * WST2 + lh * 8) * 4;

    uint32_t a_off = (uint32_t)(((wm + (lane & 15)) * WST2 + (lane >> 4) * 4) * 4);
    uint32_t b_off = (uint32_t)(((wn + ((lane >> 4) & 1) * 8 + (lane & 7)) * WST2
                                 + ((lane >> 3) & 1) * 4) * 4);

    float acc[4][4][4];
    #pragma unroll
    for (int i = 0; i < 4; i++)
        #pragma unroll
        for (int j = 0; j < 4; j++)
            #pragma unroll
            for (int r = 0; r < 4; r++) acc[i][j][r] = 0.f;

    int ntiles = K >> 5;

    auto issue = [&](int t) {
        uint32_t base = sbase + ((t % NSTAGE) * STGW2) * 4 + dstb;
        const __half* a = pA + (size_t)t * 32;
        const __half* w = pW + (size_t)t * 32;
        CP16(base,               a);
        CP16(base + 16,          a + 8);
        CP16(base + PLW2*4,      w);
        CP16(base + PLW2*4 + 16, w + 8);
    };

    issue(0); CP_COMMIT();
    issue(1); CP_COMMIT();
    issue(2); CP_COMMIT();

    for (int t = 0; t < ntiles; ++t) {
        CP_WAIT2();
        __syncthreads();
        uint32_t stb = sbase + ((t % NSTAGE) * STGW2) * 4;

        #pragma unroll
        for (int kc = 0; kc < 2; ++kc) {
            uint32_t kcb = kc * 32;
            uint32_t bw[4][2];
            #pragma unroll
            for (int p = 0; p < 2; ++p) {
                uint32_t r0, r1, r2, r3;
                LDSM4(r0, r1, r2, r3, stb + PLW2*4 + b_off + p * 16 * WST2 * 4 + kcb);
                bw[2*p][0] = r0; bw[2*p][1] = r1; bw[2*p+1][0] = r2; bw[2*p+1][1] = r3;
            }
            #pragma unroll
            for (int mt = 0; mt < 4; ++mt) {
                uint32_t a0, a1, a2, a3;
                LDSM4(a0, a1, a2, a3, stb + a_off + mt * 16 * WST2 * 4 + kcb);
                #pragma unroll
                for (int nt = 0; nt < 4; ++nt)
                    mma_f16(acc[mt][nt], a0, a1, a2, a3, bw[nt][0], bw[nt][1]);
            }
        }
        if (t + 3 < ntiles) issue(t + 3);
        CP_COMMIT();
    }

    // ---- epilogue ----
    #pragma unroll
    for (int mt = 0; mt < 4; ++mt) {
        #pragma unroll
        for (int nt = 0; nt < 4; ++nt) {
            int row = bm + wm + mt * 16 + gid;
            int col = bn + wn + nt * 8 + tig * 2;
            float2 v0 = make_float2(acc[mt][nt][0], acc[mt][nt][1]);
            float2 v1 = make_float2(acc[mt][nt][2], acc[mt][nt][3]);
            if (EPI == EPI_BIAS_RES || EPI == EPI_SILU_H) {
                float bx = bias[col], by = bias[col + 1];
                v0.x += bx; v0.y += by; v1.x += bx; v1.y += by;
            }
            if (EPI == EPI_BIAS_RES) {
                float2 r0 = *(const float2*)(res + (size_t)row * N + col);
                float2 r1 = *(const float2*)(res + (size_t)(row + 8) * N + col);
                v0.x += r0.x; v0.y += r0.y; v1.x += r1.x; v1.y += r1.y;
                *(float2*)(C + (size_t)row * N + col)       = v0;
                *(float2*)(C + (size_t)(row + 8) * N + col) = v1;
            } else if (EPI == EPI_SILU_H) {
                v0.x *= 1.f / (1.f + __expf(-v0.x));
                v0.y *= 1.f / (1.f + __expf(-v0.y));
                v1.x *= 1.f / (1.f + __expf(-v1.x));
                v1.y *= 1.f / (1.f + __expf(-v1.y));
                *(uint32_t*)(H0 + (size_t)row * N + col)       = cvt2h(v0.x, v0.y);
                *(uint32_t*)(H0 + (size_t)(row + 8) * N + col) = cvt2h(v1.x, v1.y);
            } else if (EPI == EPI_QKV) {
                int region = col >> 10;
                int colr   = col & 1023;
                __half* dst = (region == 0) ? H0 : (region == 1) ? H1 : H2;
                float sc = (region == 0) ? 0.125f : 1.0f;
                *(uint32_t*)(dst + (size_t)row * DIM + colr) =
                    cvt2h(v0.x * sc, v0.y * sc);
                *(uint32_t*)(dst + (size_t)(row + 8) * DIM + colr) =
                    cvt2h(v1.x * sc, v1.y * sc);
            } else {
                *(float2*)(C + (size_t)row * N + col)       = v0;
                *(float2*)(C + (size_t)(row + 8) * N + col) = v1;
            }
        }
    }
}

// ---------------- Flash attention fp16, K/V register-prefetch pipeline -----
#define AST 36
#define W_Q 0
#define W_K (W_Q + 128 * AST)                 // double-buffered: 2 x 64 rows
#define W_V (W_K + 2 * 64 * AST)
#define ATTN_WORDS (W_V + 2 * 64 * AST)
#define ATTN_SM_BYTES (ATTN_WORDS * 4)        // 55296

__global__ __launch_bounds__(256, 2) void attn_f16(
    const __half* __restrict__ Qg, const __half* __restrict__ Kg,
    const __half* __restrict__ Vg, __half* __restrict__ o)
{
    extern __shared__ uint32_t smw[];
    uint32_t sbase = (uint32_t)__cvta_generic_to_shared(smw);
    uint32_t* Qs = smw + W_Q;
    uint32_t* Kb = smw + W_K;
    uint32_t* Vb = smw + W_V;

    int tid  = threadIdx.x;
    int warp = tid >> 5, lane = tid & 31;
    int gid  = lane >> 2, tig = lane & 3;
    int qrow0 = warp * 16;

    int qb = blockIdx.x;
    int b  = blockIdx.y >> 4;
    int h  = blockIdx.y & 15;

    uint32_t aoff = (uint32_t)((((lane & 15)) * AST + (lane >> 4) * 4) * 4);
    uint32_t boff = (uint32_t)(((((lane >> 4) & 1) * 8 + (lane & 7)) * AST
                                + ((lane >> 3) & 1) * 4) * 4);

    // fill-thread mappings
    int kr = tid >> 3, kc = (tid & 7) * 8;      // K: rows kr, kr+32
    int vr = tid >> 4, vc = (tid & 15) * 4;     // V: row-pairs 2vr(+1), 2(vr+16)(+1)

    const __half* kbase = Kg + (size_t)(b * SEQ) * DIM + h * HD;
    const __half* vbase = Vg + (size_t)(b * SEQ) * DIM + h * HD;

    uint4 kA, kB;
    uint2 vA0, vA1, vB0, vB1;
    auto ldgKV = [&](int jb) {
        const __half* kg = kbase + (size_t)(jb * 64) * DIM;
        const __half* vg = vbase + (size_t)(jb * 64) * DIM;
        kA = *(const uint4*)(kg + (size_t)kr * DIM + kc);
        kB = *(const uint4*)(kg + (size_t)(kr + 32) * DIM + kc);
        vA0 = *(const uint2*)(vg + (size_t)(2 * vr) * DIM + vc);
        vA1 = *(const uint2*)(vg + (size_t)(2 * vr + 1) * DIM + vc);
        vB0 = *(const uint2*)(vg + (size_t)(2 * (vr + 16)) * DIM + vc);
        vB1 = *(const uint2*)(vg + (size_t)(2 * (vr + 16) + 1) * DIM + vc);
    };
    auto stsKV = [&](int buf) {
        uint32_t* kp = Kb + buf * 64 * AST;
        *(uint4*)(kp + kr * AST + (kc >> 1))        = kA;
        *(uint4*)(kp + (kr + 32) * AST + (kc >> 1)) = kB;
        uint32_t* vp = Vb + buf * 64 * AST;
        vp[(vc + 0) * AST + vr] = __byte_perm(vA0.x, vA1.x, 0x5410);
        vp[(vc + 1) * AST + vr] = __byte_perm(vA0.x, vA1.x, 0x7632);
        vp[(vc + 2) * AST + vr] = __byte_perm(vA0.y, vA1.y, 0x5410);
        vp[(vc + 3) * AST + vr] = __byte_perm(vA0.y, vA1.y, 0x7632);
        vp[(vc + 0) * AST + vr + 16] = __byte_perm(vB0.x, vB1.x, 0x5410);
        vp[(vc + 1) * AST + vr + 16] = __byte_perm(vB0.x, vB1.x, 0x7632);
        vp[(vc + 2) * AST + vr + 16] = __byte_perm(vB0.y, vB1.y, 0x5410);
        vp[(vc + 3) * AST + vr + 16] = __byte_perm(vB0.y, vB1.y, 0x7632);
    };

    // prologue: start K/V(0) loads, fill Q
    ldgKV(0);
    {
        const __half* qg = Qg + (size_t)(b * SEQ + qb * 128) * DIM + h * HD;
        for (int e = tid; e < 128 * 8; e += 256) {
            int r = e >> 3, c = (e & 7) * 8;
            uint4 v = *(const uint4*)(qg + (size_t)r * DIM + c);
            *(uint4*)(Qs + r * AST + (c >> 1)) = v;
        }
    }

    float m0 = -1e30f, m1 = -1e30f, l0r = 0.f, l1r = 0.f;
    float oacc[8][4];
    #pragma unroll
    for (int nt = 0; nt < 8; nt++)
        #pragma unroll
        for (int r = 0; r < 4; r++) oacc[nt][r] = 0.f;

    for (int jb = 0; jb < SEQ / 64; ++jb) {
        int buf = jb & 1;
        stsKV(buf);
        __syncthreads();
        if (jb + 1 < SEQ / 64) ldgKV(jb + 1);

        uint32_t kb4 = sbase + (W_K + buf * 64 * AST) * 4;
        uint32_t vb4 = sbase + (W_V + buf * 64 * AST) * 4;

        // ---- S = Q K^T ----
        float s[8][4];
        #pragma unroll
        for (int nt = 0; nt < 8; nt++)
            #pragma unroll
            for (int r = 0; r < 4; r++) s[nt][r] = 0.f;

        #pragma unroll
        for (int kcx = 0; kcx < 4; ++kcx) {
            uint32_t kcb = kcx * 32;
            uint32_t qa0, qa1, qa2, qa3;
            LDSM4(qa0, qa1, qa2, qa3, sbase + (W_Q + qrow0 * AST) * 4 + aoff + kcb);
            #pragma unroll
            for (int p = 0; p < 4; ++p) {
                uint32_t r0, r1, r2, r3;
                LDSM4(r0, r1, r2, r3, kb4 + p * 16 * AST * 4 + boff + kcb);
                mma_f16(s[2*p],   qa0, qa1, qa2, qa3, r0, r1);
                mma_f16(s[2*p+1], qa0, qa1, qa2, qa3, r2, r3);
            }
        }

        // ---- online softmax (P stays in registers) ----
        float mc0 = s[0][0], mc1 = s[0][2];
        #pragma unroll
        for (int nt = 0; nt < 8; ++nt) {
            mc0 = fmaxf(mc0, fmaxf(s[nt][0], s[nt][1]));
            mc1 = fmaxf(mc1, fmaxf(s[nt][2], s[nt][3]));
        }
        mc0 = fmaxf(mc0, __shfl_xor_sync(0xffffffffu, mc0, 1));
        mc0 = fmaxf(mc0, __shfl_xor_sync(0xffffffffu, mc0, 2));
        mc1 = fmaxf(mc1, __shfl_xor_sync(0xffffffffu, mc1, 1));
        mc1 = fmaxf(mc1, __shfl_xor_sync(0xffffffffu, mc1, 2));
        float mn0 = fmaxf(m0, mc0), mn1 = fmaxf(m1, mc1);
        float f0 = __expf(m0 - mn0), f1 = __expf(m1 - mn1);
        m0 = mn0; m1 = mn1;

        float ps0 = 0.f, ps1 = 0.f;
        #pragma unroll
        for (int nt = 0; nt < 8; ++nt) {
            float p0 = __expf(s[nt][0] - m0);
            float p1 = __expf(s[nt][1] - m0);
            float p2 = __expf(s[nt][2] - m1);
            float p3 = __expf(s[nt][3] - m1);
            ps0 += p0 + p1; ps1 += p2 + p3;
            s[nt][0] = p0; s[nt][1] = p1; s[nt][2] = p2; s[nt][3] = p3;
        }
        ps0 += __shfl_xor_sync(0xffffffffu, ps0, 1);
        ps0 += __shfl_xor_sync(0xffffffffu, ps0, 2);
        ps1 += __shfl_xor_sync(0xffffffffu, ps1, 1);
        ps1 += __shfl_xor_sync(0xffffffffu, ps1, 2);
        l0r = l0r * f0 + ps0;
        l1r = l1r * f1 + ps1;
        #pragma unroll
        for (int nt = 0; nt < 8; ++nt) {
            oacc[nt][0] *= f0; oacc[nt][1] *= f0;
            oacc[nt][2] *= f1; oacc[nt][3] *= f1;
        }

        // ---- O += P V (register repack: C-frag == A-frag) ----
        #pragma unroll
        for (int kcx = 0; kcx < 4; ++kcx) {
            uint32_t kcb = kcx * 32;
            uint32_t pa0 = cvt2h(s[2*kcx][0],   s[2*kcx][1]);
            uint32_t pa1 = cvt2h(s[2*kcx][2],   s[2*kcx][3]);
            uint32_t pa2 = cvt2h(s[2*kcx+1][0], s[2*kcx+1][1]);
            uint32_t pa3 = cvt2h(s[2*kcx+1][2], s[2*kcx+1][3]);
            #pragma unroll
            for (int p = 0; p < 4; ++p) {
                uint32_t r0, r1, r2, r3;
                LDSM4(r0, r1, r2, r3, vb4 + p * 16 * AST * 4 + boff + kcb);
                mma_f16(oacc[2*p],   pa0, pa1, pa2, pa3, r0, r1);
                mma_f16(oacc[2*p+1], pa0, pa1, pa2, pa3, r2, r3);
            }
        }
    }

    float inv0 = 1.0f / l0r, inv1 = 1.0f / l1r;
    int grow0 = b * SEQ + qb * 128 + qrow0 + gid;
    #pragma unroll
    for (int nt = 0; nt < 8; ++nt) {
        int col = h * HD + nt * 8 + tig * 2;
        *(uint32_t*)(o + (size_t)grow0 * DIM + col) =
            cvt2h(oacc[nt][0] * inv0, oacc[nt][1] * inv0);
        *(uint32_t*)(o + (size_t)(grow0 + 8) * DIM + col) =
            cvt2h(oacc[nt][2] * inv1, oacc[nt][3] * inv1);
    }
}

// ---------------- launch ----------------
extern "C" void kernel_launch(void* const* d_in, const int* in_sizes, int n_in,
                              void* d_out, int out_size)
{
    const float* x     = (const float*)d_in[0];
    const float* qkv_w = (const float*)d_in[1];
    const float* out_w = (const float*)d_in[2];
    const float* out_b = (const float*)d_in[3];
    const float* ff_w1 = (const float*)d_in[4];
    const float* ff_b1 = (const float*)d_in[5];
    const float* ff_w2 = (const float*)d_in[6];
    const float* ff_b2 = (const float*)d_in[7];
    const float* ln1_w = (const float*)d_in[8];
    const float* ln1_b = (const float*)d_in[9];
    const float* ln2_w = (const float*)d_in[10];
    const float* ln2_b = (const float*)d_in[11];
    float* out = (float*)d_out;

    float *x1;
    __half *xln, *q, *k, *v, *attn, *xln2, *hbuf;
    __half *wq, *wo, *w1, *w2;
    cudaGetSymbolAddress((void**)&x1,   g_x1);
    cudaGetSymbolAddress((void**)&xln,  g_xln);
    cudaGetSymbolAddress((void**)&q,    g_q);
    cudaGetSymbolAddress((void**)&k,    g_k);
    cudaGetSymbolAddress((void**)&v,    g_v);
    cudaGetSymbolAddress((void**)&attn, g_attn);
    cudaGetSymbolAddress((void**)&xln2, g_xln2);
    cudaGetSymbolAddress((void**)&hbuf, g_h);
    cudaGetSymbolAddress((void**)&wq,   g_wqkv);
    cudaGetSymbolAddress((void**)&wo,   g_wout);
    cudaGetSymbolAddress((void**)&w1,   g_w1);
    cudaGetSymbolAddress((void**)&w2,   g_w2);

    cudaFuncSetAttribute(gemm_f16<EPI_QKV>,
        cudaFuncAttributeMaxDynamicSharedMemorySize, GEMM_SMEM);
    cudaFuncSetAttribute(gemm_f16<EPI_BIAS_RES>,
        cudaFuncAttributeMaxDynamicSharedMemorySize, GEMM_SMEM);
    cudaFuncSetAttribute(gemm_f16<EPI_SILU_H>,
        cudaFuncAttributeMaxDynamicSharedMemorySize, GEMM_SMEM);
    cudaFuncSetAttribute(attn_f16,
        cudaFuncAttributeMaxDynamicSharedMemorySize, ATTN_SM_BYTES);

    // 0. convert all weights to fp16 (single launch)
    conv_all<<<(CB3 + 1023) / 1024, 256>>>(qkv_w, out_w, ff_w1, ff_w2, wq, wo, w1, w2);

    // 1. LN1 -> fp16
    ln_kernel<<<TOK / 8, 256>>>(x, ln1_w, ln1_b, xln);
    // 2. QKV -> fp16 q(scaled)/k/v
    gemm_f16<EPI_QKV><<<dim3(3 * DIM / 128, TOK / 128), 256, GEMM_SMEM>>>(
        xln, wq, nullptr, nullptr, nullptr, q, k, v, TOK, 3 * DIM, DIM);
    // 3. attention -> fp16
    attn_f16<<<dim3(SEQ / 128, 2 * NHEAD), 256, ATTN_SM_BYTES>>>(q, k, v, attn);
    // 4. x1 = x + attn @ out_w^T + out_b -> fp32
    gemm_f16<EPI_BIAS_RES><<<dim3(DIM / 128, TOK / 128), 256, GEMM_SMEM>>>(
        attn, wo, out_b, x, x1, nullptr, nullptr, nullptr, TOK, DIM, DIM);
    // 5. LN2 -> fp16
    ln_kernel<<<TOK / 8, 256>>>(x1, ln2_w, ln2_b, xln2);
    // 6. h = silu(...) -> fp16
    gemm_f16<EPI_SILU_H><<<dim3(MLPD / 128, TOK / 128), 256, GEMM_SMEM>>>(
        xln2, w1, ff_b1, nullptr, nullptr, hbuf, nullptr, nullptr, TOK, MLPD, DIM);
    // 7. out = x1 + h @ ff_w2^T + ff_b2 -> fp32
    gemm_f16<EPI_BIAS_RES><<<dim3(DIM / 128, TOK / 128), 256, GEMM_SMEM>>>(
        hbuf, w2, ff_b2, x1, out, nullptr, nullptr, nullptr, TOK, DIM, MLPD);
}